// round 1
// baseline (speedup 1.0000x reference)
#include <cuda_runtime.h>
#include <math.h>

#define SEQ 8192
#define DIM 1024

// Scratch (device globals — allocation-free kernel_launch)
__device__ float g_Q[SEQ * DIM];
__device__ float g_K[SEQ * DIM];
__device__ float g_P[(size_t)SEQ * SEQ];   // 256 MB score/prob matrix

// ---------------------------------------------------------------------------
// Tiled fp32 GEMM.
//   TRANSB == false : C[M,N] = alpha * A[M,K] @ B[K,N]
//   TRANSB == true  : C[M,N] = alpha * A[M,K] @ B[N,K]^T
// BM=BN=128, BK=16, 256 threads, 8x8 microtile. M,N multiples of 128; K of 16.
// ---------------------------------------------------------------------------
template <bool TRANSB>
__global__ __launch_bounds__(256)
void gemm128(const float* __restrict__ A, const float* __restrict__ B,
             float* __restrict__ C, int M, int N, int K, float alpha)
{
    constexpr int BM = 128, BN = 128, BK = 16, TM = 8, TN = 8;
    __shared__ float As[BK][BM];   // stored k-major (transposed)
    __shared__ float Bs[BK][BN];

    const int bm = blockIdx.y * BM;
    const int bn = blockIdx.x * BN;
    const int tid = threadIdx.x;
    const int trow = tid / 16;     // 0..15
    const int tcol = tid % 16;     // 0..15

    // A-tile load mapping (also used for transposed-B load)
    const int a_row  = tid >> 2;          // 0..63
    const int a_col4 = (tid & 3) * 4;     // 0,4,8,12
    // B-tile load mapping (non-transposed)
    const int b_row  = tid >> 5;          // 0..7
    const int b_col4 = (tid & 31) * 4;    // 0..124

    float acc[TM][TN];
#pragma unroll
    for (int i = 0; i < TM; i++)
#pragma unroll
        for (int j = 0; j < TN; j++) acc[i][j] = 0.0f;

    for (int k0 = 0; k0 < K; k0 += BK) {
        // ---- load A tile: A[bm+row][k0 + c], scatter into As[c][row]
        const float* Ap = A + (size_t)bm * K + k0;
#pragma unroll
        for (int r = 0; r < 2; r++) {
            int row = a_row + r * 64;
            float4 v = *(const float4*)(Ap + (size_t)row * K + a_col4);
            As[a_col4 + 0][row] = v.x;
            As[a_col4 + 1][row] = v.y;
            As[a_col4 + 2][row] = v.z;
            As[a_col4 + 3][row] = v.w;
        }
        // ---- load B tile
        if (!TRANSB) {
            const float* Bp = B + (size_t)k0 * N + bn;
#pragma unroll
            for (int r = 0; r < 2; r++) {
                int kr = b_row + r * 8;
                float4 v = *(const float4*)(Bp + (size_t)kr * N + b_col4);
                *(float4*)&Bs[kr][b_col4] = v;
            }
        } else {
            // B is [N,K]; Bs[k][n] = B[bn+n][k0+k]
            const float* Bp = B + (size_t)bn * K + k0;
#pragma unroll
            for (int r = 0; r < 2; r++) {
                int row = a_row + r * 64;
                float4 v = *(const float4*)(Bp + (size_t)row * K + a_col4);
                Bs[a_col4 + 0][row] = v.x;
                Bs[a_col4 + 1][row] = v.y;
                Bs[a_col4 + 2][row] = v.z;
                Bs[a_col4 + 3][row] = v.w;
            }
        }
        __syncthreads();

        // ---- compute
#pragma unroll
        for (int k = 0; k < BK; k++) {
            float ar[TM], br[TN];
            *(float4*)&ar[0] = *(const float4*)&As[k][trow * TM + 0];
            *(float4*)&ar[4] = *(const float4*)&As[k][trow * TM + 4];
            *(float4*)&br[0] = *(const float4*)&Bs[k][tcol * TN + 0];
            *(float4*)&br[4] = *(const float4*)&Bs[k][tcol * TN + 4];
#pragma unroll
            for (int i = 0; i < TM; i++)
#pragma unroll
                for (int j = 0; j < TN; j++)
                    acc[i][j] = fmaf(ar[i], br[j], acc[i][j]);
        }
        __syncthreads();
    }

    // ---- write C
#pragma unroll
    for (int i = 0; i < TM; i++) {
        float* Cp = C + (size_t)(bm + trow * TM + i) * N + bn + tcol * TN;
#pragma unroll
        for (int j = 0; j < TN; j += 4) {
            float4 v;
            v.x = alpha * acc[i][j + 0];
            v.y = alpha * acc[i][j + 1];
            v.z = alpha * acc[i][j + 2];
            v.w = alpha * acc[i][j + 3];
            *(float4*)(Cp + j) = v;
        }
    }
}

// ---------------------------------------------------------------------------
// Row softmax over [SEQ, SEQ] in place. One block per row.
// ---------------------------------------------------------------------------
__global__ __launch_bounds__(256)
void softmax_rows(float* __restrict__ P, int n)
{
    float* p = P + (size_t)blockIdx.x * n;
    const int tid = threadIdx.x;
    __shared__ float red[256];

    // max
    float m = -3.4e38f;
    for (int i = tid; i < n; i += 256) m = fmaxf(m, p[i]);
    red[tid] = m;
    __syncthreads();
    for (int s = 128; s > 0; s >>= 1) {
        if (tid < s) red[tid] = fmaxf(red[tid], red[tid + s]);
        __syncthreads();
    }
    m = red[0];
    __syncthreads();

    // exp + sum
    float sum = 0.0f;
    for (int i = tid; i < n; i += 256) {
        float e = expf(p[i] - m);
        p[i] = e;
        sum += e;
    }
    red[tid] = sum;
    __syncthreads();
    for (int s = 128; s > 0; s >>= 1) {
        if (tid < s) red[tid] += red[tid + s];
        __syncthreads();
    }
    float inv = 1.0f / red[0];
    __syncthreads();

    for (int i = tid; i < n; i += 256) p[i] *= inv;
}

// ---------------------------------------------------------------------------
extern "C" void kernel_launch(void* const* d_in, const int* in_sizes, int n_in,
                              void* d_out, int out_size)
{
    const float* X  = (const float*)d_in[0];
    const float* Wq = (const float*)d_in[1];
    const float* Wk = (const float*)d_in[2];
    float* out = (float*)d_out;

    void *qp, *kp, *pp;
    cudaGetSymbolAddress(&qp, g_Q);
    cudaGetSymbolAddress(&kp, g_K);
    cudaGetSymbolAddress(&pp, g_P);
    float* Q = (float*)qp;
    float* Kb = (float*)kp;
    float* P = (float*)pp;

    const float scale = 0.03125f;  // 1/sqrt(1024)

    dim3 blk(256);
    // Q = X @ Wq ; K = X @ Wk
    gemm128<false><<<dim3(DIM / 128, SEQ / 128), blk>>>(X, Wq, Q,  SEQ, DIM, DIM, 1.0f);
    gemm128<false><<<dim3(DIM / 128, SEQ / 128), blk>>>(X, Wk, Kb, SEQ, DIM, DIM, 1.0f);
    // S = (Q @ K^T) * scale
    gemm128<true><<<dim3(SEQ / 128, SEQ / 128), blk>>>(Q, Kb, P, SEQ, SEQ, DIM, scale);
    // P = softmax(S) rows
    softmax_rows<<<SEQ, blk>>>(P, SEQ);
    // out = P @ X
    gemm128<false><<<dim3(DIM / 128, SEQ / 128), blk>>>(P, X, out, SEQ, DIM, SEQ, 1.0f);
}

// round 3
// speedup vs baseline: 1.2313x; 1.2313x over previous
#include <cuda_runtime.h>
#include <cuda_bf16.h>
#include <cstdint>
#include <math.h>

#define SEQ 8192
#define DIM 1024

// ---------------------------------------------------------------------------
// Scratch (device globals — allocation-free)
// ---------------------------------------------------------------------------
__device__ __align__(256) float g_S[(size_t)SEQ * SEQ];           // 256MB logits
__device__ __align__(256) __nv_bfloat16 g_Ph[(size_t)SEQ * SEQ];  // 128MB
__device__ __align__(256) __nv_bfloat16 g_Pl[(size_t)SEQ * SEQ];  // 128MB
__device__ __align__(256) __nv_bfloat16 g_Qh[SEQ * DIM], g_Qm[SEQ * DIM], g_Ql[SEQ * DIM];
__device__ __align__(256) __nv_bfloat16 g_Kh[SEQ * DIM], g_Km[SEQ * DIM], g_Kl[SEQ * DIM];
__device__ __align__(256) __nv_bfloat16 g_Xh[SEQ * DIM], g_Xm[SEQ * DIM], g_Xl[SEQ * DIM];
__device__ __align__(256) __nv_bfloat16 g_Xth[DIM * SEQ], g_Xtl[DIM * SEQ];
__device__ __align__(256) __nv_bfloat16 g_Wth[DIM * DIM], g_Wtm[DIM * DIM], g_Wtl[DIM * DIM];

// ---------------------------------------------------------------------------
// PTX helpers (baseline ISA only — valid on .target sm_103)
// ---------------------------------------------------------------------------
__device__ __forceinline__ uint32_t smem_u32(const void* p) {
    uint32_t a;
    asm("{ .reg .u64 t; cvta.to.shared.u64 t, %1; cvt.u32.u64 %0, t; }"
        : "=r"(a) : "l"(p));
    return a;
}

__device__ __forceinline__ void cp_async16(uint32_t saddr, const void* gaddr) {
    asm volatile("cp.async.cg.shared.global [%0], [%1], 16;"
                 :: "r"(saddr), "l"(gaddr));
}
#define CP_COMMIT() asm volatile("cp.async.commit_group;")
#define CP_WAIT(N)  asm volatile("cp.async.wait_group %0;" :: "n"(N))

__device__ __forceinline__ void ldsm4(uint32_t* r, uint32_t addr) {
    asm volatile("ldmatrix.sync.aligned.m8n8.x4.shared.b16 {%0,%1,%2,%3}, [%4];"
                 : "=r"(r[0]), "=r"(r[1]), "=r"(r[2]), "=r"(r[3])
                 : "r"(addr));
}

__device__ __forceinline__ void mma16816(float* d, const uint32_t* a,
                                         uint32_t b0, uint32_t b1) {
    asm volatile(
        "mma.sync.aligned.m16n8k16.row.col.f32.bf16.bf16.f32 "
        "{%0,%1,%2,%3}, {%4,%5,%6,%7}, {%8,%9}, {%0,%1,%2,%3};"
        : "+f"(d[0]), "+f"(d[1]), "+f"(d[2]), "+f"(d[3])
        : "r"(a[0]), "r"(a[1]), "r"(a[2]), "r"(a[3]), "r"(b0), "r"(b1));
}

// swizzled smem byte offset for (row, 16B-segment) in a 64B-pitch tile
__device__ __forceinline__ uint32_t swz(int row, int seg) {
    return (uint32_t)(row * 64 + ((seg ^ ((row >> 1) & 3)) << 4));
}

// ---------------------------------------------------------------------------
// HMMA GEMM:  D[128x128 tile] = alpha * sum_p A_p[M,K] @ B_p[N,K]^T
// A, B K-major bf16. fp32 register accumulation across all pairs.
// EPI 0: C = alpha * D (fp32).  EPI 1: 3-way bf16 split of D.
// ---------------------------------------------------------------------------
struct GemmArgs {
    const __nv_bfloat16* A[6];
    const __nv_bfloat16* B[6];
    int K;        // per-pair reduction length (multiple of 32)
    int ldc;
    float alpha;
    float* C;
    __nv_bfloat16 *Oh, *Om, *Ol;
};

template <int NPAIRS, int EPI>
__global__ __launch_bounds__(256, 1)
void gemm_mma(const GemmArgs args)
{
    constexpr int BM = 128, BN = 128, BK = 32, STAGES = 4;
    constexpr int TILE_B = BM * 64;            // 8KB per operand per stage
    constexpr int STAGE_B = 2 * TILE_B;        // 16KB
    extern __shared__ __align__(128) char smem[];
    const uint32_t sbase = smem_u32(smem);

    const int tid = threadIdx.x;
    const int wid = tid >> 5;
    const int lane = tid & 31;
    const int wm = wid & 1;          // 2 warps along M
    const int wn = wid >> 1;         // 4 warps along N
    const int bm = blockIdx.y * BM;
    const int bn = blockIdx.x * BN;
    const int K = args.K;
    const int nchunk = K / BK;
    const int total = NPAIRS * nchunk;

    // per-lane ldmatrix offsets
    const int sub = lane >> 3, r8 = lane & 7;
    uint32_t aoff[2][4], boff[2][2];
#pragma unroll
    for (int kk = 0; kk < 2; kk++) {
#pragma unroll
        for (int mi = 0; mi < 4; mi++) {
            int row = wm * 64 + mi * 16 + (sub & 1) * 8 + r8;
            int seg = 2 * kk + (sub >> 1);
            aoff[kk][mi] = swz(row, seg);
        }
#pragma unroll
        for (int nj = 0; nj < 2; nj++) {
            int row = wn * 32 + nj * 16 + (sub >> 1) * 8 + r8;
            int seg = 2 * kk + (sub & 1);
            boff[kk][nj] = swz(row, seg);
        }
    }

    // cp.async chunk mapping (2 chunks of A and 2 of B per thread per tile)
    const int ld_row0 = tid >> 2;
    const int ld_seg = tid & 3;
    const uint32_t ld_soff0 = swz(ld_row0, ld_seg);
    const uint32_t ld_soff1 = swz(ld_row0 + 64, ld_seg);

    float acc[4][4][4];
#pragma unroll
    for (int mi = 0; mi < 4; mi++)
#pragma unroll
        for (int ni = 0; ni < 4; ni++)
#pragma unroll
            for (int v = 0; v < 4; v++) acc[mi][ni][v] = 0.0f;

    auto issue_tile = [&](int t, int s) {
        const int p = t / nchunk;
        const int c = t - p * nchunk;
        const __nv_bfloat16* Ap = args.A[p] + (size_t)bm * K + c * BK;
        const __nv_bfloat16* Bp = args.B[p] + (size_t)bn * K + c * BK;
        const uint32_t as = sbase + s * STAGE_B;
        const uint32_t bs = as + TILE_B;
        const size_t g0 = (size_t)ld_row0 * K + ld_seg * 8;
        const size_t g1 = (size_t)(ld_row0 + 64) * K + ld_seg * 8;
        cp_async16(as + ld_soff0, Ap + g0);
        cp_async16(as + ld_soff1, Ap + g1);
        cp_async16(bs + ld_soff0, Bp + g0);
        cp_async16(bs + ld_soff1, Bp + g1);
    };

    // prologue: stages 0..S-2
#pragma unroll
    for (int j = 0; j < STAGES - 1; j++) {
        issue_tile(j, j);
        CP_COMMIT();
    }

    for (int i = 0; i < total; i++) {
        CP_WAIT(STAGES - 2);
        __syncthreads();
        if (i + STAGES - 1 < total) issue_tile(i + STAGES - 1, (i + STAGES - 1) % STAGES);
        CP_COMMIT();

        const int s = i % STAGES;
        const uint32_t as = sbase + s * STAGE_B;
        const uint32_t bs = as + TILE_B;
#pragma unroll
        for (int kk = 0; kk < 2; kk++) {
            uint32_t ar[4][4], br[2][4];
#pragma unroll
            for (int mi = 0; mi < 4; mi++) ldsm4(ar[mi], as + aoff[kk][mi]);
#pragma unroll
            for (int nj = 0; nj < 2; nj++) ldsm4(br[nj], bs + boff[kk][nj]);
#pragma unroll
            for (int mi = 0; mi < 4; mi++)
#pragma unroll
                for (int ni = 0; ni < 4; ni++) {
                    const int nj = ni >> 1, o = (ni & 1) * 2;
                    mma16816(acc[mi][ni], ar[mi], br[nj][o], br[nj][o + 1]);
                }
        }
        __syncthreads();
    }

    // ---- epilogue from registers ----
    const int ldc = args.ldc;
#pragma unroll
    for (int mi = 0; mi < 4; mi++) {
#pragma unroll
        for (int ni = 0; ni < 4; ni++) {
            const int r0 = bm + wm * 64 + mi * 16 + (lane >> 2);
            const int c0 = bn + wn * 32 + ni * 8 + (lane & 3) * 2;
#pragma unroll
            for (int h = 0; h < 2; h++) {
                const size_t o = (size_t)(r0 + h * 8) * ldc + c0;
                const float v0 = acc[mi][ni][2 * h + 0];
                const float v1 = acc[mi][ni][2 * h + 1];
                if (EPI == 0) {
                    float2 w;
                    w.x = args.alpha * v0;
                    w.y = args.alpha * v1;
                    *(float2*)(args.C + o) = w;
                } else {
                    __nv_bfloat16 h0 = __float2bfloat16(v0);
                    __nv_bfloat16 h1 = __float2bfloat16(v1);
                    float rm0 = v0 - __bfloat162float(h0);
                    float rm1 = v1 - __bfloat162float(h1);
                    __nv_bfloat16 m0 = __float2bfloat16(rm0);
                    __nv_bfloat16 m1 = __float2bfloat16(rm1);
                    float rl0 = rm0 - __bfloat162float(m0);
                    float rl1 = rm1 - __bfloat162float(m1);
                    __nv_bfloat16 l0 = __float2bfloat16(rl0);
                    __nv_bfloat16 l1 = __float2bfloat16(rl1);
                    uint32_t ph = (uint32_t)*(unsigned short*)&h0 |
                                  ((uint32_t)*(unsigned short*)&h1 << 16);
                    uint32_t pm = (uint32_t)*(unsigned short*)&m0 |
                                  ((uint32_t)*(unsigned short*)&m1 << 16);
                    uint32_t pl = (uint32_t)*(unsigned short*)&l0 |
                                  ((uint32_t)*(unsigned short*)&l1 << 16);
                    *(uint32_t*)((unsigned short*)args.Oh + o) = ph;
                    *(uint32_t*)((unsigned short*)args.Om + o) = pm;
                    *(uint32_t*)((unsigned short*)args.Ol + o) = pl;
                }
            }
        }
    }
}

// ---------------------------------------------------------------------------
// elementwise 3-way split
// ---------------------------------------------------------------------------
__global__ __launch_bounds__(256)
void split3_kernel(const float* __restrict__ in, __nv_bfloat16* __restrict__ oh,
                   __nv_bfloat16* __restrict__ om, __nv_bfloat16* __restrict__ ol)
{
    size_t i = (size_t)blockIdx.x * 256 + threadIdx.x;
    float v = in[i];
    __nv_bfloat16 h = __float2bfloat16(v);
    float r1 = v - __bfloat162float(h);
    __nv_bfloat16 m = __float2bfloat16(r1);
    float r2 = r1 - __bfloat162float(m);
    oh[i] = h;
    om[i] = m;
    ol[i] = __float2bfloat16(r2);
}

// ---------------------------------------------------------------------------
// transpose + split: in[R][C] fp32 -> out*[C][R] bf16 (om/ol optional)
// ---------------------------------------------------------------------------
__global__ __launch_bounds__(256)
void transp_split(const float* __restrict__ in, __nv_bfloat16* oh,
                  __nv_bfloat16* om, __nv_bfloat16* ol, int R, int C)
{
    __shared__ float t[32][33];
    const int bc = blockIdx.x * 32, br = blockIdx.y * 32;
    const int tx = threadIdx.x & 31, ty = threadIdx.x >> 5;   // 32 x 8
#pragma unroll
    for (int j = 0; j < 32; j += 8)
        t[ty + j][tx] = in[(size_t)(br + ty + j) * C + bc + tx];
    __syncthreads();
#pragma unroll
    for (int j = 0; j < 32; j += 8) {
        int oc = bc + ty + j;
        float v = t[tx][ty + j];
        __nv_bfloat16 h = __float2bfloat16(v);
        float r1 = v - __bfloat162float(h);
        size_t o = (size_t)oc * R + br + tx;
        oh[o] = h;
        if (om) {
            __nv_bfloat16 m = __float2bfloat16(r1);
            om[o] = m;
            if (ol) {
                float r2 = r1 - __bfloat162float(m);
                ol[o] = __float2bfloat16(r2);
            }
        }
    }
}

// ---------------------------------------------------------------------------
// softmax over rows of S, emitting 2-way bf16 split of P. Row cached in SMEM.
// ---------------------------------------------------------------------------
__global__ __launch_bounds__(256)
void softmax_split(const float* __restrict__ S, __nv_bfloat16* __restrict__ Ph,
                   __nv_bfloat16* __restrict__ Pl, int n)
{
    __shared__ float row[SEQ];
    __shared__ float red[256];
    const float* s = S + (size_t)blockIdx.x * n;
    const int tid = threadIdx.x;

    float m = -3.4e38f;
    for (int i = tid; i < n; i += 256) {
        float v = s[i];
        row[i] = v;
        m = fmaxf(m, v);
    }
    red[tid] = m;
    __syncthreads();
    for (int st = 128; st > 0; st >>= 1) {
        if (tid < st) red[tid] = fmaxf(red[tid], red[tid + st]);
        __syncthreads();
    }
    m = red[0];
    __syncthreads();

    float sum = 0.0f;
    for (int i = tid; i < n; i += 256) {
        float e = expf(row[i] - m);
        row[i] = e;
        sum += e;
    }
    red[tid] = sum;
    __syncthreads();
    for (int st = 128; st > 0; st >>= 1) {
        if (tid < st) red[tid] += red[tid + st];
        __syncthreads();
    }
    const float inv = 1.0f / red[0];
    __syncthreads();

    __nv_bfloat16* ph = Ph + (size_t)blockIdx.x * n;
    __nv_bfloat16* pl = Pl + (size_t)blockIdx.x * n;
    for (int i = tid; i < n; i += 256) {
        float p = row[i] * inv;
        __nv_bfloat16 h = __float2bfloat16(p);
        float r1 = p - __bfloat162float(h);
        ph[i] = h;
        pl[i] = __float2bfloat16(r1);
    }
}

// ---------------------------------------------------------------------------
extern "C" void kernel_launch(void* const* d_in, const int* in_sizes, int n_in,
                              void* d_out, int out_size)
{
    const float* X  = (const float*)d_in[0];
    const float* Wq = (const float*)d_in[1];
    const float* Wk = (const float*)d_in[2];
    float* out = (float*)d_out;

    void* p;
#define SYM(name, var) cudaGetSymbolAddress(&p, name); auto* var = (decltype(&name[0]))p;
    SYM(g_S, S) SYM(g_Ph, Ph) SYM(g_Pl, Pl)
    SYM(g_Qh, Qh) SYM(g_Qm, Qm) SYM(g_Ql, Ql)
    SYM(g_Kh, Kh) SYM(g_Km, Km) SYM(g_Kl, Kl)
    SYM(g_Xh, Xh) SYM(g_Xm, Xm) SYM(g_Xl, Xl)
    SYM(g_Xth, Xth) SYM(g_Xtl, Xtl)
    SYM(g_Wth, Wth) SYM(g_Wtm, Wtm) SYM(g_Wtl, Wtl)
#undef SYM

    const int SMEM_GEMM = 4 * 16384;   // 4 stages x 16KB
    cudaFuncSetAttribute(gemm_mma<6, 0>, cudaFuncAttributeMaxDynamicSharedMemorySize, SMEM_GEMM);
    cudaFuncSetAttribute(gemm_mma<6, 1>, cudaFuncAttributeMaxDynamicSharedMemorySize, SMEM_GEMM);
    cudaFuncSetAttribute(gemm_mma<3, 0>, cudaFuncAttributeMaxDynamicSharedMemorySize, SMEM_GEMM);

    // --- prep: splits & transposes ---
    split3_kernel<<<SEQ * DIM / 256, 256>>>(X, Xh, Xm, Xl);
    transp_split<<<dim3(DIM / 32, SEQ / 32), 256>>>(X, Xth, Xtl, nullptr, SEQ, DIM);

    // --- projection Q ---
    transp_split<<<dim3(DIM / 32, DIM / 32), 256>>>(Wq, Wth, Wtm, Wtl, DIM, DIM);
    {
        GemmArgs a{};
        const __nv_bfloat16* As[6] = {Xh, Xh, Xm, Xh, Xl, Xm};
        const __nv_bfloat16* Bs[6] = {Wth, Wtm, Wth, Wtl, Wth, Wtm};
        for (int i = 0; i < 6; i++) { a.A[i] = As[i]; a.B[i] = Bs[i]; }
        a.K = DIM; a.ldc = DIM; a.alpha = 1.0f;
        a.Oh = Qh; a.Om = Qm; a.Ol = Ql;
        gemm_mma<6, 1><<<dim3(DIM / 128, SEQ / 128), 256, SMEM_GEMM>>>(a);
    }
    // --- projection K ---
    transp_split<<<dim3(DIM / 32, DIM / 32), 256>>>(Wk, Wth, Wtm, Wtl, DIM, DIM);
    {
        GemmArgs a{};
        const __nv_bfloat16* As[6] = {Xh, Xh, Xm, Xh, Xl, Xm};
        const __nv_bfloat16* Bs[6] = {Wth, Wtm, Wth, Wtl, Wth, Wtm};
        for (int i = 0; i < 6; i++) { a.A[i] = As[i]; a.B[i] = Bs[i]; }
        a.K = DIM; a.ldc = DIM; a.alpha = 1.0f;
        a.Oh = Kh; a.Om = Km; a.Ol = Kl;
        gemm_mma<6, 1><<<dim3(DIM / 128, SEQ / 128), 256, SMEM_GEMM>>>(a);
    }
    // --- S = (Q @ K^T) / 32 ---
    {
        GemmArgs a{};
        const __nv_bfloat16* As[6] = {Qh, Qh, Qm, Qh, Ql, Qm};
        const __nv_bfloat16* Bs[6] = {Kh, Km, Kh, Kl, Kh, Km};
        for (int i = 0; i < 6; i++) { a.A[i] = As[i]; a.B[i] = Bs[i]; }
        a.K = DIM; a.ldc = SEQ; a.alpha = 0.03125f;
        a.C = S;
        gemm_mma<6, 0><<<dim3(SEQ / 128, SEQ / 128), 256, SMEM_GEMM>>>(a);
    }
    // --- softmax + split of P ---
    softmax_split<<<SEQ, 256>>>(S, Ph, Pl, SEQ);
    // --- out = P @ X ---
    {
        GemmArgs a{};
        const __nv_bfloat16* As[3] = {Ph, Ph, Pl};
        const __nv_bfloat16* Bs[3] = {Xth, Xtl, Xth};
        for (int i = 0; i < 3; i++) { a.A[i] = As[i]; a.B[i] = Bs[i]; }
        a.K = SEQ; a.ldc = DIM; a.alpha = 1.0f;
        a.C = out;
        gemm_mma<3, 0><<<dim3(DIM / 128, SEQ / 128), 256, SMEM_GEMM>>>(a);
    }
}

// round 4
// speedup vs baseline: 1.5953x; 1.2956x over previous
#include <cuda_runtime.h>
#include <cuda_bf16.h>
#include <cstdint>
#include <math.h>

#define SEQ 8192
#define DIM 1024

// ---------------------------------------------------------------------------
// Scratch (device globals — allocation-free)
// ---------------------------------------------------------------------------
__device__ __align__(256) float g_S[(size_t)SEQ * SEQ];           // 256MB logits
__device__ __align__(256) __nv_bfloat16 g_Ph[(size_t)SEQ * SEQ];  // 128MB
__device__ __align__(256) __nv_bfloat16 g_Pl[(size_t)SEQ * SEQ];  // 128MB
__device__ __align__(256) __nv_bfloat16 g_Qh[SEQ * DIM], g_Qm[SEQ * DIM], g_Ql[SEQ * DIM];
__device__ __align__(256) __nv_bfloat16 g_Kh[SEQ * DIM], g_Km[SEQ * DIM], g_Kl[SEQ * DIM];
__device__ __align__(256) __nv_bfloat16 g_Xh[SEQ * DIM], g_Xm[SEQ * DIM], g_Xl[SEQ * DIM];
__device__ __align__(256) __nv_bfloat16 g_Xth[DIM * SEQ], g_Xtl[DIM * SEQ];
__device__ __align__(256) __nv_bfloat16 g_Wth[DIM * DIM], g_Wtm[DIM * DIM], g_Wtl[DIM * DIM];

// ---------------------------------------------------------------------------
// PTX helpers (baseline ISA only — valid on .target sm_103)
// ---------------------------------------------------------------------------
__device__ __forceinline__ uint32_t smem_u32(const void* p) {
    uint32_t a;
    asm("{ .reg .u64 t; cvta.to.shared.u64 t, %1; cvt.u32.u64 %0, t; }"
        : "=r"(a) : "l"(p));
    return a;
}

__device__ __forceinline__ void cp_async16(uint32_t saddr, const void* gaddr) {
    asm volatile("cp.async.cg.shared.global [%0], [%1], 16;"
                 :: "r"(saddr), "l"(gaddr));
}
#define CP_COMMIT() asm volatile("cp.async.commit_group;")
#define CP_WAIT(N)  asm volatile("cp.async.wait_group %0;" :: "n"(N))

__device__ __forceinline__ void ldsm4(uint32_t* r, uint32_t addr) {
    asm volatile("ldmatrix.sync.aligned.m8n8.x4.shared.b16 {%0,%1,%2,%3}, [%4];"
                 : "=r"(r[0]), "=r"(r[1]), "=r"(r[2]), "=r"(r[3])
                 : "r"(addr));
}

__device__ __forceinline__ void mma16816(float* d, const uint32_t* a,
                                         uint32_t b0, uint32_t b1) {
    asm volatile(
        "mma.sync.aligned.m16n8k16.row.col.f32.bf16.bf16.f32 "
        "{%0,%1,%2,%3}, {%4,%5,%6,%7}, {%8,%9}, {%0,%1,%2,%3};"
        : "+f"(d[0]), "+f"(d[1]), "+f"(d[2]), "+f"(d[3])
        : "r"(a[0]), "r"(a[1]), "r"(a[2]), "r"(a[3]), "r"(b0), "r"(b1));
}

// swizzled smem byte offset for (row, 16B-segment) in a 64B-pitch tile
__device__ __forceinline__ uint32_t swz(int row, int seg) {
    return (uint32_t)(row * 64 + ((seg ^ ((row >> 1) & 3)) << 4));
}

// ---------------------------------------------------------------------------
// HMMA GEMM:  D[128x256 tile] = alpha * sum_p A_p[M,K] @ B_p[N,K]^T
// A, B K-major bf16. fp32 register accumulation across all pairs.
// Warp tile 64x64 (2x4 warps). EPI 0: C = alpha*D. EPI 1: 3-way bf16 split.
// ---------------------------------------------------------------------------
struct GemmArgs {
    const __nv_bfloat16* A[6];
    const __nv_bfloat16* B[6];
    int K;        // per-pair reduction length (multiple of 32)
    int ldc;
    float alpha;
    float* C;
    __nv_bfloat16 *Oh, *Om, *Ol;
};

template <int NPAIRS, int EPI>
__global__ __launch_bounds__(256, 1)
void gemm_mma(const GemmArgs args)
{
    constexpr int BM = 128, BN = 256, BK = 32, STAGES = 4;
    constexpr int A_B = BM * 64;               // 8KB
    constexpr int B_B = BN * 64;               // 16KB
    constexpr int STAGE_B = A_B + B_B;         // 24KB
    extern __shared__ __align__(128) char smem[];
    const uint32_t sbase = smem_u32(smem);

    const int tid = threadIdx.x;
    const int wid = tid >> 5;
    const int lane = tid & 31;
    const int wm = wid & 1;          // 2 warps along M (64 rows each)
    const int wn = wid >> 1;         // 4 warps along N (64 cols each)
    const int bm = blockIdx.y * BM;
    const int bn = blockIdx.x * BN;
    const int K = args.K;
    const int nchunk = K / BK;
    const int total = NPAIRS * nchunk;

    // per-lane ldmatrix offsets
    const int sub = lane >> 3, r8 = lane & 7;
    uint32_t aoff[2][4], boff[2][4];
#pragma unroll
    for (int kk = 0; kk < 2; kk++) {
#pragma unroll
        for (int mi = 0; mi < 4; mi++) {
            int row = wm * 64 + mi * 16 + (sub & 1) * 8 + r8;
            int seg = 2 * kk + (sub >> 1);
            aoff[kk][mi] = swz(row, seg);
        }
#pragma unroll
        for (int nj = 0; nj < 4; nj++) {
            int row = wn * 64 + nj * 16 + (sub >> 1) * 8 + r8;
            int seg = 2 * kk + (sub & 1);
            boff[kk][nj] = swz(row, seg);
        }
    }

    // cp.async mapping: 6 chunks/thread (2 for A, 4 for B)
    const int ld_row = tid >> 2;         // 0..63
    const int ld_seg = tid & 3;
    const size_t g_off0 = (size_t)ld_row * K + ld_seg * 8;

    float acc[4][8][4];
#pragma unroll
    for (int mi = 0; mi < 4; mi++)
#pragma unroll
        for (int ni = 0; ni < 8; ni++)
#pragma unroll
            for (int v = 0; v < 4; v++) acc[mi][ni][v] = 0.0f;

    auto issue_tile = [&](int t, int s) {
        const int p = t / nchunk;
        const int c = t - p * nchunk;
        const __nv_bfloat16* Ap = args.A[p] + (size_t)bm * K + c * BK;
        const __nv_bfloat16* Bp = args.B[p] + (size_t)bn * K + c * BK;
        const uint32_t as = sbase + s * STAGE_B;
        const uint32_t bs = as + A_B;
        const size_t rstep = (size_t)64 * K;
#pragma unroll
        for (int r = 0; r < 2; r++)
            cp_async16(as + swz(ld_row + r * 64, ld_seg), Ap + g_off0 + r * rstep);
#pragma unroll
        for (int r = 0; r < 4; r++)
            cp_async16(bs + swz(ld_row + r * 64, ld_seg), Bp + g_off0 + r * rstep);
    };

#pragma unroll
    for (int j = 0; j < STAGES - 1; j++) {
        issue_tile(j, j);
        CP_COMMIT();
    }

    for (int i = 0; i < total; i++) {
        CP_WAIT(STAGES - 2);
        __syncthreads();
        if (i + STAGES - 1 < total) issue_tile(i + STAGES - 1, (i + STAGES - 1) % STAGES);
        CP_COMMIT();

        const int s = i % STAGES;
        const uint32_t as = sbase + s * STAGE_B;
        const uint32_t bs = as + A_B;
#pragma unroll
        for (int kk = 0; kk < 2; kk++) {
            uint32_t br[4][4];
#pragma unroll
            for (int nj = 0; nj < 4; nj++) ldsm4(br[nj], bs + boff[kk][nj]);
#pragma unroll
            for (int mi = 0; mi < 4; mi++) {
                uint32_t ar[4];
                ldsm4(ar, as + aoff[kk][mi]);
#pragma unroll
                for (int ni = 0; ni < 8; ni++) {
                    const int nj = ni >> 1, o = (ni & 1) * 2;
                    mma16816(acc[mi][ni], ar, br[nj][o], br[nj][o + 1]);
                }
            }
        }
        __syncthreads();
    }

    // ---- epilogue from registers ----
    const int ldc = args.ldc;
#pragma unroll
    for (int mi = 0; mi < 4; mi++) {
#pragma unroll
        for (int ni = 0; ni < 8; ni++) {
            const int r0 = bm + wm * 64 + mi * 16 + (lane >> 2);
            const int c0 = bn + wn * 64 + ni * 8 + (lane & 3) * 2;
#pragma unroll
            for (int h = 0; h < 2; h++) {
                const size_t o = (size_t)(r0 + h * 8) * ldc + c0;
                const float v0 = acc[mi][ni][2 * h + 0];
                const float v1 = acc[mi][ni][2 * h + 1];
                if (EPI == 0) {
                    float2 w;
                    w.x = args.alpha * v0;
                    w.y = args.alpha * v1;
                    *(float2*)(args.C + o) = w;
                } else {
                    __nv_bfloat16 h0 = __float2bfloat16(v0);
                    __nv_bfloat16 h1 = __float2bfloat16(v1);
                    float rm0 = v0 - __bfloat162float(h0);
                    float rm1 = v1 - __bfloat162float(h1);
                    __nv_bfloat16 m0 = __float2bfloat16(rm0);
                    __nv_bfloat16 m1 = __float2bfloat16(rm1);
                    float rl0 = rm0 - __bfloat162float(m0);
                    float rl1 = rm1 - __bfloat162float(m1);
                    __nv_bfloat16 l0 = __float2bfloat16(rl0);
                    __nv_bfloat16 l1 = __float2bfloat16(rl1);
                    uint32_t ph = (uint32_t)*(unsigned short*)&h0 |
                                  ((uint32_t)*(unsigned short*)&h1 << 16);
                    uint32_t pm = (uint32_t)*(unsigned short*)&m0 |
                                  ((uint32_t)*(unsigned short*)&m1 << 16);
                    uint32_t pl = (uint32_t)*(unsigned short*)&l0 |
                                  ((uint32_t)*(unsigned short*)&l1 << 16);
                    *(uint32_t*)((unsigned short*)args.Oh + o) = ph;
                    *(uint32_t*)((unsigned short*)args.Om + o) = pm;
                    *(uint32_t*)((unsigned short*)args.Ol + o) = pl;
                }
            }
        }
    }
}

// ---------------------------------------------------------------------------
// elementwise 3-way split
// ---------------------------------------------------------------------------
__global__ __launch_bounds__(256)
void split3_kernel(const float* __restrict__ in, __nv_bfloat16* __restrict__ oh,
                   __nv_bfloat16* __restrict__ om, __nv_bfloat16* __restrict__ ol)
{
    size_t i = (size_t)blockIdx.x * 256 + threadIdx.x;
    float v = in[i];
    __nv_bfloat16 h = __float2bfloat16(v);
    float r1 = v - __bfloat162float(h);
    __nv_bfloat16 m = __float2bfloat16(r1);
    float r2 = r1 - __bfloat162float(m);
    oh[i] = h;
    om[i] = m;
    ol[i] = __float2bfloat16(r2);
}

// ---------------------------------------------------------------------------
// transpose + split: in[R][C] fp32 -> out*[C][R] bf16 (om/ol optional)
// ---------------------------------------------------------------------------
__global__ __launch_bounds__(256)
void transp_split(const float* __restrict__ in, __nv_bfloat16* oh,
                  __nv_bfloat16* om, __nv_bfloat16* ol, int R, int C)
{
    __shared__ float t[32][33];
    const int bc = blockIdx.x * 32, br = blockIdx.y * 32;
    const int tx = threadIdx.x & 31, ty = threadIdx.x >> 5;   // 32 x 8
#pragma unroll
    for (int j = 0; j < 32; j += 8)
        t[ty + j][tx] = in[(size_t)(br + ty + j) * C + bc + tx];
    __syncthreads();
#pragma unroll
    for (int j = 0; j < 32; j += 8) {
        int oc = bc + ty + j;
        float v = t[tx][ty + j];
        __nv_bfloat16 h = __float2bfloat16(v);
        float r1 = v - __bfloat162float(h);
        size_t o = (size_t)oc * R + br + tx;
        oh[o] = h;
        if (om) {
            __nv_bfloat16 m = __float2bfloat16(r1);
            om[o] = m;
            if (ol) {
                float r2 = r1 - __bfloat162float(m);
                ol[o] = __float2bfloat16(r2);
            }
        }
    }
}

// ---------------------------------------------------------------------------
// softmax over rows of S, emitting 2-way bf16 split of P. Row cached in SMEM.
// ---------------------------------------------------------------------------
__global__ __launch_bounds__(256)
void softmax_split(const float* __restrict__ S, __nv_bfloat16* __restrict__ Ph,
                   __nv_bfloat16* __restrict__ Pl, int n)
{
    __shared__ float row[SEQ];
    __shared__ float red[256];
    const float* s = S + (size_t)blockIdx.x * n;
    const int tid = threadIdx.x;

    float m = -3.4e38f;
    for (int i = tid; i < n; i += 256) {
        float v = s[i];
        row[i] = v;
        m = fmaxf(m, v);
    }
    red[tid] = m;
    __syncthreads();
    for (int st = 128; st > 0; st >>= 1) {
        if (tid < st) red[tid] = fmaxf(red[tid], red[tid + st]);
        __syncthreads();
    }
    m = red[0];
    __syncthreads();

    float sum = 0.0f;
    for (int i = tid; i < n; i += 256) {
        float e = expf(row[i] - m);
        row[i] = e;
        sum += e;
    }
    red[tid] = sum;
    __syncthreads();
    for (int st = 128; st > 0; st >>= 1) {
        if (tid < st) red[tid] += red[tid + st];
        __syncthreads();
    }
    const float inv = 1.0f / red[0];
    __syncthreads();

    __nv_bfloat16* ph = Ph + (size_t)blockIdx.x * n;
    __nv_bfloat16* pl = Pl + (size_t)blockIdx.x * n;
    for (int i = tid; i < n; i += 256) {
        float p = row[i] * inv;
        __nv_bfloat16 h = __float2bfloat16(p);
        float r1 = p - __bfloat162float(h);
        ph[i] = h;
        pl[i] = __float2bfloat16(r1);
    }
}

// ---------------------------------------------------------------------------
extern "C" void kernel_launch(void* const* d_in, const int* in_sizes, int n_in,
                              void* d_out, int out_size)
{
    const float* X  = (const float*)d_in[0];
    const float* Wq = (const float*)d_in[1];
    const float* Wk = (const float*)d_in[2];
    float* out = (float*)d_out;

    void* p;
#define SYM(name, var) cudaGetSymbolAddress(&p, name); auto* var = (decltype(&name[0]))p;
    SYM(g_S, S) SYM(g_Ph, Ph) SYM(g_Pl, Pl)
    SYM(g_Qh, Qh) SYM(g_Qm, Qm) SYM(g_Ql, Ql)
    SYM(g_Kh, Kh) SYM(g_Km, Km) SYM(g_Kl, Kl)
    SYM(g_Xh, Xh) SYM(g_Xm, Xm) SYM(g_Xl, Xl)
    SYM(g_Xth, Xth) SYM(g_Xtl, Xtl)
    SYM(g_Wth, Wth) SYM(g_Wtm, Wtm) SYM(g_Wtl, Wtl)
#undef SYM

    const int SMEM_GEMM = 4 * 24576;   // 4 stages x 24KB
    cudaFuncSetAttribute(gemm_mma<6, 0>, cudaFuncAttributeMaxDynamicSharedMemorySize, SMEM_GEMM);
    cudaFuncSetAttribute(gemm_mma<6, 1>, cudaFuncAttributeMaxDynamicSharedMemorySize, SMEM_GEMM);
    cudaFuncSetAttribute(gemm_mma<3, 0>, cudaFuncAttributeMaxDynamicSharedMemorySize, SMEM_GEMM);

    // --- prep: splits & transposes ---
    split3_kernel<<<SEQ * DIM / 256, 256>>>(X, Xh, Xm, Xl);
    transp_split<<<dim3(DIM / 32, SEQ / 32), 256>>>(X, Xth, Xtl, nullptr, SEQ, DIM);

    // --- projection Q ---
    transp_split<<<dim3(DIM / 32, DIM / 32), 256>>>(Wq, Wth, Wtm, Wtl, DIM, DIM);
    {
        GemmArgs a{};
        const __nv_bfloat16* As[6] = {Xh, Xh, Xm, Xh, Xl, Xm};
        const __nv_bfloat16* Bs[6] = {Wth, Wtm, Wth, Wtl, Wth, Wtm};
        for (int i = 0; i < 6; i++) { a.A[i] = As[i]; a.B[i] = Bs[i]; }
        a.K = DIM; a.ldc = DIM; a.alpha = 1.0f;
        a.Oh = Qh; a.Om = Qm; a.Ol = Ql;
        gemm_mma<6, 1><<<dim3(DIM / 256, SEQ / 128), 256, SMEM_GEMM>>>(a);
    }
    // --- projection K ---
    transp_split<<<dim3(DIM / 32, DIM / 32), 256>>>(Wk, Wth, Wtm, Wtl, DIM, DIM);
    {
        GemmArgs a{};
        const __nv_bfloat16* As[6] = {Xh, Xh, Xm, Xh, Xl, Xm};
        const __nv_bfloat16* Bs[6] = {Wth, Wtm, Wth, Wtl, Wth, Wtm};
        for (int i = 0; i < 6; i++) { a.A[i] = As[i]; a.B[i] = Bs[i]; }
        a.K = DIM; a.ldc = DIM; a.alpha = 1.0f;
        a.Oh = Kh; a.Om = Km; a.Ol = Kl;
        gemm_mma<6, 1><<<dim3(DIM / 256, SEQ / 128), 256, SMEM_GEMM>>>(a);
    }
    // --- S = (Q @ K^T) / 32 ---
    {
        GemmArgs a{};
        const __nv_bfloat16* As[6] = {Qh, Qh, Qm, Qh, Ql, Qm};
        const __nv_bfloat16* Bs[6] = {Kh, Km, Kh, Kl, Kh, Km};
        for (int i = 0; i < 6; i++) { a.A[i] = As[i]; a.B[i] = Bs[i]; }
        a.K = DIM; a.ldc = SEQ; a.alpha = 0.03125f;
        a.C = S;
        gemm_mma<6, 0><<<dim3(SEQ / 256, SEQ / 128), 256, SMEM_GEMM>>>(a);
    }
    // --- softmax + split of P ---
    softmax_split<<<SEQ, 256>>>(S, Ph, Pl, SEQ);
    // --- out = P @ X ---
    {
        GemmArgs a{};
        const __nv_bfloat16* As[3] = {Ph, Ph, Pl};
        const __nv_bfloat16* Bs[3] = {Xth, Xtl, Xth};
        for (int i = 0; i < 3; i++) { a.A[i] = As[i]; a.B[i] = Bs[i]; }
        a.K = SEQ; a.ldc = DIM; a.alpha = 1.0f;
        a.C = out;
        gemm_mma<3, 0><<<dim3(DIM / 256, SEQ / 128), 256, SMEM_GEMM>>>(a);
    }
}

// round 5
// speedup vs baseline: 2.1002x; 1.3165x over previous
#include <cuda_runtime.h>
#include <cuda_bf16.h>
#include <cuda_fp16.h>
#include <cstdint>
#include <math.h>

#define SEQ 8192
#define DIM 1024

// ---------------------------------------------------------------------------
// Scratch (device globals — allocation-free)
// ---------------------------------------------------------------------------
__device__ __align__(256) float g_S[(size_t)SEQ * SEQ];           // 256MB logits
__device__ __align__(256) __nv_bfloat16 g_Ph[(size_t)SEQ * SEQ];  // 128MB
__device__ __align__(256) __nv_bfloat16 g_Pl[(size_t)SEQ * SEQ];  // 128MB
__device__ __align__(256) __half g_Qh[SEQ * DIM], g_Qm[SEQ * DIM];
__device__ __align__(256) __half g_Kh[SEQ * DIM], g_Km[SEQ * DIM];
__device__ __align__(256) __half g_Xh[SEQ * DIM], g_Xm[SEQ * DIM];
__device__ __align__(256) __nv_bfloat16 g_Xth[DIM * SEQ], g_Xtl[DIM * SEQ];
__device__ __align__(256) __half g_Wth[DIM * DIM], g_Wtm[DIM * DIM];

// ---------------------------------------------------------------------------
// PTX helpers (baseline ISA only — valid on .target sm_103)
// ---------------------------------------------------------------------------
__device__ __forceinline__ uint32_t smem_u32(const void* p) {
    uint32_t a;
    asm("{ .reg .u64 t; cvta.to.shared.u64 t, %1; cvt.u32.u64 %0, t; }"
        : "=r"(a) : "l"(p));
    return a;
}

__device__ __forceinline__ void cp_async16(uint32_t saddr, const void* gaddr) {
    asm volatile("cp.async.cg.shared.global [%0], [%1], 16;"
                 :: "r"(saddr), "l"(gaddr));
}
#define CP_COMMIT() asm volatile("cp.async.commit_group;")
#define CP_WAIT(N)  asm volatile("cp.async.wait_group %0;" :: "n"(N))

__device__ __forceinline__ void ldsm4(uint32_t* r, uint32_t addr) {
    asm volatile("ldmatrix.sync.aligned.m8n8.x4.shared.b16 {%0,%1,%2,%3}, [%4];"
                 : "=r"(r[0]), "=r"(r[1]), "=r"(r[2]), "=r"(r[3])
                 : "r"(addr));
}

// FT = 0 -> bf16 inputs, FT = 1 -> fp16 inputs. fp32 accumulate.
template <int FT>
__device__ __forceinline__ void mma16816(float* d, const uint32_t* a,
                                         uint32_t b0, uint32_t b1) {
    if (FT == 0) {
        asm volatile(
            "mma.sync.aligned.m16n8k16.row.col.f32.bf16.bf16.f32 "
            "{%0,%1,%2,%3}, {%4,%5,%6,%7}, {%8,%9}, {%0,%1,%2,%3};"
            : "+f"(d[0]), "+f"(d[1]), "+f"(d[2]), "+f"(d[3])
            : "r"(a[0]), "r"(a[1]), "r"(a[2]), "r"(a[3]), "r"(b0), "r"(b1));
    } else {
        asm volatile(
            "mma.sync.aligned.m16n8k16.row.col.f32.f16.f16.f32 "
            "{%0,%1,%2,%3}, {%4,%5,%6,%7}, {%8,%9}, {%0,%1,%2,%3};"
            : "+f"(d[0]), "+f"(d[1]), "+f"(d[2]), "+f"(d[3])
            : "r"(a[0]), "r"(a[1]), "r"(a[2]), "r"(a[3]), "r"(b0), "r"(b1));
    }
}

// swizzled smem byte offset for (row, 16B-segment) in a 64B-pitch tile
__device__ __forceinline__ uint32_t swz(int row, int seg) {
    return (uint32_t)(row * 64 + ((seg ^ ((row >> 1) & 3)) << 4));
}

// ---------------------------------------------------------------------------
// HMMA GEMM:  D[128x256 tile] = alpha * sum_p A_p[M,K] @ B_p[N,K]^T
// Operands K-major 16-bit (bf16 or fp16 per FT). fp32 register accumulation.
// Warp tile 64x64 (2x4 warps). One __syncthreads per mainloop iteration.
// EPI 0: C = alpha*D (fp32). EPI 1: 2-way fp16 split of D.
// ---------------------------------------------------------------------------
struct GemmArgs {
    const void* A[4];
    const void* B[4];
    int K;        // per-pair reduction length (multiple of 32)
    int ldc;
    float alpha;
    float* C;
    __half *Oh, *Om;
};

template <int NPAIRS, int EPI, int FT>
__global__ __launch_bounds__(256, 1)
void gemm_mma(const GemmArgs args)
{
    constexpr int BM = 128, BN = 256, BK = 32, STAGES = 4;
    constexpr int A_B = BM * 64;               // 8KB
    constexpr int B_B = BN * 64;               // 16KB
    constexpr int STAGE_B = A_B + B_B;         // 24KB
    extern __shared__ __align__(128) char smem[];
    const uint32_t sbase = smem_u32(smem);

    const int tid = threadIdx.x;
    const int wid = tid >> 5;
    const int lane = tid & 31;
    const int wm = wid & 1;          // 2 warps along M (64 rows each)
    const int wn = wid >> 1;         // 4 warps along N (64 cols each)
    const int bm = blockIdx.y * BM;
    const int bn = blockIdx.x * BN;
    const int K = args.K;
    const int nchunk = K / BK;
    const int total = NPAIRS * nchunk;

    // per-lane ldmatrix offsets
    const int sub = lane >> 3, r8 = lane & 7;
    uint32_t aoff[2][4], boff[2][4];
#pragma unroll
    for (int kk = 0; kk < 2; kk++) {
#pragma unroll
        for (int mi = 0; mi < 4; mi++) {
            int row = wm * 64 + mi * 16 + (sub & 1) * 8 + r8;
            int seg = 2 * kk + (sub >> 1);
            aoff[kk][mi] = swz(row, seg);
        }
#pragma unroll
        for (int nj = 0; nj < 4; nj++) {
            int row = wn * 64 + nj * 16 + (sub >> 1) * 8 + r8;
            int seg = 2 * kk + (sub & 1);
            boff[kk][nj] = swz(row, seg);
        }
    }

    // cp.async mapping: 6 chunks/thread (2 for A, 4 for B)
    const int ld_row = tid >> 2;         // 0..63
    const int ld_seg = tid & 3;
    const size_t g_off0 = (size_t)ld_row * K + ld_seg * 8;

    float acc[4][8][4];
#pragma unroll
    for (int mi = 0; mi < 4; mi++)
#pragma unroll
        for (int ni = 0; ni < 8; ni++)
#pragma unroll
            for (int v = 0; v < 4; v++) acc[mi][ni][v] = 0.0f;

    auto issue_tile = [&](int t, int s) {
        const int p = t / nchunk;
        const int c = t - p * nchunk;
        const unsigned short* Ap = (const unsigned short*)args.A[p] + (size_t)bm * K + c * BK;
        const unsigned short* Bp = (const unsigned short*)args.B[p] + (size_t)bn * K + c * BK;
        const uint32_t as = sbase + s * STAGE_B;
        const uint32_t bs = as + A_B;
        const size_t rstep = (size_t)64 * K;
#pragma unroll
        for (int r = 0; r < 2; r++)
            cp_async16(as + swz(ld_row + r * 64, ld_seg), Ap + g_off0 + r * rstep);
#pragma unroll
        for (int r = 0; r < 4; r++)
            cp_async16(bs + swz(ld_row + r * 64, ld_seg), Bp + g_off0 + r * rstep);
    };

    // prologue: issue stages 0..2
#pragma unroll
    for (int j = 0; j < STAGES - 1; j++) {
        issue_tile(j, j);
        CP_COMMIT();
    }
    CP_WAIT(STAGES - 2);
    __syncthreads();

    for (int i = 0; i < total; i++) {
        // issue next tile first (overlaps DMA with this iteration's math).
        // It writes slot (i+3)%4 == (i-1)%4; the barrier that ended iteration
        // i-1 guarantees every warp finished reading that slot.
        if (i + STAGES - 1 < total) issue_tile(i + STAGES - 1, (i + STAGES - 1) % STAGES);
        CP_COMMIT();

        const int s = i % STAGES;
        const uint32_t as = sbase + s * STAGE_B;
        const uint32_t bs = as + A_B;
#pragma unroll
        for (int kk = 0; kk < 2; kk++) {
            uint32_t br[4][4];
#pragma unroll
            for (int nj = 0; nj < 4; nj++) ldsm4(br[nj], bs + boff[kk][nj]);
#pragma unroll
            for (int mi = 0; mi < 4; mi++) {
                uint32_t ar[4];
                ldsm4(ar, as + aoff[kk][mi]);
#pragma unroll
                for (int ni = 0; ni < 8; ni++) {
                    const int nj = ni >> 1, o = (ni & 1) * 2;
                    mma16816<FT>(acc[mi][ni], ar, br[nj][o], br[nj][o + 1]);
                }
            }
        }
        CP_WAIT(STAGES - 2);   // tile i+1 resident
        __syncthreads();       // everyone done with slot i
    }

    // ---- epilogue from registers ----
    const int ldc = args.ldc;
#pragma unroll
    for (int mi = 0; mi < 4; mi++) {
#pragma unroll
        for (int ni = 0; ni < 8; ni++) {
            const int r0 = bm + wm * 64 + mi * 16 + (lane >> 2);
            const int c0 = bn + wn * 64 + ni * 8 + (lane & 3) * 2;
#pragma unroll
            for (int h = 0; h < 2; h++) {
                const size_t o = (size_t)(r0 + h * 8) * ldc + c0;
                const float v0 = acc[mi][ni][2 * h + 0];
                const float v1 = acc[mi][ni][2 * h + 1];
                if (EPI == 0) {
                    float2 w;
                    w.x = args.alpha * v0;
                    w.y = args.alpha * v1;
                    *(float2*)(args.C + o) = w;
                } else {
                    __half h0 = __float2half_rn(v0);
                    __half h1 = __float2half_rn(v1);
                    __half m0 = __float2half_rn(v0 - __half2float(h0));
                    __half m1 = __float2half_rn(v1 - __half2float(h1));
                    uint32_t ph = (uint32_t)*(unsigned short*)&h0 |
                                  ((uint32_t)*(unsigned short*)&h1 << 16);
                    uint32_t pm = (uint32_t)*(unsigned short*)&m0 |
                                  ((uint32_t)*(unsigned short*)&m1 << 16);
                    *(uint32_t*)((unsigned short*)args.Oh + o) = ph;
                    *(uint32_t*)((unsigned short*)args.Om + o) = pm;
                }
            }
        }
    }
}

// ---------------------------------------------------------------------------
// elementwise 2-way fp16 split
// ---------------------------------------------------------------------------
__global__ __launch_bounds__(256)
void split2h_kernel(const float* __restrict__ in, __half* __restrict__ oh,
                    __half* __restrict__ om)
{
    size_t i = (size_t)blockIdx.x * 256 + threadIdx.x;
    float v = in[i];
    __half h = __float2half_rn(v);
    om[i] = __float2half_rn(v - __half2float(h));
    oh[i] = h;
}

// ---------------------------------------------------------------------------
// transpose + 2-way fp16 split: in[R][C] fp32 -> oh/om [C][R] fp16
// ---------------------------------------------------------------------------
__global__ __launch_bounds__(256)
void transp_split2h(const float* __restrict__ in, __half* oh, __half* om,
                    int R, int C)
{
    __shared__ float t[32][33];
    const int bc = blockIdx.x * 32, br = blockIdx.y * 32;
    const int tx = threadIdx.x & 31, ty = threadIdx.x >> 5;
#pragma unroll
    for (int j = 0; j < 32; j += 8)
        t[ty + j][tx] = in[(size_t)(br + ty + j) * C + bc + tx];
    __syncthreads();
#pragma unroll
    for (int j = 0; j < 32; j += 8) {
        int oc = bc + ty + j;
        float v = t[tx][ty + j];
        __half h = __float2half_rn(v);
        size_t o = (size_t)oc * R + br + tx;
        oh[o] = h;
        om[o] = __float2half_rn(v - __half2float(h));
    }
}

// ---------------------------------------------------------------------------
// transpose + 2-way bf16 split: in[R][C] fp32 -> oh/ol [C][R] bf16
// ---------------------------------------------------------------------------
__global__ __launch_bounds__(256)
void transp_split2b(const float* __restrict__ in, __nv_bfloat16* oh,
                    __nv_bfloat16* ol, int R, int C)
{
    __shared__ float t[32][33];
    const int bc = blockIdx.x * 32, br = blockIdx.y * 32;
    const int tx = threadIdx.x & 31, ty = threadIdx.x >> 5;
#pragma unroll
    for (int j = 0; j < 32; j += 8)
        t[ty + j][tx] = in[(size_t)(br + ty + j) * C + bc + tx];
    __syncthreads();
#pragma unroll
    for (int j = 0; j < 32; j += 8) {
        int oc = bc + ty + j;
        float v = t[tx][ty + j];
        __nv_bfloat16 h = __float2bfloat16(v);
        size_t o = (size_t)oc * R + br + tx;
        oh[o] = h;
        ol[o] = __float2bfloat16(v - __bfloat162float(h));
    }
}

// ---------------------------------------------------------------------------
// softmax over rows of S, emitting 2-way bf16 split of P. Row cached in SMEM.
// ---------------------------------------------------------------------------
__global__ __launch_bounds__(256)
void softmax_split(const float* __restrict__ S, __nv_bfloat16* __restrict__ Ph,
                   __nv_bfloat16* __restrict__ Pl, int n)
{
    __shared__ float row[SEQ];
    __shared__ float red[256];
    const float* s = S + (size_t)blockIdx.x * n;
    const int tid = threadIdx.x;

    float m = -3.4e38f;
    for (int i = tid; i < n; i += 256) {
        float v = s[i];
        row[i] = v;
        m = fmaxf(m, v);
    }
    red[tid] = m;
    __syncthreads();
    for (int st = 128; st > 0; st >>= 1) {
        if (tid < st) red[tid] = fmaxf(red[tid], red[tid + st]);
        __syncthreads();
    }
    m = red[0];
    __syncthreads();

    float sum = 0.0f;
    for (int i = tid; i < n; i += 256) {
        float e = expf(row[i] - m);
        row[i] = e;
        sum += e;
    }
    red[tid] = sum;
    __syncthreads();
    for (int st = 128; st > 0; st >>= 1) {
        if (tid < st) red[tid] += red[tid + st];
        __syncthreads();
    }
    const float inv = 1.0f / red[0];
    __syncthreads();

    __nv_bfloat16* ph = Ph + (size_t)blockIdx.x * n;
    __nv_bfloat16* pl = Pl + (size_t)blockIdx.x * n;
    for (int i = tid; i < n; i += 256) {
        float p = row[i] * inv;
        __nv_bfloat16 h = __float2bfloat16(p);
        ph[i] = h;
        pl[i] = __float2bfloat16(p - __bfloat162float(h));
    }
}

// ---------------------------------------------------------------------------
extern "C" void kernel_launch(void* const* d_in, const int* in_sizes, int n_in,
                              void* d_out, int out_size)
{
    const float* X  = (const float*)d_in[0];
    const float* Wq = (const float*)d_in[1];
    const float* Wk = (const float*)d_in[2];
    float* out = (float*)d_out;

    void* p;
#define SYM(name, var) cudaGetSymbolAddress(&p, name); auto* var = (decltype(&name[0]))p;
    SYM(g_S, S) SYM(g_Ph, Ph) SYM(g_Pl, Pl)
    SYM(g_Qh, Qh) SYM(g_Qm, Qm)
    SYM(g_Kh, Kh) SYM(g_Km, Km)
    SYM(g_Xh, Xh) SYM(g_Xm, Xm)
    SYM(g_Xth, Xth) SYM(g_Xtl, Xtl)
    SYM(g_Wth, Wth) SYM(g_Wtm, Wtm)
#undef SYM

    const int SMEM_GEMM = 4 * 24576;   // 4 stages x 24KB
    cudaFuncSetAttribute(gemm_mma<3, 1, 1>, cudaFuncAttributeMaxDynamicSharedMemorySize, SMEM_GEMM);
    cudaFuncSetAttribute(gemm_mma<4, 0, 1>, cudaFuncAttributeMaxDynamicSharedMemorySize, SMEM_GEMM);
    cudaFuncSetAttribute(gemm_mma<3, 0, 0>, cudaFuncAttributeMaxDynamicSharedMemorySize, SMEM_GEMM);

    // --- prep: splits & transposes ---
    split2h_kernel<<<SEQ * DIM / 256, 256>>>(X, Xh, Xm);
    transp_split2b<<<dim3(DIM / 32, SEQ / 32), 256>>>(X, Xth, Xtl, SEQ, DIM);

    // --- projection Q: 3 fp16 products ---
    transp_split2h<<<dim3(DIM / 32, DIM / 32), 256>>>(Wq, Wth, Wtm, DIM, DIM);
    {
        GemmArgs a{};
        const void* As[3] = {Xh, Xh, Xm};
        const void* Bs[3] = {Wth, Wtm, Wth};
        for (int i = 0; i < 3; i++) { a.A[i] = As[i]; a.B[i] = Bs[i]; }
        a.K = DIM; a.ldc = DIM; a.alpha = 1.0f;
        a.Oh = Qh; a.Om = Qm;
        gemm_mma<3, 1, 1><<<dim3(DIM / 256, SEQ / 128), 256, SMEM_GEMM>>>(a);
    }
    // --- projection K ---
    transp_split2h<<<dim3(DIM / 32, DIM / 32), 256>>>(Wk, Wth, Wtm, DIM, DIM);
    {
        GemmArgs a{};
        const void* As[3] = {Xh, Xh, Xm};
        const void* Bs[3] = {Wth, Wtm, Wth};
        for (int i = 0; i < 3; i++) { a.A[i] = As[i]; a.B[i] = Bs[i]; }
        a.K = DIM; a.ldc = DIM; a.alpha = 1.0f;
        a.Oh = Kh; a.Om = Km;
        gemm_mma<3, 1, 1><<<dim3(DIM / 256, SEQ / 128), 256, SMEM_GEMM>>>(a);
    }
    // --- S = (Q @ K^T) / 32 : 4 fp16 products {hh, hm, mh, mm} ---
    {
        GemmArgs a{};
        const void* As[4] = {Qh, Qh, Qm, Qm};
        const void* Bs[4] = {Kh, Km, Kh, Km};
        for (int i = 0; i < 4; i++) { a.A[i] = As[i]; a.B[i] = Bs[i]; }
        a.K = DIM; a.ldc = SEQ; a.alpha = 0.03125f;
        a.C = S;
        gemm_mma<4, 0, 1><<<dim3(SEQ / 256, SEQ / 128), 256, SMEM_GEMM>>>(a);
    }
    // --- softmax + split of P ---
    softmax_split<<<SEQ, 256>>>(S, Ph, Pl, SEQ);
    // --- out = P @ X : 3 bf16 products ---
    {
        GemmArgs a{};
        const void* As[3] = {Ph, Ph, Pl};
        const void* Bs[3] = {Xth, Xtl, Xth};
        for (int i = 0; i < 3; i++) { a.A[i] = As[i]; a.B[i] = Bs[i]; }
        a.K = SEQ; a.ldc = DIM; a.alpha = 1.0f;
        a.C = out;
        gemm_mma<3, 0, 0><<<dim3(DIM / 256, SEQ / 128), 256, SMEM_GEMM>>>(a);
    }
}

// round 6
// speedup vs baseline: 2.6933x; 1.2824x over previous
#include <cuda_runtime.h>
#include <cuda_bf16.h>
#include <cuda_fp16.h>
#include <cstdint>
#include <math.h>

#define SEQ 8192
#define DIM 1024

// ---------------------------------------------------------------------------
// Scratch (device globals — allocation-free)
// ---------------------------------------------------------------------------
__device__ __align__(256) float g_S[(size_t)SEQ * SEQ];           // 256MB logits
__device__ __align__(256) __nv_bfloat16 g_Ph[(size_t)SEQ * SEQ];  // 128MB
__device__ __align__(256) __nv_bfloat16 g_Pl[(size_t)SEQ * SEQ];  // 128MB
__device__ __align__(256) __half g_Qh[SEQ * DIM], g_Qm[SEQ * DIM];
__device__ __align__(256) __half g_Kh[SEQ * DIM], g_Km[SEQ * DIM];
__device__ __align__(256) __half g_Xh[SEQ * DIM], g_Xm[SEQ * DIM];
__device__ __align__(256) __nv_bfloat16 g_Xth[DIM * SEQ], g_Xtl[DIM * SEQ];
__device__ __align__(256) __half g_Wth[DIM * DIM], g_Wtm[DIM * DIM];

// ---------------------------------------------------------------------------
// PTX helpers (baseline ISA only — valid on .target sm_103)
// ---------------------------------------------------------------------------
__device__ __forceinline__ uint32_t smem_u32(const void* p) {
    uint32_t a;
    asm("{ .reg .u64 t; cvta.to.shared.u64 t, %1; cvt.u32.u64 %0, t; }"
        : "=r"(a) : "l"(p));
    return a;
}

__device__ __forceinline__ void cp_async16(uint32_t saddr, const void* gaddr) {
    asm volatile("cp.async.cg.shared.global [%0], [%1], 16;"
                 :: "r"(saddr), "l"(gaddr));
}
#define CP_COMMIT() asm volatile("cp.async.commit_group;")
#define CP_WAIT(N)  asm volatile("cp.async.wait_group %0;" :: "n"(N))

__device__ __forceinline__ void ldsm4(uint32_t* r, uint32_t addr) {
    asm volatile("ldmatrix.sync.aligned.m8n8.x4.shared.b16 {%0,%1,%2,%3}, [%4];"
                 : "=r"(r[0]), "=r"(r[1]), "=r"(r[2]), "=r"(r[3])
                 : "r"(addr));
}

// FT = 0 -> bf16 inputs, FT = 1 -> fp16 inputs. fp32 accumulate.
template <int FT>
__device__ __forceinline__ void mma16816(float* d, const uint32_t* a,
                                         uint32_t b0, uint32_t b1) {
    if (FT == 0) {
        asm volatile(
            "mma.sync.aligned.m16n8k16.row.col.f32.bf16.bf16.f32 "
            "{%0,%1,%2,%3}, {%4,%5,%6,%7}, {%8,%9}, {%0,%1,%2,%3};"
            : "+f"(d[0]), "+f"(d[1]), "+f"(d[2]), "+f"(d[3])
            : "r"(a[0]), "r"(a[1]), "r"(a[2]), "r"(a[3]), "r"(b0), "r"(b1));
    } else {
        asm volatile(
            "mma.sync.aligned.m16n8k16.row.col.f32.f16.f16.f32 "
            "{%0,%1,%2,%3}, {%4,%5,%6,%7}, {%8,%9}, {%0,%1,%2,%3};"
            : "+f"(d[0]), "+f"(d[1]), "+f"(d[2]), "+f"(d[3])
            : "r"(a[0]), "r"(a[1]), "r"(a[2]), "r"(a[3]), "r"(b0), "r"(b1));
    }
}

// swizzled smem byte offset for (row, 16B-segment) in a 128B-pitch tile
__device__ __forceinline__ uint32_t swz128(int row, int seg) {
    return (uint32_t)(row * 128 + ((seg ^ (row & 7)) << 4));
}

// ---------------------------------------------------------------------------
// HMMA GEMM:  D[128x256 tile] = alpha * sum_p A_p[M,K] @ B_p[N,K]^T
// Operands K-major 16-bit (bf16 or fp16 per FT). fp32 register accumulation.
// Warp tile 64x64 (2x4 warps). BK=64, 3 stages, one __syncthreads per BK step.
// EPI 0: C = alpha*D (fp32). EPI 1: 2-way fp16 split of D.
// ---------------------------------------------------------------------------
struct GemmArgs {
    const void* A[4];
    const void* B[4];
    int K;        // per-pair reduction length (multiple of 64)
    int ldc;
    float alpha;
    float* C;
    __half *Oh, *Om;
};

template <int NPAIRS, int EPI, int FT>
__global__ __launch_bounds__(256, 1)
void gemm_mma(const GemmArgs args)
{
    constexpr int BM = 128, BN = 256, BK = 64, STAGES = 3;
    constexpr int A_B = BM * 128;              // 16KB
    constexpr int B_B = BN * 128;              // 32KB
    constexpr int STAGE_B = A_B + B_B;         // 48KB
    extern __shared__ __align__(128) char smem[];
    const uint32_t sbase = smem_u32(smem);

    const int tid = threadIdx.x;
    const int wid = tid >> 5;
    const int lane = tid & 31;
    const int wm = wid & 1;          // 2 warps along M (64 rows each)
    const int wn = wid >> 1;         // 4 warps along N (64 cols each)
    const int bm = blockIdx.y * BM;
    const int bn = blockIdx.x * BN;
    const int K = args.K;
    const int nchunk = K / BK;
    const int total = NPAIRS * nchunk;

    // per-lane ldmatrix offsets: 4 k16-steps per BK=64 tile
    const int sub = lane >> 3, r8 = lane & 7;
    uint32_t aoff[4][4], boff[4][4];
#pragma unroll
    for (int kk = 0; kk < 4; kk++) {
#pragma unroll
        for (int mi = 0; mi < 4; mi++) {
            int row = wm * 64 + mi * 16 + (sub & 1) * 8 + r8;
            int seg = 2 * kk + (sub >> 1);
            aoff[kk][mi] = swz128(row, seg);
        }
#pragma unroll
        for (int nj = 0; nj < 4; nj++) {
            int row = wn * 64 + nj * 16 + (sub >> 1) * 8 + r8;
            int seg = 2 * kk + (sub & 1);
            boff[kk][nj] = swz128(row, seg);
        }
    }

    // cp.async mapping: 12 chunks/thread (4 A + 8 B); 32 rows x 8 segs per pass
    const int ld_row = tid >> 3;         // 0..31
    const int ld_seg = tid & 7;          // 0..7
    const size_t g_off0 = (size_t)ld_row * K + ld_seg * 8;

    float acc[4][8][4];
#pragma unroll
    for (int mi = 0; mi < 4; mi++)
#pragma unroll
        for (int ni = 0; ni < 8; ni++)
#pragma unroll
            for (int v = 0; v < 4; v++) acc[mi][ni][v] = 0.0f;

    auto issue_tile = [&](int t, int s) {
        const int p = t / nchunk;
        const int c = t - p * nchunk;
        const unsigned short* Ap = (const unsigned short*)args.A[p] + (size_t)bm * K + c * BK;
        const unsigned short* Bp = (const unsigned short*)args.B[p] + (size_t)bn * K + c * BK;
        const uint32_t as = sbase + s * STAGE_B;
        const uint32_t bs = as + A_B;
        const size_t rstep = (size_t)32 * K;
#pragma unroll
        for (int r = 0; r < 4; r++)
            cp_async16(as + swz128(ld_row + r * 32, ld_seg), Ap + g_off0 + r * rstep);
#pragma unroll
        for (int r = 0; r < 8; r++)
            cp_async16(bs + swz128(ld_row + r * 32, ld_seg), Bp + g_off0 + r * rstep);
    };

    // prologue: stages 0 and 1 in flight
    issue_tile(0, 0); CP_COMMIT();
    issue_tile(1, 1); CP_COMMIT();
    CP_WAIT(1);           // tile 0 resident
    __syncthreads();

    for (int i = 0; i < total; i++) {
        // issue tile i+2 into slot (i+2)%3 == (i-1)%3 — freed by the barrier
        // that ended iteration i-1.
        if (i + 2 < total) issue_tile(i + 2, (i + 2) % STAGES);
        CP_COMMIT();

        const int s = i % STAGES;
        const uint32_t as = sbase + s * STAGE_B;
        const uint32_t bs = as + A_B;
#pragma unroll
        for (int kk = 0; kk < 4; kk++) {
            uint32_t br[4][4];
#pragma unroll
            for (int nj = 0; nj < 4; nj++) ldsm4(br[nj], bs + boff[kk][nj]);
#pragma unroll
            for (int mi = 0; mi < 4; mi++) {
                uint32_t ar[4];
                ldsm4(ar, as + aoff[kk][mi]);
#pragma unroll
                for (int ni = 0; ni < 8; ni++) {
                    const int nj = ni >> 1, o = (ni & 1) * 2;
                    mma16816<FT>(acc[mi][ni], ar, br[nj][o], br[nj][o + 1]);
                }
            }
        }
        CP_WAIT(1);        // tile i+1 resident
        __syncthreads();   // everyone done with slot i
    }

    // ---- epilogue from registers ----
    const int ldc = args.ldc;
#pragma unroll
    for (int mi = 0; mi < 4; mi++) {
#pragma unroll
        for (int ni = 0; ni < 8; ni++) {
            const int r0 = bm + wm * 64 + mi * 16 + (lane >> 2);
            const int c0 = bn + wn * 64 + ni * 8 + (lane & 3) * 2;
#pragma unroll
            for (int h = 0; h < 2; h++) {
                const size_t o = (size_t)(r0 + h * 8) * ldc + c0;
                const float v0 = acc[mi][ni][2 * h + 0];
                const float v1 = acc[mi][ni][2 * h + 1];
                if (EPI == 0) {
                    float2 w;
                    w.x = args.alpha * v0;
                    w.y = args.alpha * v1;
                    *(float2*)(args.C + o) = w;
                } else {
                    __half h0 = __float2half_rn(v0);
                    __half h1 = __float2half_rn(v1);
                    __half m0 = __float2half_rn(v0 - __half2float(h0));
                    __half m1 = __float2half_rn(v1 - __half2float(h1));
                    uint32_t ph = (uint32_t)*(unsigned short*)&h0 |
                                  ((uint32_t)*(unsigned short*)&h1 << 16);
                    uint32_t pm = (uint32_t)*(unsigned short*)&m0 |
                                  ((uint32_t)*(unsigned short*)&m1 << 16);
                    *(uint32_t*)((unsigned short*)args.Oh + o) = ph;
                    *(uint32_t*)((unsigned short*)args.Om + o) = pm;
                }
            }
        }
    }
}

// ---------------------------------------------------------------------------
// elementwise 2-way fp16 split
// ---------------------------------------------------------------------------
__global__ __launch_bounds__(256)
void split2h_kernel(const float* __restrict__ in, __half* __restrict__ oh,
                    __half* __restrict__ om)
{
    size_t i = (size_t)blockIdx.x * 256 + threadIdx.x;
    float v = in[i];
    __half h = __float2half_rn(v);
    om[i] = __float2half_rn(v - __half2float(h));
    oh[i] = h;
}

// ---------------------------------------------------------------------------
// transpose + 2-way fp16 split: in[R][C] fp32 -> oh/om [C][R] fp16
// ---------------------------------------------------------------------------
__global__ __launch_bounds__(256)
void transp_split2h(const float* __restrict__ in, __half* oh, __half* om,
                    int R, int C)
{
    __shared__ float t[32][33];
    const int bc = blockIdx.x * 32, br = blockIdx.y * 32;
    const int tx = threadIdx.x & 31, ty = threadIdx.x >> 5;
#pragma unroll
    for (int j = 0; j < 32; j += 8)
        t[ty + j][tx] = in[(size_t)(br + ty + j) * C + bc + tx];
    __syncthreads();
#pragma unroll
    for (int j = 0; j < 32; j += 8) {
        int oc = bc + ty + j;
        float v = t[tx][ty + j];
        __half h = __float2half_rn(v);
        size_t o = (size_t)oc * R + br + tx;
        oh[o] = h;
        om[o] = __float2half_rn(v - __half2float(h));
    }
}

// ---------------------------------------------------------------------------
// transpose + 2-way bf16 split: in[R][C] fp32 -> oh/ol [C][R] bf16
// ---------------------------------------------------------------------------
__global__ __launch_bounds__(256)
void transp_split2b(const float* __restrict__ in, __nv_bfloat16* oh,
                    __nv_bfloat16* ol, int R, int C)
{
    __shared__ float t[32][33];
    const int bc = blockIdx.x * 32, br = blockIdx.y * 32;
    const int tx = threadIdx.x & 31, ty = threadIdx.x >> 5;
#pragma unroll
    for (int j = 0; j < 32; j += 8)
        t[ty + j][tx] = in[(size_t)(br + ty + j) * C + bc + tx];
    __syncthreads();
#pragma unroll
    for (int j = 0; j < 32; j += 8) {
        int oc = bc + ty + j;
        float v = t[tx][ty + j];
        __nv_bfloat16 h = __float2bfloat16(v);
        size_t o = (size_t)oc * R + br + tx;
        oh[o] = h;
        ol[o] = __float2bfloat16(v - __bfloat162float(h));
    }
}

// ---------------------------------------------------------------------------
// softmax over rows of S, emitting 2-way bf16 split of P. Row cached in SMEM.
// ---------------------------------------------------------------------------
__global__ __launch_bounds__(256)
void softmax_split(const float* __restrict__ S, __nv_bfloat16* __restrict__ Ph,
                   __nv_bfloat16* __restrict__ Pl, int n)
{
    __shared__ float row[SEQ];
    __shared__ float red[256];
    const float* s = S + (size_t)blockIdx.x * n;
    const int tid = threadIdx.x;

    float m = -3.4e38f;
    for (int i = tid; i < n; i += 256) {
        float v = s[i];
        row[i] = v;
        m = fmaxf(m, v);
    }
    red[tid] = m;
    __syncthreads();
    for (int st = 128; st > 0; st >>= 1) {
        if (tid < st) red[tid] = fmaxf(red[tid], red[tid + st]);
        __syncthreads();
    }
    m = red[0];
    __syncthreads();

    float sum = 0.0f;
    for (int i = tid; i < n; i += 256) {
        float e = expf(row[i] - m);
        row[i] = e;
        sum += e;
    }
    red[tid] = sum;
    __syncthreads();
    for (int st = 128; st > 0; st >>= 1) {
        if (tid < st) red[tid] += red[tid + st];
        __syncthreads();
    }
    const float inv = 1.0f / red[0];
    __syncthreads();

    __nv_bfloat16* ph = Ph + (size_t)blockIdx.x * n;
    __nv_bfloat16* pl = Pl + (size_t)blockIdx.x * n;
    for (int i = tid; i < n; i += 256) {
        float p = row[i] * inv;
        __nv_bfloat16 h = __float2bfloat16(p);
        ph[i] = h;
        pl[i] = __float2bfloat16(p - __bfloat162float(h));
    }
}

// ---------------------------------------------------------------------------
extern "C" void kernel_launch(void* const* d_in, const int* in_sizes, int n_in,
                              void* d_out, int out_size)
{
    const float* X  = (const float*)d_in[0];
    const float* Wq = (const float*)d_in[1];
    const float* Wk = (const float*)d_in[2];
    float* out = (float*)d_out;

    void* p;
#define SYM(name, var) cudaGetSymbolAddress(&p, name); auto* var = (decltype(&name[0]))p;
    SYM(g_S, S) SYM(g_Ph, Ph) SYM(g_Pl, Pl)
    SYM(g_Qh, Qh) SYM(g_Qm, Qm)
    SYM(g_Kh, Kh) SYM(g_Km, Km)
    SYM(g_Xh, Xh) SYM(g_Xm, Xm)
    SYM(g_Xth, Xth) SYM(g_Xtl, Xtl)
    SYM(g_Wth, Wth) SYM(g_Wtm, Wtm)
#undef SYM

    const int SMEM_GEMM = 3 * 49152;   // 3 stages x 48KB
    cudaFuncSetAttribute(gemm_mma<3, 1, 1>, cudaFuncAttributeMaxDynamicSharedMemorySize, SMEM_GEMM);
    cudaFuncSetAttribute(gemm_mma<3, 0, 1>, cudaFuncAttributeMaxDynamicSharedMemorySize, SMEM_GEMM);
    cudaFuncSetAttribute(gemm_mma<3, 0, 0>, cudaFuncAttributeMaxDynamicSharedMemorySize, SMEM_GEMM);

    // --- prep: splits & transposes ---
    split2h_kernel<<<SEQ * DIM / 256, 256>>>(X, Xh, Xm);
    transp_split2b<<<dim3(DIM / 32, SEQ / 32), 256>>>(X, Xth, Xtl, SEQ, DIM);

    // --- projection Q: 3 fp16 products ---
    transp_split2h<<<dim3(DIM / 32, DIM / 32), 256>>>(Wq, Wth, Wtm, DIM, DIM);
    {
        GemmArgs a{};
        const void* As[3] = {Xh, Xh, Xm};
        const void* Bs[3] = {Wth, Wtm, Wth};
        for (int i = 0; i < 3; i++) { a.A[i] = As[i]; a.B[i] = Bs[i]; }
        a.K = DIM; a.ldc = DIM; a.alpha = 1.0f;
        a.Oh = Qh; a.Om = Qm;
        gemm_mma<3, 1, 1><<<dim3(DIM / 256, SEQ / 128), 256, SMEM_GEMM>>>(a);
    }
    // --- projection K ---
    transp_split2h<<<dim3(DIM / 32, DIM / 32), 256>>>(Wk, Wth, Wtm, DIM, DIM);
    {
        GemmArgs a{};
        const void* As[3] = {Xh, Xh, Xm};
        const void* Bs[3] = {Wth, Wtm, Wth};
        for (int i = 0; i < 3; i++) { a.A[i] = As[i]; a.B[i] = Bs[i]; }
        a.K = DIM; a.ldc = DIM; a.alpha = 1.0f;
        a.Oh = Kh; a.Om = Km;
        gemm_mma<3, 1, 1><<<dim3(DIM / 256, SEQ / 128), 256, SMEM_GEMM>>>(a);
    }
    // --- S = (Q @ K^T) / 32 : 3 fp16 products {hh, hm, mh} ---
    {
        GemmArgs a{};
        const void* As[3] = {Qh, Qh, Qm};
        const void* Bs[3] = {Kh, Km, Kh};
        for (int i = 0; i < 3; i++) { a.A[i] = As[i]; a.B[i] = Bs[i]; }
        a.K = DIM; a.ldc = SEQ; a.alpha = 0.03125f;
        a.C = S;
        gemm_mma<3, 0, 1><<<dim3(SEQ / 256, SEQ / 128), 256, SMEM_GEMM>>>(a);
    }
    // --- softmax + split of P ---
    softmax_split<<<SEQ, 256>>>(S, Ph, Pl, SEQ);
    // --- out = P @ X : 3 bf16 products ---
    {
        GemmArgs a{};
        const void* As[3] = {Ph, Ph, Pl};
        const void* Bs[3] = {Xth, Xtl, Xth};
        for (int i = 0; i < 3; i++) { a.A[i] = As[i]; a.B[i] = Bs[i]; }
        a.K = SEQ; a.ldc = DIM; a.alpha = 1.0f;
        a.C = out;
        gemm_mma<3, 0, 0><<<dim3(DIM / 256, SEQ / 128), 256, SMEM_GEMM>>>(a);
    }
}

// round 7
// speedup vs baseline: 2.9471x; 1.0942x over previous
#include <cuda_runtime.h>
#include <cuda_bf16.h>
#include <cuda_fp16.h>
#include <cstdint>
#include <math.h>

#define SEQ 8192
#define DIM 1024

// ---------------------------------------------------------------------------
// Scratch (device globals — allocation-free)
// ---------------------------------------------------------------------------
__device__ __align__(256) float g_S[(size_t)SEQ * SEQ];           // 256MB logits
__device__ __align__(256) __nv_bfloat16 g_Ph[(size_t)SEQ * SEQ];  // 128MB
__device__ __align__(256) __nv_bfloat16 g_Pl[(size_t)SEQ * SEQ];  // 128MB
__device__ __align__(256) __half g_Qh[SEQ * DIM], g_Qm[SEQ * DIM];
__device__ __align__(256) __half g_Kh[SEQ * DIM], g_Km[SEQ * DIM];
__device__ __align__(256) __half g_Xh[SEQ * DIM], g_Xm[SEQ * DIM];
__device__ __align__(256) __nv_bfloat16 g_Xth[DIM * SEQ], g_Xtl[DIM * SEQ];
__device__ __align__(256) __half g_Wqh[DIM * DIM], g_Wqm[DIM * DIM];
__device__ __align__(256) __half g_Wkh[DIM * DIM], g_Wkm[DIM * DIM];

// ---------------------------------------------------------------------------
// PTX helpers (baseline ISA only — valid on .target sm_103)
// ---------------------------------------------------------------------------
__device__ __forceinline__ uint32_t smem_u32(const void* p) {
    uint32_t a;
    asm("{ .reg .u64 t; cvta.to.shared.u64 t, %1; cvt.u32.u64 %0, t; }"
        : "=r"(a) : "l"(p));
    return a;
}

__device__ __forceinline__ void cp_async16(uint32_t saddr, const void* gaddr) {
    asm volatile("cp.async.cg.shared.global [%0], [%1], 16;"
                 :: "r"(saddr), "l"(gaddr));
}
#define CP_COMMIT() asm volatile("cp.async.commit_group;")
#define CP_WAIT(N)  asm volatile("cp.async.wait_group %0;" :: "n"(N))

__device__ __forceinline__ void ldsm4(uint32_t* r, uint32_t addr) {
    asm volatile("ldmatrix.sync.aligned.m8n8.x4.shared.b16 {%0,%1,%2,%3}, [%4];"
                 : "=r"(r[0]), "=r"(r[1]), "=r"(r[2]), "=r"(r[3])
                 : "r"(addr));
}

// FT = 0 -> bf16 inputs, FT = 1 -> fp16 inputs. fp32 accumulate.
template <int FT>
__device__ __forceinline__ void mma16816(float* d, const uint32_t* a,
                                         uint32_t b0, uint32_t b1) {
    if (FT == 0) {
        asm volatile(
            "mma.sync.aligned.m16n8k16.row.col.f32.bf16.bf16.f32 "
            "{%0,%1,%2,%3}, {%4,%5,%6,%7}, {%8,%9}, {%0,%1,%2,%3};"
            : "+f"(d[0]), "+f"(d[1]), "+f"(d[2]), "+f"(d[3])
            : "r"(a[0]), "r"(a[1]), "r"(a[2]), "r"(a[3]), "r"(b0), "r"(b1));
    } else {
        asm volatile(
            "mma.sync.aligned.m16n8k16.row.col.f32.f16.f16.f32 "
            "{%0,%1,%2,%3}, {%4,%5,%6,%7}, {%8,%9}, {%0,%1,%2,%3};"
            : "+f"(d[0]), "+f"(d[1]), "+f"(d[2]), "+f"(d[3])
            : "r"(a[0]), "r"(a[1]), "r"(a[2]), "r"(a[3]), "r"(b0), "r"(b1));
    }
}

// swizzled smem byte offset for (row, 16B-segment 0..15) in a 256B-pitch tile:
// XOR the low-3 seg bits with row&7 (stays within the 128B half selected by
// seg bit 3) — conflict-free for both the cp.async stores and ldmatrix reads.
__device__ __forceinline__ uint32_t swz256(int row, int seg) {
    return (uint32_t)(row * 256 +
        (((((seg ^ row) & 7)) | (seg & 8)) << 4));
}

// ---------------------------------------------------------------------------
// HMMA GEMM:  D[128x256 tile] = alpha * sum_p A_p[M,K] @ B_p[N,K]^T
// Operands K-major 16-bit (bf16 or fp16 per FT). fp32 register accumulation.
// Warp tile 64x64 (2x4 warps). BK=128, 2 stages, one __syncthreads per tile.
// blockIdx.z selects {B, outputs} set (merged twin-GEMM launches).
// EPI 0: C = alpha*D (fp32). EPI 1: 2-way fp16 split of D.
// ---------------------------------------------------------------------------
struct GemmArgs {
    const void* A[3];
    const void* B[3];
    const void* B2[3];
    int K;        // per-pair reduction length (multiple of 128)
    int ldc;
    float alpha;
    float* C;
    __half *Oh, *Om, *Oh2, *Om2;
};

template <int NPAIRS, int EPI, int FT>
__global__ __launch_bounds__(256, 1)
void gemm_mma(const GemmArgs args)
{
    constexpr int BM = 128, BN = 256, BK = 128, STAGES = 2;
    constexpr int A_B = BM * 256;              // 32KB
    constexpr int B_B = BN * 256;              // 64KB
    constexpr int STAGE_B = A_B + B_B;         // 96KB
    extern __shared__ __align__(128) char smem[];
    const uint32_t sbase = smem_u32(smem);

    const int tid = threadIdx.x;
    const int wid = tid >> 5;
    const int lane = tid & 31;
    const int wm = wid & 1;          // 2 warps along M (64 rows each)
    const int wn = wid >> 1;         // 4 warps along N (64 cols each)
    const int bm = blockIdx.y * BM;
    const int bn = blockIdx.x * BN;
    const int K = args.K;
    const int nchunk = K / BK;
    const int total = NPAIRS * nchunk;
    const int z = blockIdx.z;
    const void* const* Bp_set = z ? args.B2 : args.B;

    // ldmatrix row bases. row&7 == lane&7 for every fragment, so the swizzle
    // XOR operand is the same (r8) — per-kk offsets are computed inline.
    const int sub = lane >> 3, r8 = lane & 7;
    const int ca = sub >> 1;         // A seg low bit
    const int cb = sub & 1;          // B seg low bit
    uint32_t arow[4], brow[4];
#pragma unroll
    for (int mi = 0; mi < 4; mi++)
        arow[mi] = (uint32_t)(wm * 64 + mi * 16 + (sub & 1) * 8 + r8) * 256;
#pragma unroll
    for (int nj = 0; nj < 4; nj++)
        brow[nj] = (uint32_t)(wn * 64 + nj * 16 + (sub >> 1) * 8 + r8) * 256;

    // cp.async mapping: 24 chunks/thread (8 A + 16 B); 16 rows x 16 segs/pass
    const int ld_row = tid >> 4;         // 0..15
    const int ld_seg = tid & 15;         // 0..15
    const size_t g_off0 = (size_t)ld_row * K + ld_seg * 8;

    float acc[4][8][4];
#pragma unroll
    for (int mi = 0; mi < 4; mi++)
#pragma unroll
        for (int ni = 0; ni < 8; ni++)
#pragma unroll
            for (int v = 0; v < 4; v++) acc[mi][ni][v] = 0.0f;

    auto issue_tile = [&](int t, int s) {
        const int p = t / nchunk;
        const int c = t - p * nchunk;
        const unsigned short* Ap = (const unsigned short*)args.A[p] + (size_t)bm * K + c * BK;
        const unsigned short* Bp = (const unsigned short*)Bp_set[p] + (size_t)bn * K + c * BK;
        const uint32_t as = sbase + s * STAGE_B;
        const uint32_t bs = as + A_B;
        const size_t rstep = (size_t)16 * K;
#pragma unroll
        for (int r = 0; r < 8; r++)
            cp_async16(as + swz256(ld_row + r * 16, ld_seg), Ap + g_off0 + r * rstep);
#pragma unroll
        for (int r = 0; r < 16; r++)
            cp_async16(bs + swz256(ld_row + r * 16, ld_seg), Bp + g_off0 + r * rstep);
    };

    // prologue
    issue_tile(0, 0);
    CP_COMMIT();
    CP_WAIT(0);
    __syncthreads();

    for (int i = 0; i < total; i++) {
        // load tile i+1 into the other slot (freed by the barrier that ended
        // iteration i-1) while computing tile i.
        if (i + 1 < total) { issue_tile(i + 1, (i + 1) & 1); CP_COMMIT(); }

        const uint32_t as = sbase + (i & 1) * STAGE_B;
        const uint32_t bs = as + A_B;
#pragma unroll
        for (int kk = 0; kk < 8; kk++) {
            const int sa = 2 * kk + ca;
            const int sb = 2 * kk + cb;
            const uint32_t offa = (uint32_t)(((((sa ^ r8) & 7)) | (sa & 8)) << 4);
            const uint32_t offb = (uint32_t)(((((sb ^ r8) & 7)) | (sb & 8)) << 4);
            uint32_t br[4][4];
#pragma unroll
            for (int nj = 0; nj < 4; nj++) ldsm4(br[nj], bs + brow[nj] + offb);
#pragma unroll
            for (int mi = 0; mi < 4; mi++) {
                uint32_t ar[4];
                ldsm4(ar, as + arow[mi] + offa);
#pragma unroll
                for (int ni = 0; ni < 8; ni++) {
                    const int nj = ni >> 1, o = (ni & 1) * 2;
                    mma16816<FT>(acc[mi][ni], ar, br[nj][o], br[nj][o + 1]);
                }
            }
        }
        CP_WAIT(0);        // tile i+1 resident
        __syncthreads();   // everyone done reading slot i
    }

    // ---- epilogue from registers ----
    const int ldc = args.ldc;
    __half* Ohp = z ? args.Oh2 : args.Oh;
    __half* Omp = z ? args.Om2 : args.Om;
#pragma unroll
    for (int mi = 0; mi < 4; mi++) {
#pragma unroll
        for (int ni = 0; ni < 8; ni++) {
            const int r0 = bm + wm * 64 + mi * 16 + (lane >> 2);
            const int c0 = bn + wn * 64 + ni * 8 + (lane & 3) * 2;
#pragma unroll
            for (int h = 0; h < 2; h++) {
                const size_t o = (size_t)(r0 + h * 8) * ldc + c0;
                const float v0 = acc[mi][ni][2 * h + 0];
                const float v1 = acc[mi][ni][2 * h + 1];
                if (EPI == 0) {
                    float2 w;
                    w.x = args.alpha * v0;
                    w.y = args.alpha * v1;
                    *(float2*)(args.C + o) = w;
                } else {
                    __half h0 = __float2half_rn(v0);
                    __half h1 = __float2half_rn(v1);
                    __half m0 = __float2half_rn(v0 - __half2float(h0));
                    __half m1 = __float2half_rn(v1 - __half2float(h1));
                    uint32_t ph = (uint32_t)*(unsigned short*)&h0 |
                                  ((uint32_t)*(unsigned short*)&h1 << 16);
                    uint32_t pm = (uint32_t)*(unsigned short*)&m0 |
                                  ((uint32_t)*(unsigned short*)&m1 << 16);
                    *(uint32_t*)((unsigned short*)Ohp + o) = ph;
                    *(uint32_t*)((unsigned short*)Omp + o) = pm;
                }
            }
        }
    }
}

// ---------------------------------------------------------------------------
// elementwise 2-way fp16 split
// ---------------------------------------------------------------------------
__global__ __launch_bounds__(256)
void split2h_kernel(const float* __restrict__ in, __half* __restrict__ oh,
                    __half* __restrict__ om)
{
    size_t i = (size_t)blockIdx.x * 256 + threadIdx.x;
    float v = in[i];
    __half h = __float2half_rn(v);
    om[i] = __float2half_rn(v - __half2float(h));
    oh[i] = h;
}

// ---------------------------------------------------------------------------
// transpose + 2-way fp16 split: in[R][C] fp32 -> oh/om [C][R] fp16
// blockIdx.z selects (input, output) pair — merged Wq/Wk transpose.
// ---------------------------------------------------------------------------
__global__ __launch_bounds__(256)
void transp_split2h_dual(const float* __restrict__ in0, __half* oh0, __half* om0,
                         const float* __restrict__ in1, __half* oh1, __half* om1,
                         int R, int C)
{
    const float* in = blockIdx.z ? in1 : in0;
    __half* oh = blockIdx.z ? oh1 : oh0;
    __half* om = blockIdx.z ? om1 : om0;
    __shared__ float t[32][33];
    const int bc = blockIdx.x * 32, br = blockIdx.y * 32;
    const int tx = threadIdx.x & 31, ty = threadIdx.x >> 5;
#pragma unroll
    for (int j = 0; j < 32; j += 8)
        t[ty + j][tx] = in[(size_t)(br + ty + j) * C + bc + tx];
    __syncthreads();
#pragma unroll
    for (int j = 0; j < 32; j += 8) {
        int oc = bc + ty + j;
        float v = t[tx][ty + j];
        __half h = __float2half_rn(v);
        size_t o = (size_t)oc * R + br + tx;
        oh[o] = h;
        om[o] = __float2half_rn(v - __half2float(h));
    }
}

// ---------------------------------------------------------------------------
// transpose + 2-way bf16 split: in[R][C] fp32 -> oh/ol [C][R] bf16
// ---------------------------------------------------------------------------
__global__ __launch_bounds__(256)
void transp_split2b(const float* __restrict__ in, __nv_bfloat16* oh,
                    __nv_bfloat16* ol, int R, int C)
{
    __shared__ float t[32][33];
    const int bc = blockIdx.x * 32, br = blockIdx.y * 32;
    const int tx = threadIdx.x & 31, ty = threadIdx.x >> 5;
#pragma unroll
    for (int j = 0; j < 32; j += 8)
        t[ty + j][tx] = in[(size_t)(br + ty + j) * C + bc + tx];
    __syncthreads();
#pragma unroll
    for (int j = 0; j < 32; j += 8) {
        int oc = bc + ty + j;
        float v = t[tx][ty + j];
        __nv_bfloat16 h = __float2bfloat16(v);
        size_t o = (size_t)oc * R + br + tx;
        oh[o] = h;
        ol[o] = __float2bfloat16(v - __bfloat162float(h));
    }
}

// ---------------------------------------------------------------------------
// softmax over rows of S, emitting 2-way bf16 split of P. Row cached in SMEM.
// ---------------------------------------------------------------------------
__global__ __launch_bounds__(256)
void softmax_split(const float* __restrict__ S, __nv_bfloat16* __restrict__ Ph,
                   __nv_bfloat16* __restrict__ Pl, int n)
{
    __shared__ float row[SEQ];
    __shared__ float red[256];
    const float* s = S + (size_t)blockIdx.x * n;
    const int tid = threadIdx.x;

    float m = -3.4e38f;
    for (int i = tid; i < n; i += 256) {
        float v = s[i];
        row[i] = v;
        m = fmaxf(m, v);
    }
    red[tid] = m;
    __syncthreads();
    for (int st = 128; st > 0; st >>= 1) {
        if (tid < st) red[tid] = fmaxf(red[tid], red[tid + st]);
        __syncthreads();
    }
    m = red[0];
    __syncthreads();

    float sum = 0.0f;
    for (int i = tid; i < n; i += 256) {
        float e = expf(row[i] - m);
        row[i] = e;
        sum += e;
    }
    red[tid] = sum;
    __syncthreads();
    for (int st = 128; st > 0; st >>= 1) {
        if (tid < st) red[tid] += red[tid + st];
        __syncthreads();
    }
    const float inv = 1.0f / red[0];
    __syncthreads();

    __nv_bfloat16* ph = Ph + (size_t)blockIdx.x * n;
    __nv_bfloat16* pl = Pl + (size_t)blockIdx.x * n;
    for (int i = tid; i < n; i += 256) {
        float p = row[i] * inv;
        __nv_bfloat16 h = __float2bfloat16(p);
        ph[i] = h;
        pl[i] = __float2bfloat16(p - __bfloat162float(h));
    }
}

// ---------------------------------------------------------------------------
extern "C" void kernel_launch(void* const* d_in, const int* in_sizes, int n_in,
                              void* d_out, int out_size)
{
    const float* X  = (const float*)d_in[0];
    const float* Wq = (const float*)d_in[1];
    const float* Wk = (const float*)d_in[2];
    float* out = (float*)d_out;

    void* p;
#define SYM(name, var) cudaGetSymbolAddress(&p, name); auto* var = (decltype(&name[0]))p;
    SYM(g_S, S) SYM(g_Ph, Ph) SYM(g_Pl, Pl)
    SYM(g_Qh, Qh) SYM(g_Qm, Qm)
    SYM(g_Kh, Kh) SYM(g_Km, Km)
    SYM(g_Xh, Xh) SYM(g_Xm, Xm)
    SYM(g_Xth, Xth) SYM(g_Xtl, Xtl)
    SYM(g_Wqh, Wqh) SYM(g_Wqm, Wqm)
    SYM(g_Wkh, Wkh) SYM(g_Wkm, Wkm)
#undef SYM

    const int SMEM_GEMM = 2 * 98304;   // 2 stages x 96KB
    cudaFuncSetAttribute(gemm_mma<3, 1, 1>, cudaFuncAttributeMaxDynamicSharedMemorySize, SMEM_GEMM);
    cudaFuncSetAttribute(gemm_mma<3, 0, 1>, cudaFuncAttributeMaxDynamicSharedMemorySize, SMEM_GEMM);
    cudaFuncSetAttribute(gemm_mma<3, 0, 0>, cudaFuncAttributeMaxDynamicSharedMemorySize, SMEM_GEMM);

    // --- prep: splits & transposes ---
    split2h_kernel<<<SEQ * DIM / 256, 256>>>(X, Xh, Xm);
    transp_split2b<<<dim3(DIM / 32, SEQ / 32), 256>>>(X, Xth, Xtl, SEQ, DIM);
    transp_split2h_dual<<<dim3(DIM / 32, DIM / 32, 2), 256>>>(
        Wq, Wqh, Wqm, Wk, Wkh, Wkm, DIM, DIM);

    // --- projections Q and K in one launch (z selects weight set) ---
    {
        GemmArgs a{};
        const void* As[3]  = {Xh, Xh, Xm};
        const void* Bq[3]  = {Wqh, Wqm, Wqh};
        const void* Bk[3]  = {Wkh, Wkm, Wkh};
        for (int i = 0; i < 3; i++) { a.A[i] = As[i]; a.B[i] = Bq[i]; a.B2[i] = Bk[i]; }
        a.K = DIM; a.ldc = DIM; a.alpha = 1.0f;
        a.Oh = Qh; a.Om = Qm; a.Oh2 = Kh; a.Om2 = Km;
        gemm_mma<3, 1, 1><<<dim3(DIM / 256, SEQ / 128, 2), 256, SMEM_GEMM>>>(a);
    }
    // --- S = (Q @ K^T) / 32 : 3 fp16 products {hh, hm, mh} ---
    {
        GemmArgs a{};
        const void* As[3] = {Qh, Qh, Qm};
        const void* Bs[3] = {Kh, Km, Kh};
        for (int i = 0; i < 3; i++) { a.A[i] = As[i]; a.B[i] = Bs[i]; }
        a.K = DIM; a.ldc = SEQ; a.alpha = 0.03125f;
        a.C = S;
        gemm_mma<3, 0, 1><<<dim3(SEQ / 256, SEQ / 128, 1), 256, SMEM_GEMM>>>(a);
    }
    // --- softmax + split of P ---
    softmax_split<<<SEQ, 256>>>(S, Ph, Pl, SEQ);
    // --- out = P @ X : 3 bf16 products ---
    {
        GemmArgs a{};
        const void* As[3] = {Ph, Ph, Pl};
        const void* Bs[3] = {Xth, Xtl, Xth};
        for (int i = 0; i < 3; i++) { a.A[i] = As[i]; a.B[i] = Bs[i]; }
        a.K = SEQ; a.ldc = DIM; a.alpha = 1.0f;
        a.C = out;
        gemm_mma<3, 0, 0><<<dim3(DIM / 256, SEQ / 128, 1), 256, SMEM_GEMM>>>(a);
    }
}

// round 8
// speedup vs baseline: 3.1055x; 1.0537x over previous
#include <cuda_runtime.h>
#include <cuda_bf16.h>
#include <cuda_fp16.h>
#include <cstdint>
#include <math.h>

#define SEQ 8192
#define DIM 1024

// ---------------------------------------------------------------------------
// Scratch (device globals — allocation-free)
// ---------------------------------------------------------------------------
__device__ __align__(256) float g_S[(size_t)SEQ * SEQ];           // 256MB logits
__device__ __align__(256) __nv_bfloat16 g_Ph[(size_t)SEQ * SEQ];  // 128MB
__device__ __align__(256) __nv_bfloat16 g_Pl[(size_t)SEQ * SEQ];  // 128MB
__device__ __align__(256) __half g_Qh[SEQ * DIM], g_Qm[SEQ * DIM];
__device__ __align__(256) __half g_Kh[SEQ * DIM], g_Km[SEQ * DIM];
__device__ __align__(256) __half g_Xh[SEQ * DIM], g_Xm[SEQ * DIM];
__device__ __align__(256) __nv_bfloat16 g_Xth[DIM * SEQ], g_Xtl[DIM * SEQ];
__device__ __align__(256) __half g_Wqh[DIM * DIM], g_Wqm[DIM * DIM];
__device__ __align__(256) __half g_Wkh[DIM * DIM], g_Wkm[DIM * DIM];

// ---------------------------------------------------------------------------
// PTX helpers (baseline ISA only — valid on .target sm_103)
// ---------------------------------------------------------------------------
__device__ __forceinline__ uint32_t smem_u32(const void* p) {
    uint32_t a;
    asm("{ .reg .u64 t; cvta.to.shared.u64 t, %1; cvt.u32.u64 %0, t; }"
        : "=r"(a) : "l"(p));
    return a;
}

__device__ __forceinline__ void cp_async16(uint32_t saddr, const void* gaddr) {
    asm volatile("cp.async.cg.shared.global [%0], [%1], 16;"
                 :: "r"(saddr), "l"(gaddr));
}
#define CP_COMMIT() asm volatile("cp.async.commit_group;")
#define CP_WAIT(N)  asm volatile("cp.async.wait_group %0;" :: "n"(N))

__device__ __forceinline__ void ldsm4(uint32_t* r, uint32_t addr) {
    asm volatile("ldmatrix.sync.aligned.m8n8.x4.shared.b16 {%0,%1,%2,%3}, [%4];"
                 : "=r"(r[0]), "=r"(r[1]), "=r"(r[2]), "=r"(r[3])
                 : "r"(addr));
}

// FT = 0 -> bf16 inputs, FT = 1 -> fp16 inputs. fp32 accumulate.
template <int FT>
__device__ __forceinline__ void mma16816(float* d, const uint32_t* a,
                                         uint32_t b0, uint32_t b1) {
    if (FT == 0) {
        asm volatile(
            "mma.sync.aligned.m16n8k16.row.col.f32.bf16.bf16.f32 "
            "{%0,%1,%2,%3}, {%4,%5,%6,%7}, {%8,%9}, {%0,%1,%2,%3};"
            : "+f"(d[0]), "+f"(d[1]), "+f"(d[2]), "+f"(d[3])
            : "r"(a[0]), "r"(a[1]), "r"(a[2]), "r"(a[3]), "r"(b0), "r"(b1));
    } else {
        asm volatile(
            "mma.sync.aligned.m16n8k16.row.col.f32.f16.f16.f32 "
            "{%0,%1,%2,%3}, {%4,%5,%6,%7}, {%8,%9}, {%0,%1,%2,%3};"
            : "+f"(d[0]), "+f"(d[1]), "+f"(d[2]), "+f"(d[3])
            : "r"(a[0]), "r"(a[1]), "r"(a[2]), "r"(a[3]), "r"(b0), "r"(b1));
    }
}

// swizzled smem byte offset for (row, 16B-segment 0..7) in a 128B-pitch tile
__device__ __forceinline__ uint32_t swz128(int row, int seg) {
    return (uint32_t)(row * 128 + ((seg ^ (row & 7)) << 4));
}

// ---------------------------------------------------------------------------
// HMMA GEMM:  D[128x128 tile] = alpha * sum_p A_p[M,K] @ B_p[N,K]^T
// 128 threads / 4 warps (2x2, warp tile 64x64). BK=64, 3 stages (32KB each),
// 2 CTAs per SM so pipeline stalls of the two CTAs interleave.
// blockIdx.z selects {B, outputs} set (merged twin-GEMM launches).
// EPI 0: C = alpha*D (fp32). EPI 1: 2-way fp16 split of D.
// ---------------------------------------------------------------------------
struct GemmArgs {
    const void* A[3];
    const void* B[3];
    const void* B2[3];
    int K;        // per-pair reduction length (multiple of 64)
    int ldc;
    float alpha;
    float* C;
    __half *Oh, *Om, *Oh2, *Om2;
};

template <int NPAIRS, int EPI, int FT>
__global__ __launch_bounds__(128, 2)
void gemm_mma(const GemmArgs args)
{
    constexpr int BM = 128, BN = 128, BK = 64, STAGES = 3;
    constexpr int A_B = BM * 128;              // 16KB
    constexpr int B_B = BN * 128;              // 16KB
    constexpr int STAGE_B = A_B + B_B;         // 32KB
    extern __shared__ __align__(128) char smem[];
    const uint32_t sbase = smem_u32(smem);

    const int tid = threadIdx.x;
    const int wid = tid >> 5;
    const int lane = tid & 31;
    const int wm = wid & 1;          // 2 warps along M (64 rows each)
    const int wn = wid >> 1;         // 2 warps along N (64 cols each)
    const int bm = blockIdx.y * BM;
    const int bn = blockIdx.x * BN;
    const int K = args.K;
    const int nchunk = K / BK;
    const int total = NPAIRS * nchunk;
    const int z = blockIdx.z;
    const void* const* Bp_set = z ? args.B2 : args.B;

    // per-lane ldmatrix offsets: 4 k16-steps per BK=64 tile
    const int sub = lane >> 3, r8 = lane & 7;
    uint32_t aoff[4][4], boff[4][4];
#pragma unroll
    for (int kk = 0; kk < 4; kk++) {
#pragma unroll
        for (int mi = 0; mi < 4; mi++) {
            int row = wm * 64 + mi * 16 + (sub & 1) * 8 + r8;
            int seg = 2 * kk + (sub >> 1);
            aoff[kk][mi] = swz128(row, seg);
        }
#pragma unroll
        for (int nj = 0; nj < 4; nj++) {
            int row = wn * 64 + nj * 16 + (sub >> 1) * 8 + r8;
            int seg = 2 * kk + (sub & 1);
            boff[kk][nj] = swz128(row, seg);
        }
    }

    // cp.async mapping: 16 chunks/thread (8 A + 8 B); 16 rows x 8 segs/pass
    const int ld_row = tid >> 3;         // 0..15
    const int ld_seg = tid & 7;          // 0..7
    const size_t g_off0 = (size_t)ld_row * K + ld_seg * 8;

    float acc[4][8][4];
#pragma unroll
    for (int mi = 0; mi < 4; mi++)
#pragma unroll
        for (int ni = 0; ni < 8; ni++)
#pragma unroll
            for (int v = 0; v < 4; v++) acc[mi][ni][v] = 0.0f;

    auto issue_tile = [&](int t, int s) {
        const int p = t / nchunk;
        const int c = t - p * nchunk;
        const unsigned short* Ap = (const unsigned short*)args.A[p] + (size_t)bm * K + c * BK;
        const unsigned short* Bp = (const unsigned short*)Bp_set[p] + (size_t)bn * K + c * BK;
        const uint32_t as = sbase + s * STAGE_B;
        const uint32_t bs = as + A_B;
        const size_t rstep = (size_t)16 * K;
#pragma unroll
        for (int r = 0; r < 8; r++)
            cp_async16(as + swz128(ld_row + r * 16, ld_seg), Ap + g_off0 + r * rstep);
#pragma unroll
        for (int r = 0; r < 8; r++)
            cp_async16(bs + swz128(ld_row + r * 16, ld_seg), Bp + g_off0 + r * rstep);
    };

    // prologue: stages 0 and 1 in flight
    issue_tile(0, 0); CP_COMMIT();
    issue_tile(1, 1); CP_COMMIT();
    CP_WAIT(1);           // tile 0 resident
    __syncthreads();

    for (int i = 0; i < total; i++) {
        // issue tile i+2 into slot (i+2)%3 == (i-1)%3 — freed by the barrier
        // that ended iteration i-1.
        if (i + 2 < total) issue_tile(i + 2, (i + 2) % STAGES);
        CP_COMMIT();

        const int s = i % STAGES;
        const uint32_t as = sbase + s * STAGE_B;
        const uint32_t bs = as + A_B;
#pragma unroll
        for (int kk = 0; kk < 4; kk++) {
            uint32_t br[4][4];
#pragma unroll
            for (int nj = 0; nj < 4; nj++) ldsm4(br[nj], bs + boff[kk][nj]);
#pragma unroll
            for (int mi = 0; mi < 4; mi++) {
                uint32_t ar[4];
                ldsm4(ar, as + aoff[kk][mi]);
#pragma unroll
                for (int ni = 0; ni < 8; ni++) {
                    const int nj = ni >> 1, o = (ni & 1) * 2;
                    mma16816<FT>(acc[mi][ni], ar, br[nj][o], br[nj][o + 1]);
                }
            }
        }
        CP_WAIT(1);        // tile i+1 resident
        __syncthreads();   // everyone done reading slot i
    }

    // ---- epilogue from registers ----
    const int ldc = args.ldc;
    __half* Ohp = z ? args.Oh2 : args.Oh;
    __half* Omp = z ? args.Om2 : args.Om;
#pragma unroll
    for (int mi = 0; mi < 4; mi++) {
#pragma unroll
        for (int ni = 0; ni < 8; ni++) {
            const int r0 = bm + wm * 64 + mi * 16 + (lane >> 2);
            const int c0 = bn + wn * 64 + ni * 8 + (lane & 3) * 2;
#pragma unroll
            for (int h = 0; h < 2; h++) {
                const size_t o = (size_t)(r0 + h * 8) * ldc + c0;
                const float v0 = acc[mi][ni][2 * h + 0];
                const float v1 = acc[mi][ni][2 * h + 1];
                if (EPI == 0) {
                    float2 w;
                    w.x = args.alpha * v0;
                    w.y = args.alpha * v1;
                    *(float2*)(args.C + o) = w;
                } else {
                    __half h0 = __float2half_rn(v0);
                    __half h1 = __float2half_rn(v1);
                    __half m0 = __float2half_rn(v0 - __half2float(h0));
                    __half m1 = __float2half_rn(v1 - __half2float(h1));
                    uint32_t ph = (uint32_t)*(unsigned short*)&h0 |
                                  ((uint32_t)*(unsigned short*)&h1 << 16);
                    uint32_t pm = (uint32_t)*(unsigned short*)&m0 |
                                  ((uint32_t)*(unsigned short*)&m1 << 16);
                    *(uint32_t*)((unsigned short*)Ohp + o) = ph;
                    *(uint32_t*)((unsigned short*)Omp + o) = pm;
                }
            }
        }
    }
}

// ---------------------------------------------------------------------------
// elementwise 2-way fp16 split
// ---------------------------------------------------------------------------
__global__ __launch_bounds__(256)
void split2h_kernel(const float* __restrict__ in, __half* __restrict__ oh,
                    __half* __restrict__ om)
{
    size_t i = (size_t)blockIdx.x * 256 + threadIdx.x;
    float v = in[i];
    __half h = __float2half_rn(v);
    om[i] = __float2half_rn(v - __half2float(h));
    oh[i] = h;
}

// ---------------------------------------------------------------------------
// transpose + 2-way fp16 split: in[R][C] fp32 -> oh/om [C][R] fp16
// blockIdx.z selects (input, output) pair — merged Wq/Wk transpose.
// ---------------------------------------------------------------------------
__global__ __launch_bounds__(256)
void transp_split2h_dual(const float* __restrict__ in0, __half* oh0, __half* om0,
                         const float* __restrict__ in1, __half* oh1, __half* om1,
                         int R, int C)
{
    const float* in = blockIdx.z ? in1 : in0;
    __half* oh = blockIdx.z ? oh1 : oh0;
    __half* om = blockIdx.z ? om1 : om0;
    __shared__ float t[32][33];
    const int bc = blockIdx.x * 32, br = blockIdx.y * 32;
    const int tx = threadIdx.x & 31, ty = threadIdx.x >> 5;
#pragma unroll
    for (int j = 0; j < 32; j += 8)
        t[ty + j][tx] = in[(size_t)(br + ty + j) * C + bc + tx];
    __syncthreads();
#pragma unroll
    for (int j = 0; j < 32; j += 8) {
        int oc = bc + ty + j;
        float v = t[tx][ty + j];
        __half h = __float2half_rn(v);
        size_t o = (size_t)oc * R + br + tx;
        oh[o] = h;
        om[o] = __float2half_rn(v - __half2float(h));
    }
}

// ---------------------------------------------------------------------------
// transpose + 2-way bf16 split: in[R][C] fp32 -> oh/ol [C][R] bf16
// ---------------------------------------------------------------------------
__global__ __launch_bounds__(256)
void transp_split2b(const float* __restrict__ in, __nv_bfloat16* oh,
                    __nv_bfloat16* ol, int R, int C)
{
    __shared__ float t[32][33];
    const int bc = blockIdx.x * 32, br = blockIdx.y * 32;
    const int tx = threadIdx.x & 31, ty = threadIdx.x >> 5;
#pragma unroll
    for (int j = 0; j < 32; j += 8)
        t[ty + j][tx] = in[(size_t)(br + ty + j) * C + bc + tx];
    __syncthreads();
#pragma unroll
    for (int j = 0; j < 32; j += 8) {
        int oc = bc + ty + j;
        float v = t[tx][ty + j];
        __nv_bfloat16 h = __float2bfloat16(v);
        size_t o = (size_t)oc * R + br + tx;
        oh[o] = h;
        ol[o] = __float2bfloat16(v - __bfloat162float(h));
    }
}

// ---------------------------------------------------------------------------
// softmax over rows of S, emitting 2-way bf16 split of P. Row cached in SMEM.
// ---------------------------------------------------------------------------
__global__ __launch_bounds__(256)
void softmax_split(const float* __restrict__ S, __nv_bfloat16* __restrict__ Ph,
                   __nv_bfloat16* __restrict__ Pl, int n)
{
    __shared__ float row[SEQ];
    __shared__ float red[256];
    const float* s = S + (size_t)blockIdx.x * n;
    const int tid = threadIdx.x;

    float m = -3.4e38f;
    for (int i = tid; i < n; i += 256) {
        float v = s[i];
        row[i] = v;
        m = fmaxf(m, v);
    }
    red[tid] = m;
    __syncthreads();
    for (int st = 128; st > 0; st >>= 1) {
        if (tid < st) red[tid] = fmaxf(red[tid], red[tid + st]);
        __syncthreads();
    }
    m = red[0];
    __syncthreads();

    float sum = 0.0f;
    for (int i = tid; i < n; i += 256) {
        float e = expf(row[i] - m);
        row[i] = e;
        sum += e;
    }
    red[tid] = sum;
    __syncthreads();
    for (int st = 128; st > 0; st >>= 1) {
        if (tid < st) red[tid] += red[tid + st];
        __syncthreads();
    }
    const float inv = 1.0f / red[0];
    __syncthreads();

    __nv_bfloat16* ph = Ph + (size_t)blockIdx.x * n;
    __nv_bfloat16* pl = Pl + (size_t)blockIdx.x * n;
    for (int i = tid; i < n; i += 256) {
        float p = row[i] * inv;
        __nv_bfloat16 h = __float2bfloat16(p);
        ph[i] = h;
        pl[i] = __float2bfloat16(p - __bfloat162float(h));
    }
}

// ---------------------------------------------------------------------------
extern "C" void kernel_launch(void* const* d_in, const int* in_sizes, int n_in,
                              void* d_out, int out_size)
{
    const float* X  = (const float*)d_in[0];
    const float* Wq = (const float*)d_in[1];
    const float* Wk = (const float*)d_in[2];
    float* out = (float*)d_out;

    void* p;
#define SYM(name, var) cudaGetSymbolAddress(&p, name); auto* var = (decltype(&name[0]))p;
    SYM(g_S, S) SYM(g_Ph, Ph) SYM(g_Pl, Pl)
    SYM(g_Qh, Qh) SYM(g_Qm, Qm)
    SYM(g_Kh, Kh) SYM(g_Km, Km)
    SYM(g_Xh, Xh) SYM(g_Xm, Xm)
    SYM(g_Xth, Xth) SYM(g_Xtl, Xtl)
    SYM(g_Wqh, Wqh) SYM(g_Wqm, Wqm)
    SYM(g_Wkh, Wkh) SYM(g_Wkm, Wkm)
#undef SYM

    const int SMEM_GEMM = 3 * 32768;   // 3 stages x 32KB = 96KB (2 CTAs/SM)
    cudaFuncSetAttribute(gemm_mma<3, 1, 1>, cudaFuncAttributeMaxDynamicSharedMemorySize, SMEM_GEMM);
    cudaFuncSetAttribute(gemm_mma<3, 0, 1>, cudaFuncAttributeMaxDynamicSharedMemorySize, SMEM_GEMM);
    cudaFuncSetAttribute(gemm_mma<3, 0, 0>, cudaFuncAttributeMaxDynamicSharedMemorySize, SMEM_GEMM);

    // --- prep: splits & transposes ---
    split2h_kernel<<<SEQ * DIM / 256, 256>>>(X, Xh, Xm);
    transp_split2b<<<dim3(DIM / 32, SEQ / 32), 256>>>(X, Xth, Xtl, SEQ, DIM);
    transp_split2h_dual<<<dim3(DIM / 32, DIM / 32, 2), 256>>>(
        Wq, Wqh, Wqm, Wk, Wkh, Wkm, DIM, DIM);

    // --- projections Q and K in one launch (z selects weight set) ---
    {
        GemmArgs a{};
        const void* As[3]  = {Xh, Xh, Xm};
        const void* Bq[3]  = {Wqh, Wqm, Wqh};
        const void* Bk[3]  = {Wkh, Wkm, Wkh};
        for (int i = 0; i < 3; i++) { a.A[i] = As[i]; a.B[i] = Bq[i]; a.B2[i] = Bk[i]; }
        a.K = DIM; a.ldc = DIM; a.alpha = 1.0f;
        a.Oh = Qh; a.Om = Qm; a.Oh2 = Kh; a.Om2 = Km;
        gemm_mma<3, 1, 1><<<dim3(DIM / 128, SEQ / 128, 2), 128, SMEM_GEMM>>>(a);
    }
    // --- S = (Q @ K^T) / 32 : 3 fp16 products {hh, hm, mh} ---
    {
        GemmArgs a{};
        const void* As[3] = {Qh, Qh, Qm};
        const void* Bs[3] = {Kh, Km, Kh};
        for (int i = 0; i < 3; i++) { a.A[i] = As[i]; a.B[i] = Bs[i]; }
        a.K = DIM; a.ldc = SEQ; a.alpha = 0.03125f;
        a.C = S;
        gemm_mma<3, 0, 1><<<dim3(SEQ / 128, SEQ / 128, 1), 128, SMEM_GEMM>>>(a);
    }
    // --- softmax + split of P ---
    softmax_split<<<SEQ, 256>>>(S, Ph, Pl, SEQ);
    // --- out = P @ X : 3 bf16 products ---
    {
        GemmArgs a{};
        const void* As[3] = {Ph, Ph, Pl};
        const void* Bs[3] = {Xth, Xtl, Xth};
        for (int i = 0; i < 3; i++) { a.A[i] = As[i]; a.B[i] = Bs[i]; }
        a.K = SEQ; a.ldc = DIM; a.alpha = 1.0f;
        a.C = out;
        gemm_mma<3, 0, 0><<<dim3(DIM / 128, SEQ / 128, 1), 128, SMEM_GEMM>>>(a);
    }
}

// round 9
// speedup vs baseline: 3.6501x; 1.1754x over previous
#include <cuda_runtime.h>
#include <cuda_bf16.h>
#include <cuda_fp16.h>
#include <cstdint>
#include <math.h>

#define SEQ 8192
#define DIM 1024

// ---------------------------------------------------------------------------
// Scratch (device globals — allocation-free)
// ---------------------------------------------------------------------------
__device__ __align__(256) float g_S[(size_t)SEQ * SEQ];     // 256MB logits
__device__ __align__(256) __half g_Ph[(size_t)SEQ * SEQ];   // 128MB
__device__ __align__(256) __half g_Pl[(size_t)SEQ * SEQ];   // 128MB
__device__ __align__(256) __half g_Qh[SEQ * DIM], g_Qm[SEQ * DIM];
__device__ __align__(256) __half g_Kh[SEQ * DIM], g_Km[SEQ * DIM];
__device__ __align__(256) __half g_Xh[SEQ * DIM], g_Xm[SEQ * DIM];
__device__ __align__(256) __half g_Xth[DIM * SEQ];
__device__ __align__(256) __half g_Wqh[DIM * DIM], g_Wqm[DIM * DIM];
__device__ __align__(256) __half g_Wkh[DIM * DIM], g_Wkm[DIM * DIM];

// ---------------------------------------------------------------------------
// PTX helpers (baseline ISA only — valid on .target sm_103)
// ---------------------------------------------------------------------------
__device__ __forceinline__ uint32_t smem_u32(const void* p) {
    uint32_t a;
    asm("{ .reg .u64 t; cvta.to.shared.u64 t, %1; cvt.u32.u64 %0, t; }"
        : "=r"(a) : "l"(p));
    return a;
}

__device__ __forceinline__ void cp_async16(uint32_t saddr, const void* gaddr) {
    asm volatile("cp.async.cg.shared.global [%0], [%1], 16;"
                 :: "r"(saddr), "l"(gaddr));
}
#define CP_COMMIT() asm volatile("cp.async.commit_group;")
#define CP_WAIT(N)  asm volatile("cp.async.wait_group %0;" :: "n"(N))

__device__ __forceinline__ void ldsm4(uint32_t* r, uint32_t addr) {
    asm volatile("ldmatrix.sync.aligned.m8n8.x4.shared.b16 {%0,%1,%2,%3}, [%4];"
                 : "=r"(r[0]), "=r"(r[1]), "=r"(r[2]), "=r"(r[3])
                 : "r"(addr));
}

// fp16 inputs, fp32 accumulate
__device__ __forceinline__ void mma16816(float* d, const uint32_t* a,
                                         uint32_t b0, uint32_t b1) {
    asm volatile(
        "mma.sync.aligned.m16n8k16.row.col.f32.f16.f16.f32 "
        "{%0,%1,%2,%3}, {%4,%5,%6,%7}, {%8,%9}, {%0,%1,%2,%3};"
        : "+f"(d[0]), "+f"(d[1]), "+f"(d[2]), "+f"(d[3])
        : "r"(a[0]), "r"(a[1]), "r"(a[2]), "r"(a[3]), "r"(b0), "r"(b1));
}

// swizzled smem byte offset for (row, 16B-segment 0..7) in a 128B-pitch tile
__device__ __forceinline__ uint32_t swz128(int row, int seg) {
    return (uint32_t)(row * 128 + ((seg ^ (row & 7)) << 4));
}

// ---------------------------------------------------------------------------
// HMMA GEMM:  D[128x128 tile] = alpha * sum_p A_p[M,K] @ B_p[N,K]^T
// 128 threads / 4 warps (2x2, warp tile 64x64). BK=64, 3 stages (32KB each),
// 2 CTAs per SM so pipeline stalls of the two CTAs interleave.
// blockIdx.z selects {B, outputs} set (merged twin-GEMM launches).
// EPI 0: C = alpha*D (fp32). EPI 1: 2-way fp16 split of D.
// ---------------------------------------------------------------------------
struct GemmArgs {
    const void* A[3];
    const void* B[3];
    const void* B2[3];
    int K;        // per-pair reduction length (multiple of 64)
    int ldc;
    float alpha;
    float* C;
    __half *Oh, *Om, *Oh2, *Om2;
};

template <int NPAIRS, int EPI>
__global__ __launch_bounds__(128, 2)
void gemm_mma(const GemmArgs args)
{
    constexpr int BM = 128, BN = 128, BK = 64, STAGES = 3;
    constexpr int A_B = BM * 128;              // 16KB
    constexpr int B_B = BN * 128;              // 16KB
    constexpr int STAGE_B = A_B + B_B;         // 32KB
    extern __shared__ __align__(128) char smem[];
    const uint32_t sbase = smem_u32(smem);

    const int tid = threadIdx.x;
    const int wid = tid >> 5;
    const int lane = tid & 31;
    const int wm = wid & 1;          // 2 warps along M (64 rows each)
    const int wn = wid >> 1;         // 2 warps along N (64 cols each)
    const int bm = blockIdx.y * BM;
    const int bn = blockIdx.x * BN;
    const int K = args.K;
    const int nchunk = K / BK;
    const int total = NPAIRS * nchunk;
    const int z = blockIdx.z;
    const void* const* Bp_set = z ? args.B2 : args.B;

    // per-lane ldmatrix offsets: 4 k16-steps per BK=64 tile
    const int sub = lane >> 3, r8 = lane & 7;
    uint32_t aoff[4][4], boff[4][4];
#pragma unroll
    for (int kk = 0; kk < 4; kk++) {
#pragma unroll
        for (int mi = 0; mi < 4; mi++) {
            int row = wm * 64 + mi * 16 + (sub & 1) * 8 + r8;
            int seg = 2 * kk + (sub >> 1);
            aoff[kk][mi] = swz128(row, seg);
        }
#pragma unroll
        for (int nj = 0; nj < 4; nj++) {
            int row = wn * 64 + nj * 16 + (sub >> 1) * 8 + r8;
            int seg = 2 * kk + (sub & 1);
            boff[kk][nj] = swz128(row, seg);
        }
    }

    // cp.async mapping: 16 chunks/thread (8 A + 8 B); 16 rows x 8 segs/pass
    const int ld_row = tid >> 3;         // 0..15
    const int ld_seg = tid & 7;          // 0..7
    const size_t g_off0 = (size_t)ld_row * K + ld_seg * 8;

    float acc[4][8][4];
#pragma unroll
    for (int mi = 0; mi < 4; mi++)
#pragma unroll
        for (int ni = 0; ni < 8; ni++)
#pragma unroll
            for (int v = 0; v < 4; v++) acc[mi][ni][v] = 0.0f;

    auto issue_tile = [&](int t, int s) {
        const int p = t / nchunk;
        const int c = t - p * nchunk;
        const unsigned short* Ap = (const unsigned short*)args.A[p] + (size_t)bm * K + c * BK;
        const unsigned short* Bp = (const unsigned short*)Bp_set[p] + (size_t)bn * K + c * BK;
        const uint32_t as = sbase + s * STAGE_B;
        const uint32_t bs = as + A_B;
        const size_t rstep = (size_t)16 * K;
#pragma unroll
        for (int r = 0; r < 8; r++)
            cp_async16(as + swz128(ld_row + r * 16, ld_seg), Ap + g_off0 + r * rstep);
#pragma unroll
        for (int r = 0; r < 8; r++)
            cp_async16(bs + swz128(ld_row + r * 16, ld_seg), Bp + g_off0 + r * rstep);
    };

    // prologue: stages 0 and 1 in flight
    issue_tile(0, 0); CP_COMMIT();
    issue_tile(1, 1); CP_COMMIT();
    CP_WAIT(1);           // tile 0 resident
    __syncthreads();

    for (int i = 0; i < total; i++) {
        // issue tile i+2 into slot (i+2)%3 == (i-1)%3 — freed by the barrier
        // that ended iteration i-1.
        if (i + 2 < total) issue_tile(i + 2, (i + 2) % STAGES);
        CP_COMMIT();

        const int s = i % STAGES;
        const uint32_t as = sbase + s * STAGE_B;
        const uint32_t bs = as + A_B;
#pragma unroll
        for (int kk = 0; kk < 4; kk++) {
            uint32_t br[4][4];
#pragma unroll
            for (int nj = 0; nj < 4; nj++) ldsm4(br[nj], bs + boff[kk][nj]);
#pragma unroll
            for (int mi = 0; mi < 4; mi++) {
                uint32_t ar[4];
                ldsm4(ar, as + aoff[kk][mi]);
#pragma unroll
                for (int ni = 0; ni < 8; ni++) {
                    const int nj = ni >> 1, o = (ni & 1) * 2;
                    mma16816(acc[mi][ni], ar, br[nj][o], br[nj][o + 1]);
                }
            }
        }
        CP_WAIT(1);        // tile i+1 resident
        __syncthreads();   // everyone done reading slot i
    }

    // ---- epilogue from registers ----
    const int ldc = args.ldc;
    __half* Ohp = z ? args.Oh2 : args.Oh;
    __half* Omp = z ? args.Om2 : args.Om;
#pragma unroll
    for (int mi = 0; mi < 4; mi++) {
#pragma unroll
        for (int ni = 0; ni < 8; ni++) {
            const int r0 = bm + wm * 64 + mi * 16 + (lane >> 2);
            const int c0 = bn + wn * 64 + ni * 8 + (lane & 3) * 2;
#pragma unroll
            for (int h = 0; h < 2; h++) {
                const size_t o = (size_t)(r0 + h * 8) * ldc + c0;
                const float v0 = acc[mi][ni][2 * h + 0];
                const float v1 = acc[mi][ni][2 * h + 1];
                if (EPI == 0) {
                    float2 w;
                    w.x = args.alpha * v0;
                    w.y = args.alpha * v1;
                    *(float2*)(args.C + o) = w;
                } else {
                    __half h0 = __float2half_rn(v0);
                    __half h1 = __float2half_rn(v1);
                    __half m0 = __float2half_rn(v0 - __half2float(h0));
                    __half m1 = __float2half_rn(v1 - __half2float(h1));
                    uint32_t ph = (uint32_t)*(unsigned short*)&h0 |
                                  ((uint32_t)*(unsigned short*)&h1 << 16);
                    uint32_t pm = (uint32_t)*(unsigned short*)&m0 |
                                  ((uint32_t)*(unsigned short*)&m1 << 16);
                    *(uint32_t*)((unsigned short*)Ohp + o) = ph;
                    *(uint32_t*)((unsigned short*)Omp + o) = pm;
                }
            }
        }
    }
}

// ---------------------------------------------------------------------------
// elementwise 2-way fp16 split
// ---------------------------------------------------------------------------
__global__ __launch_bounds__(256)
void split2h_kernel(const float* __restrict__ in, __half* __restrict__ oh,
                    __half* __restrict__ om)
{
    size_t i = (size_t)blockIdx.x * 256 + threadIdx.x;
    float v = in[i];
    __half h = __float2half_rn(v);
    om[i] = __float2half_rn(v - __half2float(h));
    oh[i] = h;
}

// ---------------------------------------------------------------------------
// transpose + 2-way fp16 split: in[R][C] fp32 -> oh/om [C][R] fp16
// blockIdx.z selects (input, output) pair — merged Wq/Wk transpose.
// ---------------------------------------------------------------------------
__global__ __launch_bounds__(256)
void transp_split2h_dual(const float* __restrict__ in0, __half* oh0, __half* om0,
                         const float* __restrict__ in1, __half* oh1, __half* om1,
                         int R, int C)
{
    const float* in = blockIdx.z ? in1 : in0;
    __half* oh = blockIdx.z ? oh1 : oh0;
    __half* om = blockIdx.z ? om1 : om0;
    __shared__ float t[32][33];
    const int bc = blockIdx.x * 32, br = blockIdx.y * 32;
    const int tx = threadIdx.x & 31, ty = threadIdx.x >> 5;
#pragma unroll
    for (int j = 0; j < 32; j += 8)
        t[ty + j][tx] = in[(size_t)(br + ty + j) * C + bc + tx];
    __syncthreads();
#pragma unroll
    for (int j = 0; j < 32; j += 8) {
        int oc = bc + ty + j;
        float v = t[tx][ty + j];
        __half h = __float2half_rn(v);
        size_t o = (size_t)oc * R + br + tx;
        oh[o] = h;
        om[o] = __float2half_rn(v - __half2float(h));
    }
}

// ---------------------------------------------------------------------------
// transpose to fp16 (high only): in[R][C] fp32 -> oh[C][R] fp16
// ---------------------------------------------------------------------------
__global__ __launch_bounds__(256)
void transp_h(const float* __restrict__ in, __half* oh, int R, int C)
{
    __shared__ float t[32][33];
    const int bc = blockIdx.x * 32, br = blockIdx.y * 32;
    const int tx = threadIdx.x & 31, ty = threadIdx.x >> 5;
#pragma unroll
    for (int j = 0; j < 32; j += 8)
        t[ty + j][tx] = in[(size_t)(br + ty + j) * C + bc + tx];
    __syncthreads();
#pragma unroll
    for (int j = 0; j < 32; j += 8) {
        int oc = bc + ty + j;
        oh[(size_t)oc * R + br + tx] = __float2half_rn(t[tx][ty + j]);
    }
}

// ---------------------------------------------------------------------------
// softmax over rows of S, emitting 2-way fp16 split of P. Row cached in SMEM.
// ---------------------------------------------------------------------------
__global__ __launch_bounds__(256)
void softmax_split(const float* __restrict__ S, __half* __restrict__ Ph,
                   __half* __restrict__ Pl, int n)
{
    __shared__ float row[SEQ];
    __shared__ float red[256];
    const float* s = S + (size_t)blockIdx.x * n;
    const int tid = threadIdx.x;

    float m = -3.4e38f;
    for (int i = tid; i < n; i += 256) {
        float v = s[i];
        row[i] = v;
        m = fmaxf(m, v);
    }
    red[tid] = m;
    __syncthreads();
    for (int st = 128; st > 0; st >>= 1) {
        if (tid < st) red[tid] = fmaxf(red[tid], red[tid + st]);
        __syncthreads();
    }
    m = red[0];
    __syncthreads();

    float sum = 0.0f;
    for (int i = tid; i < n; i += 256) {
        float e = expf(row[i] - m);
        row[i] = e;
        sum += e;
    }
    red[tid] = sum;
    __syncthreads();
    for (int st = 128; st > 0; st >>= 1) {
        if (tid < st) red[tid] += red[tid + st];
        __syncthreads();
    }
    const float inv = 1.0f / red[0];
    __syncthreads();

    __half* ph = Ph + (size_t)blockIdx.x * n;
    __half* pl = Pl + (size_t)blockIdx.x * n;
    for (int i = tid; i < n; i += 256) {
        float p = row[i] * inv;
        __half h = __float2half_rn(p);
        ph[i] = h;
        pl[i] = __float2half_rn(p - __half2float(h));
    }
}

// ---------------------------------------------------------------------------
extern "C" void kernel_launch(void* const* d_in, const int* in_sizes, int n_in,
                              void* d_out, int out_size)
{
    const float* X  = (const float*)d_in[0];
    const float* Wq = (const float*)d_in[1];
    const float* Wk = (const float*)d_in[2];
    float* out = (float*)d_out;

    void* p;
#define SYM(name, var) cudaGetSymbolAddress(&p, name); auto* var = (decltype(&name[0]))p;
    SYM(g_S, S) SYM(g_Ph, Ph) SYM(g_Pl, Pl)
    SYM(g_Qh, Qh) SYM(g_Qm, Qm)
    SYM(g_Kh, Kh) SYM(g_Km, Km)
    SYM(g_Xh, Xh) SYM(g_Xm, Xm)
    SYM(g_Xth, Xth)
    SYM(g_Wqh, Wqh) SYM(g_Wqm, Wqm)
    SYM(g_Wkh, Wkh) SYM(g_Wkm, Wkm)
#undef SYM

    const int SMEM_GEMM = 3 * 32768;   // 3 stages x 32KB = 96KB (2 CTAs/SM)
    cudaFuncSetAttribute(gemm_mma<3, 1>, cudaFuncAttributeMaxDynamicSharedMemorySize, SMEM_GEMM);
    cudaFuncSetAttribute(gemm_mma<3, 0>, cudaFuncAttributeMaxDynamicSharedMemorySize, SMEM_GEMM);
    cudaFuncSetAttribute(gemm_mma<2, 0>, cudaFuncAttributeMaxDynamicSharedMemorySize, SMEM_GEMM);

    // --- prep: splits & transposes ---
    split2h_kernel<<<SEQ * DIM / 256, 256>>>(X, Xh, Xm);
    transp_h<<<dim3(DIM / 32, SEQ / 32), 256>>>(X, Xth, SEQ, DIM);
    transp_split2h_dual<<<dim3(DIM / 32, DIM / 32, 2), 256>>>(
        Wq, Wqh, Wqm, Wk, Wkh, Wkm, DIM, DIM);

    // --- projections Q and K in one launch (z selects weight set) ---
    {
        GemmArgs a{};
        const void* As[3]  = {Xh, Xh, Xm};
        const void* Bq[3]  = {Wqh, Wqm, Wqh};
        const void* Bk[3]  = {Wkh, Wkm, Wkh};
        for (int i = 0; i < 3; i++) { a.A[i] = As[i]; a.B[i] = Bq[i]; a.B2[i] = Bk[i]; }
        a.K = DIM; a.ldc = DIM; a.alpha = 1.0f;
        a.Oh = Qh; a.Om = Qm; a.Oh2 = Kh; a.Om2 = Km;
        gemm_mma<3, 1><<<dim3(DIM / 128, SEQ / 128, 2), 128, SMEM_GEMM>>>(a);
    }
    // --- S = (Q @ K^T) / 32 : 3 fp16 products {hh, hm, mh} ---
    {
        GemmArgs a{};
        const void* As[3] = {Qh, Qh, Qm};
        const void* Bs[3] = {Kh, Km, Kh};
        for (int i = 0; i < 3; i++) { a.A[i] = As[i]; a.B[i] = Bs[i]; }
        a.K = DIM; a.ldc = SEQ; a.alpha = 0.03125f;
        a.C = S;
        gemm_mma<3, 0><<<dim3(SEQ / 128, SEQ / 128, 1), 128, SMEM_GEMM>>>(a);
    }
    // --- softmax + fp16 split of P ---
    softmax_split<<<SEQ, 256>>>(S, Ph, Pl, SEQ);
    // --- out = P @ Xh : 2 fp16 products {Ph·Xth, Pl·Xth} = P·Xth exactly ---
    {
        GemmArgs a{};
        const void* As[2] = {Ph, Pl};
        const void* Bs[2] = {Xth, Xth};
        for (int i = 0; i < 2; i++) { a.A[i] = As[i]; a.B[i] = Bs[i]; }
        a.K = SEQ; a.ldc = DIM; a.alpha = 1.0f;
        a.C = out;
        gemm_mma<2, 0><<<dim3(DIM / 128, SEQ / 128, 1), 128, SMEM_GEMM>>>(a);
    }
}

// round 10
// speedup vs baseline: 3.7280x; 1.0213x over previous
#include <cuda_runtime.h>
#include <cuda_bf16.h>
#include <cuda_fp16.h>
#include <cstdint>
#include <math.h>

#define SEQ 8192
#define DIM 1024

// ---------------------------------------------------------------------------
// Scratch (device globals — allocation-free)
// ---------------------------------------------------------------------------
__device__ __align__(256) float g_S[(size_t)SEQ * SEQ];     // 256MB logits
__device__ __align__(256) __half g_Ph[(size_t)SEQ * SEQ];   // 128MB
__device__ __align__(256) __half g_Pl[(size_t)SEQ * SEQ];   // 128MB
__device__ __align__(256) __half g_Qh[SEQ * DIM], g_Qm[SEQ * DIM];
__device__ __align__(256) __half g_Kh[SEQ * DIM], g_Km[SEQ * DIM];
__device__ __align__(256) __half g_Xh[SEQ * DIM], g_Xm[SEQ * DIM];
__device__ __align__(256) __half g_Xth[DIM * SEQ];
__device__ __align__(256) __half g_Wqh[DIM * DIM], g_Wqm[DIM * DIM];
__device__ __align__(256) __half g_Wkh[DIM * DIM], g_Wkm[DIM * DIM];

// ---------------------------------------------------------------------------
// PTX helpers (baseline ISA only — valid on .target sm_103)
// ---------------------------------------------------------------------------
__device__ __forceinline__ uint32_t smem_u32(const void* p) {
    uint32_t a;
    asm("{ .reg .u64 t; cvta.to.shared.u64 t, %1; cvt.u32.u64 %0, t; }"
        : "=r"(a) : "l"(p));
    return a;
}

__device__ __forceinline__ void cp_async16(uint32_t saddr, const void* gaddr) {
    asm volatile("cp.async.cg.shared.global [%0], [%1], 16;"
                 :: "r"(saddr), "l"(gaddr));
}
#define CP_COMMIT() asm volatile("cp.async.commit_group;")
#define CP_WAIT(N)  asm volatile("cp.async.wait_group %0;" :: "n"(N))

__device__ __forceinline__ void ldsm4(uint32_t* r, uint32_t addr) {
    asm volatile("ldmatrix.sync.aligned.m8n8.x4.shared.b16 {%0,%1,%2,%3}, [%4];"
                 : "=r"(r[0]), "=r"(r[1]), "=r"(r[2]), "=r"(r[3])
                 : "r"(addr));
}

// fp16 inputs, fp32 accumulate
__device__ __forceinline__ void mma16816(float* d, const uint32_t* a,
                                         uint32_t b0, uint32_t b1) {
    asm volatile(
        "mma.sync.aligned.m16n8k16.row.col.f32.f16.f16.f32 "
        "{%0,%1,%2,%3}, {%4,%5,%6,%7}, {%8,%9}, {%0,%1,%2,%3};"
        : "+f"(d[0]), "+f"(d[1]), "+f"(d[2]), "+f"(d[3])
        : "r"(a[0]), "r"(a[1]), "r"(a[2]), "r"(a[3]), "r"(b0), "r"(b1));
}

// swizzled smem byte offset for (row, 16B-segment 0..7) in a 128B-pitch tile
__device__ __forceinline__ uint32_t swz128(int row, int seg) {
    return (uint32_t)(row * 128 + ((seg ^ (row & 7)) << 4));
}

// ---------------------------------------------------------------------------
// Multi-plane HMMA GEMM, all products accumulated into ONE output:
//   MODE 0:  D = alpha * (A0@B0^T + A0@B1^T + A1@B0^T)    (3-product split)
//   MODE 1:  D = alpha * (A0@B0^T + A1@B0^T)              (exact pair sum)
// CTA: 256 threads (2x4 warps, warp tile 64x64), tile 128x256, BK=64.
// Per K-chunk, every plane is loaded ONCE and ldmatrix fragments are shared
// across products -> 3x more MMAs per barrier, 33% less smem-load traffic.
// blockIdx.z selects {B-plane set, outputs} (merged twin-GEMM launches).
// EPI 0: C = alpha*D (fp32). EPI 1: 2-way fp16 split of D.
// ---------------------------------------------------------------------------
struct GemmArgs {
    const void* A[2];
    const void* B[2];
    const void* B2[2];
    int K;        // reduction length (multiple of 64)
    int ldc;
    float alpha;
    float* C;
    __half *Oh, *Om, *Oh2, *Om2;
};

template <int MODE, int EPI>
__global__ __launch_bounds__(256, 1)
void gemm_mma(const GemmArgs args)
{
    constexpr int BM = 128, BN = 256, BK = 64;
    constexpr int NB = (MODE == 0) ? 2 : 1;
    constexpr int STAGES = (MODE == 0) ? 2 : 3;
    constexpr int A_PL = BM * 128;                 // 16KB per A plane
    constexpr int B_PL = BN * 128;                 // 32KB per B plane
    constexpr int STAGE_B = 2 * A_PL + NB * B_PL;  // 96KB / 64KB
    extern __shared__ __align__(128) char smem[];
    const uint32_t sbase = smem_u32(smem);

    const int tid = threadIdx.x;
    const int wid = tid >> 5;
    const int lane = tid & 31;
    const int wm = wid & 1;          // 2 warps along M (64 rows each)
    const int wn = wid >> 1;         // 4 warps along N (64 cols each)
    const int bm = blockIdx.y * BM;
    const int bn = blockIdx.x * BN;
    const int K = args.K;
    const int nchunk = K / BK;
    const int z = blockIdx.z;
    const void* const* Bset = z ? args.B2 : args.B;

    // per-lane ldmatrix offsets: 4 k16-steps per BK=64 chunk
    const int sub = lane >> 3, r8 = lane & 7;
    uint32_t aoff[4][4], boff[4][4];
#pragma unroll
    for (int kk = 0; kk < 4; kk++) {
#pragma unroll
        for (int mi = 0; mi < 4; mi++) {
            int row = wm * 64 + mi * 16 + (sub & 1) * 8 + r8;
            int seg = 2 * kk + (sub >> 1);
            aoff[kk][mi] = swz128(row, seg);
        }
#pragma unroll
        for (int nj = 0; nj < 4; nj++) {
            int row = wn * 64 + nj * 16 + (sub >> 1) * 8 + r8;
            int seg = 2 * kk + (sub & 1);
            boff[kk][nj] = swz128(row, seg);
        }
    }

    // cp.async mapping: 32 rows x 8 segs per pass (256 threads)
    const int ld_row = tid >> 3;         // 0..31
    const int ld_seg = tid & 7;          // 0..7
    const size_t g_off0 = (size_t)ld_row * K + ld_seg * 8;

    float acc[4][8][4];
#pragma unroll
    for (int mi = 0; mi < 4; mi++)
#pragma unroll
        for (int ni = 0; ni < 8; ni++)
#pragma unroll
            for (int v = 0; v < 4; v++) acc[mi][ni][v] = 0.0f;

    auto issue_tile = [&](int c, int s) {
        const uint32_t sb = sbase + s * STAGE_B;
        const size_t rstep = (size_t)32 * K;
#pragma unroll
        for (int pl = 0; pl < 2; pl++) {
            const unsigned short* Ap =
                (const unsigned short*)args.A[pl] + (size_t)bm * K + c * BK;
            const uint32_t abase = sb + pl * A_PL;
#pragma unroll
            for (int r = 0; r < 4; r++)
                cp_async16(abase + swz128(ld_row + r * 32, ld_seg),
                           Ap + g_off0 + r * rstep);
        }
#pragma unroll
        for (int pl = 0; pl < NB; pl++) {
            const unsigned short* Bp =
                (const unsigned short*)Bset[pl] + (size_t)bn * K + c * BK;
            const uint32_t bbase = sb + 2 * A_PL + pl * B_PL;
#pragma unroll
            for (int r = 0; r < 8; r++)
                cp_async16(bbase + swz128(ld_row + r * 32, ld_seg),
                           Bp + g_off0 + r * rstep);
        }
    };

    // prologue: stages 0..STAGES-2 in flight
#pragma unroll
    for (int j = 0; j < STAGES - 1; j++) {
        issue_tile(j, j);
        CP_COMMIT();
    }
    CP_WAIT(STAGES - 2);
    __syncthreads();

    for (int i = 0; i < nchunk; i++) {
        // fill slot (i+STAGES-1)%STAGES — freed by the barrier ending iter i-1
        if (i + STAGES - 1 < nchunk) {
            issue_tile(i + STAGES - 1, (i + STAGES - 1) % STAGES);
            CP_COMMIT();
        }

        const uint32_t sb = sbase + (i % STAGES) * STAGE_B;
        const uint32_t a0 = sb, a1 = sb + A_PL;
        const uint32_t b0 = sb + 2 * A_PL, b1 = b0 + B_PL;
#pragma unroll
        for (int kk = 0; kk < 4; kk++) {
            uint32_t bh[4][4];
#pragma unroll
            for (int nj = 0; nj < 4; nj++) ldsm4(bh[nj], b0 + boff[kk][nj]);
            uint32_t bm_[4][4];
            if (MODE == 0) {
#pragma unroll
                for (int nj = 0; nj < 4; nj++) ldsm4(bm_[nj], b1 + boff[kk][nj]);
            }
#pragma unroll
            for (int mi = 0; mi < 4; mi++) {
                uint32_t ah[4], am[4];
                ldsm4(ah, a0 + aoff[kk][mi]);
                ldsm4(am, a1 + aoff[kk][mi]);
                // product A0 x B0
#pragma unroll
                for (int ni = 0; ni < 8; ni++) {
                    const int nj = ni >> 1, o = (ni & 1) * 2;
                    mma16816(acc[mi][ni], ah, bh[nj][o], bh[nj][o + 1]);
                }
                if (MODE == 0) {
                    // product A0 x B1
#pragma unroll
                    for (int ni = 0; ni < 8; ni++) {
                        const int nj = ni >> 1, o = (ni & 1) * 2;
                        mma16816(acc[mi][ni], ah, bm_[nj][o], bm_[nj][o + 1]);
                    }
                }
                // product A1 x B0
#pragma unroll
                for (int ni = 0; ni < 8; ni++) {
                    const int nj = ni >> 1, o = (ni & 1) * 2;
                    mma16816(acc[mi][ni], am, bh[nj][o], bh[nj][o + 1]);
                }
            }
        }
        CP_WAIT(STAGES - 2);   // next tile resident
        __syncthreads();       // everyone done reading this slot
    }

    // ---- epilogue from registers ----
    const int ldc = args.ldc;
    __half* Ohp = z ? args.Oh2 : args.Oh;
    __half* Omp = z ? args.Om2 : args.Om;
#pragma unroll
    for (int mi = 0; mi < 4; mi++) {
#pragma unroll
        for (int ni = 0; ni < 8; ni++) {
            const int r0 = bm + wm * 64 + mi * 16 + (lane >> 2);
            const int c0 = bn + wn * 64 + ni * 8 + (lane & 3) * 2;
#pragma unroll
            for (int h = 0; h < 2; h++) {
                const size_t o = (size_t)(r0 + h * 8) * ldc + c0;
                const float v0 = acc[mi][ni][2 * h + 0];
                const float v1 = acc[mi][ni][2 * h + 1];
                if (EPI == 0) {
                    float2 w;
                    w.x = args.alpha * v0;
                    w.y = args.alpha * v1;
                    *(float2*)(args.C + o) = w;
                } else {
                    __half h0 = __float2half_rn(v0);
                    __half h1 = __float2half_rn(v1);
                    __half m0 = __float2half_rn(v0 - __half2float(h0));
                    __half m1 = __float2half_rn(v1 - __half2float(h1));
                    uint32_t ph = (uint32_t)*(unsigned short*)&h0 |
                                  ((uint32_t)*(unsigned short*)&h1 << 16);
                    uint32_t pm = (uint32_t)*(unsigned short*)&m0 |
                                  ((uint32_t)*(unsigned short*)&m1 << 16);
                    *(uint32_t*)((unsigned short*)Ohp + o) = ph;
                    *(uint32_t*)((unsigned short*)Omp + o) = pm;
                }
            }
        }
    }
}

// ---------------------------------------------------------------------------
// elementwise 2-way fp16 split
// ---------------------------------------------------------------------------
__global__ __launch_bounds__(256)
void split2h_kernel(const float* __restrict__ in, __half* __restrict__ oh,
                    __half* __restrict__ om)
{
    size_t i = (size_t)blockIdx.x * 256 + threadIdx.x;
    float v = in[i];
    __half h = __float2half_rn(v);
    om[i] = __float2half_rn(v - __half2float(h));
    oh[i] = h;
}

// ---------------------------------------------------------------------------
// transpose + 2-way fp16 split: in[R][C] fp32 -> oh/om [C][R] fp16
// blockIdx.z selects (input, output) pair — merged Wq/Wk transpose.
// ---------------------------------------------------------------------------
__global__ __launch_bounds__(256)
void transp_split2h_dual(const float* __restrict__ in0, __half* oh0, __half* om0,
                         const float* __restrict__ in1, __half* oh1, __half* om1,
                         int R, int C)
{
    const float* in = blockIdx.z ? in1 : in0;
    __half* oh = blockIdx.z ? oh1 : oh0;
    __half* om = blockIdx.z ? om1 : om0;
    __shared__ float t[32][33];
    const int bc = blockIdx.x * 32, br = blockIdx.y * 32;
    const int tx = threadIdx.x & 31, ty = threadIdx.x >> 5;
#pragma unroll
    for (int j = 0; j < 32; j += 8)
        t[ty + j][tx] = in[(size_t)(br + ty + j) * C + bc + tx];
    __syncthreads();
#pragma unroll
    for (int j = 0; j < 32; j += 8) {
        int oc = bc + ty + j;
        float v = t[tx][ty + j];
        __half h = __float2half_rn(v);
        size_t o = (size_t)oc * R + br + tx;
        oh[o] = h;
        om[o] = __float2half_rn(v - __half2float(h));
    }
}

// ---------------------------------------------------------------------------
// transpose to fp16 (high only): in[R][C] fp32 -> oh[C][R] fp16
// ---------------------------------------------------------------------------
__global__ __launch_bounds__(256)
void transp_h(const float* __restrict__ in, __half* oh, int R, int C)
{
    __shared__ float t[32][33];
    const int bc = blockIdx.x * 32, br = blockIdx.y * 32;
    const int tx = threadIdx.x & 31, ty = threadIdx.x >> 5;
#pragma unroll
    for (int j = 0; j < 32; j += 8)
        t[ty + j][tx] = in[(size_t)(br + ty + j) * C + bc + tx];
    __syncthreads();
#pragma unroll
    for (int j = 0; j < 32; j += 8) {
        int oc = bc + ty + j;
        oh[(size_t)oc * R + br + tx] = __float2half_rn(t[tx][ty + j]);
    }
}

// ---------------------------------------------------------------------------
// softmax over rows of S, emitting 2-way fp16 split of P. Row cached in SMEM.
// ---------------------------------------------------------------------------
__global__ __launch_bounds__(256)
void softmax_split(const float* __restrict__ S, __half* __restrict__ Ph,
                   __half* __restrict__ Pl, int n)
{
    __shared__ float row[SEQ];
    __shared__ float red[256];
    const float* s = S + (size_t)blockIdx.x * n;
    const int tid = threadIdx.x;

    float m = -3.4e38f;
    for (int i = tid; i < n; i += 256) {
        float v = s[i];
        row[i] = v;
        m = fmaxf(m, v);
    }
    red[tid] = m;
    __syncthreads();
    for (int st = 128; st > 0; st >>= 1) {
        if (tid < st) red[tid] = fmaxf(red[tid], red[tid + st]);
        __syncthreads();
    }
    m = red[0];
    __syncthreads();

    float sum = 0.0f;
    for (int i = tid; i < n; i += 256) {
        float e = expf(row[i] - m);
        row[i] = e;
        sum += e;
    }
    red[tid] = sum;
    __syncthreads();
    for (int st = 128; st > 0; st >>= 1) {
        if (tid < st) red[tid] += red[tid + st];
        __syncthreads();
    }
    const float inv = 1.0f / red[0];
    __syncthreads();

    __half* ph = Ph + (size_t)blockIdx.x * n;
    __half* pl = Pl + (size_t)blockIdx.x * n;
    for (int i = tid; i < n; i += 256) {
        float p = row[i] * inv;
        __half h = __float2half_rn(p);
        ph[i] = h;
        pl[i] = __float2half_rn(p - __half2float(h));
    }
}

// ---------------------------------------------------------------------------
extern "C" void kernel_launch(void* const* d_in, const int* in_sizes, int n_in,
                              void* d_out, int out_size)
{
    const float* X  = (const float*)d_in[0];
    const float* Wq = (const float*)d_in[1];
    const float* Wk = (const float*)d_in[2];
    float* out = (float*)d_out;

    void* p;
#define SYM(name, var) cudaGetSymbolAddress(&p, name); auto* var = (decltype(&name[0]))p;
    SYM(g_S, S) SYM(g_Ph, Ph) SYM(g_Pl, Pl)
    SYM(g_Qh, Qh) SYM(g_Qm, Qm)
    SYM(g_Kh, Kh) SYM(g_Km, Km)
    SYM(g_Xh, Xh) SYM(g_Xm, Xm)
    SYM(g_Xth, Xth)
    SYM(g_Wqh, Wqh) SYM(g_Wqm, Wqm)
    SYM(g_Wkh, Wkh) SYM(g_Wkm, Wkm)
#undef SYM

    const int SMEM_M0 = 2 * (2 * 16384 + 2 * 32768);   // 196608
    const int SMEM_M1 = 3 * (2 * 16384 + 1 * 32768);   // 196608
    cudaFuncSetAttribute(gemm_mma<0, 1>, cudaFuncAttributeMaxDynamicSharedMemorySize, SMEM_M0);
    cudaFuncSetAttribute(gemm_mma<0, 0>, cudaFuncAttributeMaxDynamicSharedMemorySize, SMEM_M0);
    cudaFuncSetAttribute(gemm_mma<1, 0>, cudaFuncAttributeMaxDynamicSharedMemorySize, SMEM_M1);

    // --- prep: splits & transposes ---
    split2h_kernel<<<SEQ * DIM / 256, 256>>>(X, Xh, Xm);
    transp_h<<<dim3(DIM / 32, SEQ / 32), 256>>>(X, Xth, SEQ, DIM);
    transp_split2h_dual<<<dim3(DIM / 32, DIM / 32, 2), 256>>>(
        Wq, Wqh, Wqm, Wk, Wkh, Wkm, DIM, DIM);

    // --- projections Q and K in one launch (z selects weight set) ---
    {
        GemmArgs a{};
        a.A[0] = Xh;  a.A[1] = Xm;
        a.B[0] = Wqh; a.B[1] = Wqm;
        a.B2[0] = Wkh; a.B2[1] = Wkm;
        a.K = DIM; a.ldc = DIM; a.alpha = 1.0f;
        a.Oh = Qh; a.Om = Qm; a.Oh2 = Kh; a.Om2 = Km;
        gemm_mma<0, 1><<<dim3(DIM / 256, SEQ / 128, 2), 256, SMEM_M0>>>(a);
    }
    // --- S = (Q @ K^T) / 32 : products {hh, hm, mh} ---
    {
        GemmArgs a{};
        a.A[0] = Qh; a.A[1] = Qm;
        a.B[0] = Kh; a.B[1] = Km;
        a.K = DIM; a.ldc = SEQ; a.alpha = 0.03125f;
        a.C = S;
        gemm_mma<0, 0><<<dim3(SEQ / 256, SEQ / 128, 1), 256, SMEM_M0>>>(a);
    }
    // --- softmax + fp16 split of P ---
    softmax_split<<<SEQ, 256>>>(S, Ph, Pl, SEQ);
    // --- out = P @ Xh : products {Ph·Xth, Pl·Xth} = P·Xth exactly ---
    {
        GemmArgs a{};
        a.A[0] = Ph; a.A[1] = Pl;
        a.B[0] = Xth;
        a.K = SEQ; a.ldc = DIM; a.alpha = 1.0f;
        a.C = out;
        gemm_mma<1, 0><<<dim3(DIM / 256, SEQ / 128, 1), 256, SMEM_M1>>>(a);
    }
}

// round 11
// speedup vs baseline: 3.9796x; 1.0675x over previous
#include <cuda_runtime.h>
#include <cuda_bf16.h>
#include <cuda_fp16.h>
#include <cstdint>
#include <math.h>

#define SEQ 8192
#define DIM 1024

// ---------------------------------------------------------------------------
// Scratch (device globals — allocation-free)
// ---------------------------------------------------------------------------
__device__ __align__(256) float g_S[(size_t)SEQ * SEQ];     // 256MB logits
__device__ __align__(256) __half g_Ph[(size_t)SEQ * SEQ];   // 128MB
__device__ __align__(256) __half g_Pl[(size_t)SEQ * SEQ];   // 128MB
__device__ __align__(256) __half g_Qh[SEQ * DIM], g_Qm[SEQ * DIM];
__device__ __align__(256) __half g_Kh[SEQ * DIM], g_Km[SEQ * DIM];
__device__ __align__(256) __half g_Xh[SEQ * DIM], g_Xm[SEQ * DIM];
__device__ __align__(256) __half g_Xth[DIM * SEQ];
__device__ __align__(256) __half g_Wqh[DIM * DIM], g_Wqm[DIM * DIM];
__device__ __align__(256) __half g_Wkh[DIM * DIM], g_Wkm[DIM * DIM];

// ---------------------------------------------------------------------------
// PTX helpers (baseline ISA only — valid on .target sm_103)
// ---------------------------------------------------------------------------
__device__ __forceinline__ uint32_t smem_u32(const void* p) {
    uint32_t a;
    asm("{ .reg .u64 t; cvta.to.shared.u64 t, %1; cvt.u32.u64 %0, t; }"
        : "=r"(a) : "l"(p));
    return a;
}

__device__ __forceinline__ void cp_async16(uint32_t saddr, const void* gaddr) {
    asm volatile("cp.async.cg.shared.global [%0], [%1], 16;"
                 :: "r"(saddr), "l"(gaddr));
}
#define CP_COMMIT() asm volatile("cp.async.commit_group;")
#define CP_WAIT(N)  asm volatile("cp.async.wait_group %0;" :: "n"(N))

__device__ __forceinline__ void ldsm4(uint32_t* r, uint32_t addr) {
    asm volatile("ldmatrix.sync.aligned.m8n8.x4.shared.b16 {%0,%1,%2,%3}, [%4];"
                 : "=r"(r[0]), "=r"(r[1]), "=r"(r[2]), "=r"(r[3])
                 : "r"(addr));
}

// fp16 inputs, fp32 accumulate
__device__ __forceinline__ void mma16816(float* d, const uint32_t* a,
                                         uint32_t b0, uint32_t b1) {
    asm volatile(
        "mma.sync.aligned.m16n8k16.row.col.f32.f16.f16.f32 "
        "{%0,%1,%2,%3}, {%4,%5,%6,%7}, {%8,%9}, {%0,%1,%2,%3};"
        : "+f"(d[0]), "+f"(d[1]), "+f"(d[2]), "+f"(d[3])
        : "r"(a[0]), "r"(a[1]), "r"(a[2]), "r"(a[3]), "r"(b0), "r"(b1));
}

// swizzled smem byte offset for (row, 16B-segment 0..3) in a 64B-pitch tile
__device__ __forceinline__ uint32_t swz64(int row, int seg) {
    return (uint32_t)(row * 64 + ((seg ^ ((row >> 1) & 3)) << 4));
}

// ---------------------------------------------------------------------------
// Multi-plane HMMA GEMM, all products accumulated into ONE output:
//   MODE 0:  D = alpha * (A0@B0^T + A0@B1^T + A1@B0^T)    (3-product split)
//   MODE 1:  D = alpha * (A0@B0^T + A1@B0^T)              (exact pair sum)
// CTA: 128 threads (2x2 warps, warp tile 64x64), tile 128x128, BK=32.
// Stage = all planes of one K-chunk (32KB / 24KB); 3 / 4 stages = 96KB
// -> 2 CTAs per SM, so the two CTAs' pipeline stalls interleave, AND
// fragments are shared across products (192 MMAs per 32 ldsm per barrier).
// blockIdx.z selects {B-plane set, outputs} (merged twin-GEMM launches).
// EPI 0: C = alpha*D (fp32). EPI 1: 2-way fp16 split of D.
// ---------------------------------------------------------------------------
struct GemmArgs {
    const void* A[2];
    const void* B[2];
    const void* B2[2];
    int K;        // reduction length (multiple of 32)
    int ldc;
    float alpha;
    float* C;
    __half *Oh, *Om, *Oh2, *Om2;
};

template <int MODE, int EPI>
__global__ __launch_bounds__(128, 2)
void gemm_mma(const GemmArgs args)
{
    constexpr int BM = 128, BN = 128, BK = 32;
    constexpr int NB = (MODE == 0) ? 2 : 1;
    constexpr int STAGES = (MODE == 0) ? 3 : 4;
    constexpr int A_PL = BM * 64;                  // 8KB per A plane
    constexpr int B_PL = BN * 64;                  // 8KB per B plane
    constexpr int STAGE_B = 2 * A_PL + NB * B_PL;  // 32KB / 24KB
    extern __shared__ __align__(128) char smem[];
    const uint32_t sbase = smem_u32(smem);

    const int tid = threadIdx.x;
    const int wid = tid >> 5;
    const int lane = tid & 31;
    const int wm = wid & 1;          // 2 warps along M (64 rows each)
    const int wn = wid >> 1;         // 2 warps along N (64 cols each)
    const int bm = blockIdx.y * BM;
    const int bn = blockIdx.x * BN;
    const int K = args.K;
    const int nchunk = K / BK;
    const int z = blockIdx.z;
    const void* const* Bset = z ? args.B2 : args.B;

    // per-lane ldmatrix offsets: 2 k16-steps per BK=32 chunk
    const int sub = lane >> 3, r8 = lane & 7;
    uint32_t aoff[2][4], boff[2][4];
#pragma unroll
    for (int kk = 0; kk < 2; kk++) {
#pragma unroll
        for (int mi = 0; mi < 4; mi++) {
            int row = wm * 64 + mi * 16 + (sub & 1) * 8 + r8;
            int seg = 2 * kk + (sub >> 1);
            aoff[kk][mi] = swz64(row, seg);
        }
#pragma unroll
        for (int nj = 0; nj < 4; nj++) {
            int row = wn * 64 + nj * 16 + (sub >> 1) * 8 + r8;
            int seg = 2 * kk + (sub & 1);
            boff[kk][nj] = swz64(row, seg);
        }
    }

    // cp.async mapping: 32 rows x 4 segs per pass (128 threads)
    const int ld_row = tid >> 2;         // 0..31
    const int ld_seg = tid & 3;          // 0..3
    const size_t g_off0 = (size_t)ld_row * K + ld_seg * 8;

    float acc[4][8][4];
#pragma unroll
    for (int mi = 0; mi < 4; mi++)
#pragma unroll
        for (int ni = 0; ni < 8; ni++)
#pragma unroll
            for (int v = 0; v < 4; v++) acc[mi][ni][v] = 0.0f;

    auto issue_tile = [&](int c, int s) {
        const uint32_t sb = sbase + s * STAGE_B;
        const size_t rstep = (size_t)32 * K;
#pragma unroll
        for (int pl = 0; pl < 2; pl++) {
            const unsigned short* Ap =
                (const unsigned short*)args.A[pl] + (size_t)bm * K + c * BK;
            const uint32_t abase = sb + pl * A_PL;
#pragma unroll
            for (int r = 0; r < 4; r++)
                cp_async16(abase + swz64(ld_row + r * 32, ld_seg),
                           Ap + g_off0 + r * rstep);
        }
#pragma unroll
        for (int pl = 0; pl < NB; pl++) {
            const unsigned short* Bp =
                (const unsigned short*)Bset[pl] + (size_t)bn * K + c * BK;
            const uint32_t bbase = sb + 2 * A_PL + pl * B_PL;
#pragma unroll
            for (int r = 0; r < 4; r++)
                cp_async16(bbase + swz64(ld_row + r * 32, ld_seg),
                           Bp + g_off0 + r * rstep);
        }
    };

    // prologue: stages 0..STAGES-2 in flight
#pragma unroll
    for (int j = 0; j < STAGES - 1; j++) {
        issue_tile(j, j);
        CP_COMMIT();
    }
    CP_WAIT(STAGES - 2);
    __syncthreads();

    for (int i = 0; i < nchunk; i++) {
        // fill slot (i+STAGES-1)%STAGES — freed by the barrier ending iter i-1
        if (i + STAGES - 1 < nchunk) {
            issue_tile(i + STAGES - 1, (i + STAGES - 1) % STAGES);
            CP_COMMIT();
        }

        const uint32_t sb = sbase + (i % STAGES) * STAGE_B;
        const uint32_t a0 = sb, a1 = sb + A_PL;
        const uint32_t b0 = sb + 2 * A_PL, b1 = b0 + B_PL;
#pragma unroll
        for (int kk = 0; kk < 2; kk++) {
            uint32_t bh[4][4];
#pragma unroll
            for (int nj = 0; nj < 4; nj++) ldsm4(bh[nj], b0 + boff[kk][nj]);
            uint32_t bm_[4][4];
            if (MODE == 0) {
#pragma unroll
                for (int nj = 0; nj < 4; nj++) ldsm4(bm_[nj], b1 + boff[kk][nj]);
            }
#pragma unroll
            for (int mi = 0; mi < 4; mi++) {
                uint32_t ah[4], am[4];
                ldsm4(ah, a0 + aoff[kk][mi]);
                ldsm4(am, a1 + aoff[kk][mi]);
                // product A0 x B0
#pragma unroll
                for (int ni = 0; ni < 8; ni++) {
                    const int nj = ni >> 1, o = (ni & 1) * 2;
                    mma16816(acc[mi][ni], ah, bh[nj][o], bh[nj][o + 1]);
                }
                if (MODE == 0) {
                    // product A0 x B1
#pragma unroll
                    for (int ni = 0; ni < 8; ni++) {
                        const int nj = ni >> 1, o = (ni & 1) * 2;
                        mma16816(acc[mi][ni], ah, bm_[nj][o], bm_[nj][o + 1]);
                    }
                }
                // product A1 x B0
#pragma unroll
                for (int ni = 0; ni < 8; ni++) {
                    const int nj = ni >> 1, o = (ni & 1) * 2;
                    mma16816(acc[mi][ni], am, bh[nj][o], bh[nj][o + 1]);
                }
            }
        }
        CP_WAIT(STAGES - 2);   // next tile resident
        __syncthreads();       // everyone done reading this slot
    }

    // ---- epilogue from registers ----
    const int ldc = args.ldc;
    __half* Ohp = z ? args.Oh2 : args.Oh;
    __half* Omp = z ? args.Om2 : args.Om;
#pragma unroll
    for (int mi = 0; mi < 4; mi++) {
#pragma unroll
        for (int ni = 0; ni < 8; ni++) {
            const int r0 = bm + wm * 64 + mi * 16 + (lane >> 2);
            const int c0 = bn + wn * 64 + ni * 8 + (lane & 3) * 2;
#pragma unroll
            for (int h = 0; h < 2; h++) {
                const size_t o = (size_t)(r0 + h * 8) * ldc + c0;
                const float v0 = acc[mi][ni][2 * h + 0];
                const float v1 = acc[mi][ni][2 * h + 1];
                if (EPI == 0) {
                    float2 w;
                    w.x = args.alpha * v0;
                    w.y = args.alpha * v1;
                    *(float2*)(args.C + o) = w;
                } else {
                    __half h0 = __float2half_rn(v0);
                    __half h1 = __float2half_rn(v1);
                    __half m0 = __float2half_rn(v0 - __half2float(h0));
                    __half m1 = __float2half_rn(v1 - __half2float(h1));
                    uint32_t ph = (uint32_t)*(unsigned short*)&h0 |
                                  ((uint32_t)*(unsigned short*)&h1 << 16);
                    uint32_t pm = (uint32_t)*(unsigned short*)&m0 |
                                  ((uint32_t)*(unsigned short*)&m1 << 16);
                    *(uint32_t*)((unsigned short*)Ohp + o) = ph;
                    *(uint32_t*)((unsigned short*)Omp + o) = pm;
                }
            }
        }
    }
}

// ---------------------------------------------------------------------------
// elementwise 2-way fp16 split
// ---------------------------------------------------------------------------
__global__ __launch_bounds__(256)
void split2h_kernel(const float* __restrict__ in, __half* __restrict__ oh,
                    __half* __restrict__ om)
{
    size_t i = (size_t)blockIdx.x * 256 + threadIdx.x;
    float v = in[i];
    __half h = __float2half_rn(v);
    om[i] = __float2half_rn(v - __half2float(h));
    oh[i] = h;
}

// ---------------------------------------------------------------------------
// transpose + 2-way fp16 split: in[R][C] fp32 -> oh/om [C][R] fp16
// blockIdx.z selects (input, output) pair — merged Wq/Wk transpose.
// ---------------------------------------------------------------------------
__global__ __launch_bounds__(256)
void transp_split2h_dual(const float* __restrict__ in0, __half* oh0, __half* om0,
                         const float* __restrict__ in1, __half* oh1, __half* om1,
                         int R, int C)
{
    const float* in = blockIdx.z ? in1 : in0;
    __half* oh = blockIdx.z ? oh1 : oh0;
    __half* om = blockIdx.z ? om1 : om0;
    __shared__ float t[32][33];
    const int bc = blockIdx.x * 32, br = blockIdx.y * 32;
    const int tx = threadIdx.x & 31, ty = threadIdx.x >> 5;
#pragma unroll
    for (int j = 0; j < 32; j += 8)
        t[ty + j][tx] = in[(size_t)(br + ty + j) * C + bc + tx];
    __syncthreads();
#pragma unroll
    for (int j = 0; j < 32; j += 8) {
        int oc = bc + ty + j;
        float v = t[tx][ty + j];
        __half h = __float2half_rn(v);
        size_t o = (size_t)oc * R + br + tx;
        oh[o] = h;
        om[o] = __float2half_rn(v - __half2float(h));
    }
}

// ---------------------------------------------------------------------------
// transpose to fp16 (high only): in[R][C] fp32 -> oh[C][R] fp16
// ---------------------------------------------------------------------------
__global__ __launch_bounds__(256)
void transp_h(const float* __restrict__ in, __half* oh, int R, int C)
{
    __shared__ float t[32][33];
    const int bc = blockIdx.x * 32, br = blockIdx.y * 32;
    const int tx = threadIdx.x & 31, ty = threadIdx.x >> 5;
#pragma unroll
    for (int j = 0; j < 32; j += 8)
        t[ty + j][tx] = in[(size_t)(br + ty + j) * C + bc + tx];
    __syncthreads();
#pragma unroll
    for (int j = 0; j < 32; j += 8) {
        int oc = bc + ty + j;
        oh[(size_t)oc * R + br + tx] = __float2half_rn(t[tx][ty + j]);
    }
}

// ---------------------------------------------------------------------------
// softmax over rows of S, emitting 2-way fp16 split of P. Row cached in SMEM.
// ---------------------------------------------------------------------------
__global__ __launch_bounds__(256)
void softmax_split(const float* __restrict__ S, __half* __restrict__ Ph,
                   __half* __restrict__ Pl, int n)
{
    __shared__ float row[SEQ];
    __shared__ float red[256];
    const float* s = S + (size_t)blockIdx.x * n;
    const int tid = threadIdx.x;

    float m = -3.4e38f;
    for (int i = tid; i < n; i += 256) {
        float v = s[i];
        row[i] = v;
        m = fmaxf(m, v);
    }
    red[tid] = m;
    __syncthreads();
    for (int st = 128; st > 0; st >>= 1) {
        if (tid < st) red[tid] = fmaxf(red[tid], red[tid + st]);
        __syncthreads();
    }
    m = red[0];
    __syncthreads();

    float sum = 0.0f;
    for (int i = tid; i < n; i += 256) {
        float e = expf(row[i] - m);
        row[i] = e;
        sum += e;
    }
    red[tid] = sum;
    __syncthreads();
    for (int st = 128; st > 0; st >>= 1) {
        if (tid < st) red[tid] += red[tid + st];
        __syncthreads();
    }
    const float inv = 1.0f / red[0];
    __syncthreads();

    __half* ph = Ph + (size_t)blockIdx.x * n;
    __half* pl = Pl + (size_t)blockIdx.x * n;
    for (int i = tid; i < n; i += 256) {
        float p = row[i] * inv;
        __half h = __float2half_rn(p);
        ph[i] = h;
        pl[i] = __float2half_rn(p - __half2float(h));
    }
}

// ---------------------------------------------------------------------------
extern "C" void kernel_launch(void* const* d_in, const int* in_sizes, int n_in,
                              void* d_out, int out_size)
{
    const float* X  = (const float*)d_in[0];
    const float* Wq = (const float*)d_in[1];
    const float* Wk = (const float*)d_in[2];
    float* out = (float*)d_out;

    void* p;
#define SYM(name, var) cudaGetSymbolAddress(&p, name); auto* var = (decltype(&name[0]))p;
    SYM(g_S, S) SYM(g_Ph, Ph) SYM(g_Pl, Pl)
    SYM(g_Qh, Qh) SYM(g_Qm, Qm)
    SYM(g_Kh, Kh) SYM(g_Km, Km)
    SYM(g_Xh, Xh) SYM(g_Xm, Xm)
    SYM(g_Xth, Xth)
    SYM(g_Wqh, Wqh) SYM(g_Wqm, Wqm)
    SYM(g_Wkh, Wkh) SYM(g_Wkm, Wkm)
#undef SYM

    const int SMEM_M0 = 3 * 32768;   // 3 stages x 32KB (2 CTAs/SM)
    const int SMEM_M1 = 4 * 24576;   // 4 stages x 24KB (2 CTAs/SM)
    cudaFuncSetAttribute(gemm_mma<0, 1>, cudaFuncAttributeMaxDynamicSharedMemorySize, SMEM_M0);
    cudaFuncSetAttribute(gemm_mma<0, 0>, cudaFuncAttributeMaxDynamicSharedMemorySize, SMEM_M0);
    cudaFuncSetAttribute(gemm_mma<1, 0>, cudaFuncAttributeMaxDynamicSharedMemorySize, SMEM_M1);

    // --- prep: splits & transposes ---
    split2h_kernel<<<SEQ * DIM / 256, 256>>>(X, Xh, Xm);
    transp_h<<<dim3(DIM / 32, SEQ / 32), 256>>>(X, Xth, SEQ, DIM);
    transp_split2h_dual<<<dim3(DIM / 32, DIM / 32, 2), 256>>>(
        Wq, Wqh, Wqm, Wk, Wkh, Wkm, DIM, DIM);

    // --- projections Q and K in one launch (z selects weight set) ---
    {
        GemmArgs a{};
        a.A[0] = Xh;  a.A[1] = Xm;
        a.B[0] = Wqh; a.B[1] = Wqm;
        a.B2[0] = Wkh; a.B2[1] = Wkm;
        a.K = DIM; a.ldc = DIM; a.alpha = 1.0f;
        a.Oh = Qh; a.Om = Qm; a.Oh2 = Kh; a.Om2 = Km;
        gemm_mma<0, 1><<<dim3(DIM / 128, SEQ / 128, 2), 128, SMEM_M0>>>(a);
    }
    // --- S = (Q @ K^T) / 32 : products {hh, hm, mh} ---
    {
        GemmArgs a{};
        a.A[0] = Qh; a.A[1] = Qm;
        a.B[0] = Kh; a.B[1] = Km;
        a.K = DIM; a.ldc = SEQ; a.alpha = 0.03125f;
        a.C = S;
        gemm_mma<0, 0><<<dim3(SEQ / 128, SEQ / 128, 1), 128, SMEM_M0>>>(a);
    }
    // --- softmax + fp16 split of P ---
    softmax_split<<<SEQ, 256>>>(S, Ph, Pl, SEQ);
    // --- out = P @ Xh : products {Ph·Xth, Pl·Xth} = P·Xth exactly ---
    {
        GemmArgs a{};
        a.A[0] = Ph; a.A[1] = Pl;
        a.B[0] = Xth;
        a.K = SEQ; a.ldc = DIM; a.alpha = 1.0f;
        a.C = out;
        gemm_mma<1, 0><<<dim3(DIM / 128, SEQ / 128, 1), 128, SMEM_M1>>>(a);
    }
}

// round 12
// speedup vs baseline: 4.0353x; 1.0140x over previous
#include <cuda_runtime.h>
#include <cuda_bf16.h>
#include <cuda_fp16.h>
#include <cstdint>
#include <math.h>

#define SEQ 8192
#define DIM 1024

// ---------------------------------------------------------------------------
// Scratch (device globals — allocation-free)
// ---------------------------------------------------------------------------
__device__ __align__(256) float g_S[(size_t)SEQ * SEQ];     // 256MB logits
__device__ __align__(256) __half g_Ph[(size_t)SEQ * SEQ];   // 128MB
__device__ __align__(256) __half g_Pl[(size_t)SEQ * SEQ];   // 128MB
__device__ __align__(256) __half g_Qh[SEQ * DIM], g_Qm[SEQ * DIM];
__device__ __align__(256) __half g_Kh[SEQ * DIM], g_Km[SEQ * DIM];
__device__ __align__(256) __half g_Xh[SEQ * DIM], g_Xm[SEQ * DIM];
__device__ __align__(256) __half g_Xth[DIM * SEQ];
__device__ __align__(256) __half g_Wqh[DIM * DIM], g_Wqm[DIM * DIM];
__device__ __align__(256) __half g_Wkh[DIM * DIM], g_Wkm[DIM * DIM];

// ---------------------------------------------------------------------------
// PTX helpers (baseline ISA only — valid on .target sm_103)
// ---------------------------------------------------------------------------
__device__ __forceinline__ uint32_t smem_u32(const void* p) {
    uint32_t a;
    asm("{ .reg .u64 t; cvta.to.shared.u64 t, %1; cvt.u32.u64 %0, t; }"
        : "=r"(a) : "l"(p));
    return a;
}

__device__ __forceinline__ void cp_async16(uint32_t saddr, const void* gaddr) {
    asm volatile("cp.async.cg.shared.global [%0], [%1], 16;"
                 :: "r"(saddr), "l"(gaddr));
}
#define CP_COMMIT() asm volatile("cp.async.commit_group;")
#define CP_WAIT(N)  asm volatile("cp.async.wait_group %0;" :: "n"(N))

__device__ __forceinline__ void ldsm4(uint32_t* r, uint32_t addr) {
    asm volatile("ldmatrix.sync.aligned.m8n8.x4.shared.b16 {%0,%1,%2,%3}, [%4];"
                 : "=r"(r[0]), "=r"(r[1]), "=r"(r[2]), "=r"(r[3])
                 : "r"(addr));
}

// fp16 inputs, fp32 accumulate
__device__ __forceinline__ void mma16816(float* d, const uint32_t* a,
                                         uint32_t b0, uint32_t b1) {
    asm volatile(
        "mma.sync.aligned.m16n8k16.row.col.f32.f16.f16.f32 "
        "{%0,%1,%2,%3}, {%4,%5,%6,%7}, {%8,%9}, {%0,%1,%2,%3};"
        : "+f"(d[0]), "+f"(d[1]), "+f"(d[2]), "+f"(d[3])
        : "r"(a[0]), "r"(a[1]), "r"(a[2]), "r"(a[3]), "r"(b0), "r"(b1));
}

// swizzled smem byte offset for (row, 16B-segment 0..3) in a 64B-pitch tile
__device__ __forceinline__ uint32_t swz64(int row, int seg) {
    return (uint32_t)(row * 64 + ((seg ^ ((row >> 1) & 3)) << 4));
}

// ---------------------------------------------------------------------------
// Multi-plane HMMA GEMM, all products accumulated into ONE output:
//   MODE 0:  D = alpha * (A0@B0^T + A0@B1^T + A1@B0^T)    (3-product split)
//   MODE 1:  D = alpha * (A0@B0^T + A1@B0^T)              (exact pair sum)
// CTA: 128 threads (2x2 warps, warp tile 64x64), tile 128x128, BK=32.
// Stage = all planes of one K-chunk (32KB / 24KB); 3 / 4 stages = 96KB
// -> 2 CTAs per SM; fragments shared across products.
// EPI 0: C = alpha*D (fp32, streaming store). EPI 1: 2-way fp16 split of D.
// ---------------------------------------------------------------------------
struct GemmArgs {
    const void* A[2];
    const void* B[2];
    const void* B2[2];
    int K;        // reduction length (multiple of 32)
    int ldc;
    float alpha;
    float* C;
    __half *Oh, *Om, *Oh2, *Om2;
};

template <int MODE, int EPI>
__global__ __launch_bounds__(128, 2)
void gemm_mma(const GemmArgs args)
{
    constexpr int BM = 128, BN = 128, BK = 32;
    constexpr int NB = (MODE == 0) ? 2 : 1;
    constexpr int STAGES = (MODE == 0) ? 3 : 4;
    constexpr int A_PL = BM * 64;                  // 8KB per A plane
    constexpr int B_PL = BN * 64;                  // 8KB per B plane
    constexpr int STAGE_B = 2 * A_PL + NB * B_PL;  // 32KB / 24KB
    extern __shared__ __align__(128) char smem[];
    const uint32_t sbase = smem_u32(smem);

    const int tid = threadIdx.x;
    const int wid = tid >> 5;
    const int lane = tid & 31;
    const int wm = wid & 1;          // 2 warps along M (64 rows each)
    const int wn = wid >> 1;         // 2 warps along N (64 cols each)
    const int bm = blockIdx.y * BM;
    const int bn = blockIdx.x * BN;
    const int K = args.K;
    const int nchunk = K / BK;
    const int z = blockIdx.z;
    const void* const* Bset = z ? args.B2 : args.B;

    // per-lane ldmatrix offsets: 2 k16-steps per BK=32 chunk
    const int sub = lane >> 3, r8 = lane & 7;
    uint32_t aoff[2][4], boff[2][4];
#pragma unroll
    for (int kk = 0; kk < 2; kk++) {
#pragma unroll
        for (int mi = 0; mi < 4; mi++) {
            int row = wm * 64 + mi * 16 + (sub & 1) * 8 + r8;
            int seg = 2 * kk + (sub >> 1);
            aoff[kk][mi] = swz64(row, seg);
        }
#pragma unroll
        for (int nj = 0; nj < 4; nj++) {
            int row = wn * 64 + nj * 16 + (sub >> 1) * 8 + r8;
            int seg = 2 * kk + (sub & 1);
            boff[kk][nj] = swz64(row, seg);
        }
    }

    // cp.async mapping: 32 rows x 4 segs per pass (128 threads)
    const int ld_row = tid >> 2;         // 0..31
    const int ld_seg = tid & 3;          // 0..3
    const size_t g_off0 = (size_t)ld_row * K + ld_seg * 8;

    float acc[4][8][4];
#pragma unroll
    for (int mi = 0; mi < 4; mi++)
#pragma unroll
        for (int ni = 0; ni < 8; ni++)
#pragma unroll
            for (int v = 0; v < 4; v++) acc[mi][ni][v] = 0.0f;

    auto issue_tile = [&](int c, int s) {
        const uint32_t sb = sbase + s * STAGE_B;
        const size_t rstep = (size_t)32 * K;
#pragma unroll
        for (int pl = 0; pl < 2; pl++) {
            const unsigned short* Ap =
                (const unsigned short*)args.A[pl] + (size_t)bm * K + c * BK;
            const uint32_t abase = sb + pl * A_PL;
#pragma unroll
            for (int r = 0; r < 4; r++)
                cp_async16(abase + swz64(ld_row + r * 32, ld_seg),
                           Ap + g_off0 + r * rstep);
        }
#pragma unroll
        for (int pl = 0; pl < NB; pl++) {
            const unsigned short* Bp =
                (const unsigned short*)Bset[pl] + (size_t)bn * K + c * BK;
            const uint32_t bbase = sb + 2 * A_PL + pl * B_PL;
#pragma unroll
            for (int r = 0; r < 4; r++)
                cp_async16(bbase + swz64(ld_row + r * 32, ld_seg),
                           Bp + g_off0 + r * rstep);
        }
    };

    // prologue: stages 0..STAGES-2 in flight
#pragma unroll
    for (int j = 0; j < STAGES - 1; j++) {
        issue_tile(j, j);
        CP_COMMIT();
    }
    CP_WAIT(STAGES - 2);
    __syncthreads();

    for (int i = 0; i < nchunk; i++) {
        // fill slot (i+STAGES-1)%STAGES — freed by the barrier ending iter i-1
        if (i + STAGES - 1 < nchunk) {
            issue_tile(i + STAGES - 1, (i + STAGES - 1) % STAGES);
            CP_COMMIT();
        }

        const uint32_t sb = sbase + (i % STAGES) * STAGE_B;
        const uint32_t a0 = sb, a1 = sb + A_PL;
        const uint32_t b0 = sb + 2 * A_PL, b1 = b0 + B_PL;
#pragma unroll
        for (int kk = 0; kk < 2; kk++) {
            uint32_t bh[4][4];
#pragma unroll
            for (int nj = 0; nj < 4; nj++) ldsm4(bh[nj], b0 + boff[kk][nj]);
            uint32_t bm_[4][4];
            if (MODE == 0) {
#pragma unroll
                for (int nj = 0; nj < 4; nj++) ldsm4(bm_[nj], b1 + boff[kk][nj]);
            }
#pragma unroll
            for (int mi = 0; mi < 4; mi++) {
                uint32_t ah[4], am[4];
                ldsm4(ah, a0 + aoff[kk][mi]);
                ldsm4(am, a1 + aoff[kk][mi]);
                // product A0 x B0
#pragma unroll
                for (int ni = 0; ni < 8; ni++) {
                    const int nj = ni >> 1, o = (ni & 1) * 2;
                    mma16816(acc[mi][ni], ah, bh[nj][o], bh[nj][o + 1]);
                }
                if (MODE == 0) {
                    // product A0 x B1
#pragma unroll
                    for (int ni = 0; ni < 8; ni++) {
                        const int nj = ni >> 1, o = (ni & 1) * 2;
                        mma16816(acc[mi][ni], ah, bm_[nj][o], bm_[nj][o + 1]);
                    }
                }
                // product A1 x B0
#pragma unroll
                for (int ni = 0; ni < 8; ni++) {
                    const int nj = ni >> 1, o = (ni & 1) * 2;
                    mma16816(acc[mi][ni], am, bh[nj][o], bh[nj][o + 1]);
                }
            }
        }
        CP_WAIT(STAGES - 2);   // next tile resident
        __syncthreads();       // everyone done reading this slot
    }

    // ---- epilogue from registers ----
    const int ldc = args.ldc;
    __half* Ohp = z ? args.Oh2 : args.Oh;
    __half* Omp = z ? args.Om2 : args.Om;
#pragma unroll
    for (int mi = 0; mi < 4; mi++) {
#pragma unroll
        for (int ni = 0; ni < 8; ni++) {
            const int r0 = bm + wm * 64 + mi * 16 + (lane >> 2);
            const int c0 = bn + wn * 64 + ni * 8 + (lane & 3) * 2;
#pragma unroll
            for (int h = 0; h < 2; h++) {
                const size_t o = (size_t)(r0 + h * 8) * ldc + c0;
                const float v0 = acc[mi][ni][2 * h + 0];
                const float v1 = acc[mi][ni][2 * h + 1];
                if (EPI == 0) {
                    float2 w;
                    w.x = args.alpha * v0;
                    w.y = args.alpha * v1;
                    // streaming store — C (S / out) is never re-read via L2
                    __stcs((float2*)(args.C + o), w);
                } else {
                    __half h0 = __float2half_rn(v0);
                    __half h1 = __float2half_rn(v1);
                    __half m0 = __float2half_rn(v0 - __half2float(h0));
                    __half m1 = __float2half_rn(v1 - __half2float(h1));
                    uint32_t ph = (uint32_t)*(unsigned short*)&h0 |
                                  ((uint32_t)*(unsigned short*)&h1 << 16);
                    uint32_t pm = (uint32_t)*(unsigned short*)&m0 |
                                  ((uint32_t)*(unsigned short*)&m1 << 16);
                    *(uint32_t*)((unsigned short*)Ohp + o) = ph;
                    *(uint32_t*)((unsigned short*)Omp + o) = pm;
                }
            }
        }
    }
}

// ---------------------------------------------------------------------------
// elementwise 2-way fp16 split
// ---------------------------------------------------------------------------
__global__ __launch_bounds__(256)
void split2h_kernel(const float* __restrict__ in, __half* __restrict__ oh,
                    __half* __restrict__ om)
{
    size_t i = (size_t)blockIdx.x * 256 + threadIdx.x;
    float v = in[i];
    __half h = __float2half_rn(v);
    om[i] = __float2half_rn(v - __half2float(h));
    oh[i] = h;
}

// ---------------------------------------------------------------------------
// transpose + 2-way fp16 split: in[R][C] fp32 -> oh/om [C][R] fp16
// blockIdx.z selects (input, output) pair — merged Wq/Wk transpose.
// ---------------------------------------------------------------------------
__global__ __launch_bounds__(256)
void transp_split2h_dual(const float* __restrict__ in0, __half* oh0, __half* om0,
                         const float* __restrict__ in1, __half* oh1, __half* om1,
                         int R, int C)
{
    const float* in = blockIdx.z ? in1 : in0;
    __half* oh = blockIdx.z ? oh1 : oh0;
    __half* om = blockIdx.z ? om1 : om0;
    __shared__ float t[32][33];
    const int bc = blockIdx.x * 32, br = blockIdx.y * 32;
    const int tx = threadIdx.x & 31, ty = threadIdx.x >> 5;
#pragma unroll
    for (int j = 0; j < 32; j += 8)
        t[ty + j][tx] = in[(size_t)(br + ty + j) * C + bc + tx];
    __syncthreads();
#pragma unroll
    for (int j = 0; j < 32; j += 8) {
        int oc = bc + ty + j;
        float v = t[tx][ty + j];
        __half h = __float2half_rn(v);
        size_t o = (size_t)oc * R + br + tx;
        oh[o] = h;
        om[o] = __float2half_rn(v - __half2float(h));
    }
}

// ---------------------------------------------------------------------------
// transpose to fp16 (high only): in[R][C] fp32 -> oh[C][R] fp16
// ---------------------------------------------------------------------------
__global__ __launch_bounds__(256)
void transp_h(const float* __restrict__ in, __half* oh, int R, int C)
{
    __shared__ float t[32][33];
    const int bc = blockIdx.x * 32, br = blockIdx.y * 32;
    const int tx = threadIdx.x & 31, ty = threadIdx.x >> 5;
#pragma unroll
    for (int j = 0; j < 32; j += 8)
        t[ty + j][tx] = in[(size_t)(br + ty + j) * C + bc + tx];
    __syncthreads();
#pragma unroll
    for (int j = 0; j < 32; j += 8) {
        int oc = bc + ty + j;
        oh[(size_t)oc * R + br + tx] = __float2half_rn(t[tx][ty + j]);
    }
}

// ---------------------------------------------------------------------------
// softmax over rows of S, emitting 2-way fp16 split of P.
// 512 threads, float4 streaming loads, __expf, shuffle+smem reductions,
// streaming vectorized stores. Row cached in SMEM (one global read of S).
// ---------------------------------------------------------------------------
__global__ __launch_bounds__(512)
void softmax_split(const float* __restrict__ S, __half* __restrict__ Ph,
                   __half* __restrict__ Pl, int n)
{
    __shared__ float row[SEQ];
    __shared__ float red[16];
    const int tid = threadIdx.x;
    const int lane = tid & 31;
    const int warp = tid >> 5;
    const int nv = n / 4;                      // float4 count
    const float4* s4 = (const float4*)(S + (size_t)blockIdx.x * n);
    float4* r4 = (float4*)row;

    // pass 1: load (streaming), cache, local max
    float m = -3.4e38f;
    for (int i = tid; i < nv; i += 512) {
        float4 v = __ldcs(s4 + i);
        r4[i] = v;
        m = fmaxf(fmaxf(m, v.x), fmaxf(v.y, fmaxf(v.z, v.w)));
    }
#pragma unroll
    for (int o = 16; o > 0; o >>= 1)
        m = fmaxf(m, __shfl_xor_sync(0xffffffffu, m, o));
    if (lane == 0) red[warp] = m;
    __syncthreads();
    {
        float t = red[lane & 15];
#pragma unroll
        for (int o = 8; o > 0; o >>= 1)
            t = fmaxf(t, __shfl_xor_sync(0xffffffffu, t, o));
        m = __shfl_sync(0xffffffffu, t, 0);
    }
    __syncthreads();

    // pass 2: exp + local sum (in smem)
    float sum = 0.0f;
    for (int i = tid; i < nv; i += 512) {
        float4 v = r4[i];
        v.x = __expf(v.x - m);
        v.y = __expf(v.y - m);
        v.z = __expf(v.z - m);
        v.w = __expf(v.w - m);
        r4[i] = v;
        sum += v.x + v.y + v.z + v.w;
    }
#pragma unroll
    for (int o = 16; o > 0; o >>= 1)
        sum += __shfl_xor_sync(0xffffffffu, sum, o);
    if (lane == 0) red[warp] = sum;
    __syncthreads();
    {
        float t = red[lane & 15];
#pragma unroll
        for (int o = 8; o > 0; o >>= 1)
            t += __shfl_xor_sync(0xffffffffu, t, o);
        sum = __shfl_sync(0xffffffffu, t, 0);
    }
    const float inv = 1.0f / sum;
    __syncthreads();

    // pass 3: normalize + fp16 split, streaming vector stores
    unsigned short* ph = (unsigned short*)(Ph + (size_t)blockIdx.x * n);
    unsigned short* pl = (unsigned short*)(Pl + (size_t)blockIdx.x * n);
    for (int i = tid; i < nv; i += 512) {
        float4 v = r4[i];
        float p0 = v.x * inv, p1 = v.y * inv, p2 = v.z * inv, p3 = v.w * inv;
        __half h0 = __float2half_rn(p0), h1 = __float2half_rn(p1);
        __half h2 = __float2half_rn(p2), h3 = __float2half_rn(p3);
        __half l0 = __float2half_rn(p0 - __half2float(h0));
        __half l1 = __float2half_rn(p1 - __half2float(h1));
        __half l2 = __float2half_rn(p2 - __half2float(h2));
        __half l3 = __float2half_rn(p3 - __half2float(h3));
        int2 wh, wl;
        wh.x = (int)((uint32_t)*(unsigned short*)&h0 |
                     ((uint32_t)*(unsigned short*)&h1 << 16));
        wh.y = (int)((uint32_t)*(unsigned short*)&h2 |
                     ((uint32_t)*(unsigned short*)&h3 << 16));
        wl.x = (int)((uint32_t)*(unsigned short*)&l0 |
                     ((uint32_t)*(unsigned short*)&l1 << 16));
        wl.y = (int)((uint32_t)*(unsigned short*)&l2 |
                     ((uint32_t)*(unsigned short*)&l3 << 16));
        __stcs((int2*)(ph + i * 4), wh);
        __stcs((int2*)(pl + i * 4), wl);
    }
}

// ---------------------------------------------------------------------------
extern "C" void kernel_launch(void* const* d_in, const int* in_sizes, int n_in,
                              void* d_out, int out_size)
{
    const float* X  = (const float*)d_in[0];
    const float* Wq = (const float*)d_in[1];
    const float* Wk = (const float*)d_in[2];
    float* out = (float*)d_out;

    void* p;
#define SYM(name, var) cudaGetSymbolAddress(&p, name); auto* var = (decltype(&name[0]))p;
    SYM(g_S, S) SYM(g_Ph, Ph) SYM(g_Pl, Pl)
    SYM(g_Qh, Qh) SYM(g_Qm, Qm)
    SYM(g_Kh, Kh) SYM(g_Km, Km)
    SYM(g_Xh, Xh) SYM(g_Xm, Xm)
    SYM(g_Xth, Xth)
    SYM(g_Wqh, Wqh) SYM(g_Wqm, Wqm)
    SYM(g_Wkh, Wkh) SYM(g_Wkm, Wkm)
#undef SYM

    const int SMEM_M0 = 3 * 32768;   // 3 stages x 32KB (2 CTAs/SM)
    const int SMEM_M1 = 4 * 24576;   // 4 stages x 24KB (2 CTAs/SM)
    cudaFuncSetAttribute(gemm_mma<0, 1>, cudaFuncAttributeMaxDynamicSharedMemorySize, SMEM_M0);
    cudaFuncSetAttribute(gemm_mma<0, 0>, cudaFuncAttributeMaxDynamicSharedMemorySize, SMEM_M0);
    cudaFuncSetAttribute(gemm_mma<1, 0>, cudaFuncAttributeMaxDynamicSharedMemorySize, SMEM_M1);

    // --- prep: splits & transposes ---
    split2h_kernel<<<SEQ * DIM / 256, 256>>>(X, Xh, Xm);
    transp_h<<<dim3(DIM / 32, SEQ / 32), 256>>>(X, Xth, SEQ, DIM);
    transp_split2h_dual<<<dim3(DIM / 32, DIM / 32, 2), 256>>>(
        Wq, Wqh, Wqm, Wk, Wkh, Wkm, DIM, DIM);

    // --- projections Q and K in one launch (z selects weight set) ---
    {
        GemmArgs a{};
        a.A[0] = Xh;  a.A[1] = Xm;
        a.B[0] = Wqh; a.B[1] = Wqm;
        a.B2[0] = Wkh; a.B2[1] = Wkm;
        a.K = DIM; a.ldc = DIM; a.alpha = 1.0f;
        a.Oh = Qh; a.Om = Qm; a.Oh2 = Kh; a.Om2 = Km;
        gemm_mma<0, 1><<<dim3(DIM / 128, SEQ / 128, 2), 128, SMEM_M0>>>(a);
    }
    // --- S = (Q @ K^T) / 32 : products {hh, hm, mh} ---
    {
        GemmArgs a{};
        a.A[0] = Qh; a.A[1] = Qm;
        a.B[0] = Kh; a.B[1] = Km;
        a.K = DIM; a.ldc = SEQ; a.alpha = 0.03125f;
        a.C = S;
        gemm_mma<0, 0><<<dim3(SEQ / 128, SEQ / 128, 1), 128, SMEM_M0>>>(a);
    }
    // --- softmax + fp16 split of P ---
    softmax_split<<<SEQ, 512>>>(S, Ph, Pl, SEQ);
    // --- out = P @ Xh : products {Ph·Xth, Pl·Xth} = P·Xth exactly ---
    {
        GemmArgs a{};
        a.A[0] = Ph; a.A[1] = Pl;
        a.B[0] = Xth;
        a.K = SEQ; a.ldc = DIM; a.alpha = 1.0f;
        a.C = out;
        gemm_mma<1, 0><<<dim3(DIM / 128, SEQ / 128, 1), 128, SMEM_M1>>>(a);
    }
}

// round 13
// speedup vs baseline: 4.7925x; 1.1876x over previous
#include <cuda_runtime.h>
#include <cuda_bf16.h>
#include <cuda_fp16.h>
#include <cstdint>
#include <math.h>

#define SEQ 8192
#define DIM 1024

// ---------------------------------------------------------------------------
// Scratch (device globals — allocation-free)
// ---------------------------------------------------------------------------
__device__ __align__(256) float g_S[(size_t)SEQ * SEQ];     // 256MB logits
__device__ __align__(256) __half g_Ph[(size_t)SEQ * SEQ];   // 128MB probs (fp16)
__device__ __align__(256) __half g_Qh[SEQ * DIM], g_Qm[SEQ * DIM];
__device__ __align__(256) __half g_Kh[SEQ * DIM], g_Km[SEQ * DIM];
__device__ __align__(256) __half g_Xh[SEQ * DIM], g_Xm[SEQ * DIM];
__device__ __align__(256) __half g_Xth[DIM * SEQ];
__device__ __align__(256) __half g_Wqh[DIM * DIM], g_Wqm[DIM * DIM];
__device__ __align__(256) __half g_Wkh[DIM * DIM], g_Wkm[DIM * DIM];

// ---------------------------------------------------------------------------
// PTX helpers (baseline ISA only — valid on .target sm_103)
// ---------------------------------------------------------------------------
__device__ __forceinline__ uint32_t smem_u32(const void* p) {
    uint32_t a;
    asm("{ .reg .u64 t; cvta.to.shared.u64 t, %1; cvt.u32.u64 %0, t; }"
        : "=r"(a) : "l"(p));
    return a;
}

__device__ __forceinline__ void cp_async16(uint32_t saddr, const void* gaddr) {
    asm volatile("cp.async.cg.shared.global [%0], [%1], 16;"
                 :: "r"(saddr), "l"(gaddr));
}
#define CP_COMMIT() asm volatile("cp.async.commit_group;")
#define CP_WAIT(N)  asm volatile("cp.async.wait_group %0;" :: "n"(N))

__device__ __forceinline__ void ldsm4(uint32_t* r, uint32_t addr) {
    asm volatile("ldmatrix.sync.aligned.m8n8.x4.shared.b16 {%0,%1,%2,%3}, [%4];"
                 : "=r"(r[0]), "=r"(r[1]), "=r"(r[2]), "=r"(r[3])
                 : "r"(addr));
}

// fp16 inputs, fp32 accumulate
__device__ __forceinline__ void mma16816(float* d, const uint32_t* a,
                                         uint32_t b0, uint32_t b1) {
    asm volatile(
        "mma.sync.aligned.m16n8k16.row.col.f32.f16.f16.f32 "
        "{%0,%1,%2,%3}, {%4,%5,%6,%7}, {%8,%9}, {%0,%1,%2,%3};"
        : "+f"(d[0]), "+f"(d[1]), "+f"(d[2]), "+f"(d[3])
        : "r"(a[0]), "r"(a[1]), "r"(a[2]), "r"(a[3]), "r"(b0), "r"(b1));
}

// swizzled smem byte offset for (row, 16B-segment 0..3) in a 64B-pitch tile
__device__ __forceinline__ uint32_t swz64(int row, int seg) {
    return (uint32_t)(row * 64 + ((seg ^ ((row >> 1) & 3)) << 4));
}

// ---------------------------------------------------------------------------
// Multi-plane HMMA GEMM, all products accumulated into ONE output:
//   MODE 0:  D = alpha * (A0@B0^T + A0@B1^T + A1@B0^T)    (3-product split)
//   MODE 1:  D = alpha * (A0@B0^T)                        (plain GEMM)
// CTA: 128 threads (2x2 warps, warp tile 64x64), tile 128x128, BK=32.
// Stage = all planes of one K-chunk (32KB / 16KB); 3 / 6 stages = 96KB
// -> 2 CTAs per SM; fragments shared across products.
// EPI 0: C = alpha*D (fp32, streaming store). EPI 1: 2-way fp16 split of D.
// ---------------------------------------------------------------------------
struct GemmArgs {
    const void* A[2];
    const void* B[2];
    const void* B2[2];
    int K;        // reduction length (multiple of 32)
    int ldc;
    float alpha;
    float* C;
    __half *Oh, *Om, *Oh2, *Om2;
};

template <int MODE, int EPI>
__global__ __launch_bounds__(128, 2)
void gemm_mma(const GemmArgs args)
{
    constexpr int BM = 128, BN = 128, BK = 32;
    constexpr int NA = (MODE == 0) ? 2 : 1;
    constexpr int NB = (MODE == 0) ? 2 : 1;
    constexpr int STAGES = (MODE == 0) ? 3 : 6;
    constexpr int A_PL = BM * 64;                  // 8KB per A plane
    constexpr int B_PL = BN * 64;                  // 8KB per B plane
    constexpr int STAGE_B = NA * A_PL + NB * B_PL; // 32KB / 16KB
    extern __shared__ __align__(128) char smem[];
    const uint32_t sbase = smem_u32(smem);

    const int tid = threadIdx.x;
    const int wid = tid >> 5;
    const int lane = tid & 31;
    const int wm = wid & 1;          // 2 warps along M (64 rows each)
    const int wn = wid >> 1;         // 2 warps along N (64 cols each)
    const int bm = blockIdx.y * BM;
    const int bn = blockIdx.x * BN;
    const int K = args.K;
    const int nchunk = K / BK;
    const int z = blockIdx.z;
    const void* const* Bset = z ? args.B2 : args.B;

    // per-lane ldmatrix offsets: 2 k16-steps per BK=32 chunk
    const int sub = lane >> 3, r8 = lane & 7;
    uint32_t aoff[2][4], boff[2][4];
#pragma unroll
    for (int kk = 0; kk < 2; kk++) {
#pragma unroll
        for (int mi = 0; mi < 4; mi++) {
            int row = wm * 64 + mi * 16 + (sub & 1) * 8 + r8;
            int seg = 2 * kk + (sub >> 1);
            aoff[kk][mi] = swz64(row, seg);
        }
#pragma unroll
        for (int nj = 0; nj < 4; nj++) {
            int row = wn * 64 + nj * 16 + (sub >> 1) * 8 + r8;
            int seg = 2 * kk + (sub & 1);
            boff[kk][nj] = swz64(row, seg);
        }
    }

    // cp.async mapping: 32 rows x 4 segs per pass (128 threads)
    const int ld_row = tid >> 2;         // 0..31
    const int ld_seg = tid & 3;          // 0..3
    const size_t g_off0 = (size_t)ld_row * K + ld_seg * 8;

    float acc[4][8][4];
#pragma unroll
    for (int mi = 0; mi < 4; mi++)
#pragma unroll
        for (int ni = 0; ni < 8; ni++)
#pragma unroll
            for (int v = 0; v < 4; v++) acc[mi][ni][v] = 0.0f;

    auto issue_tile = [&](int c, int s) {
        const uint32_t sb = sbase + s * STAGE_B;
        const size_t rstep = (size_t)32 * K;
#pragma unroll
        for (int pl = 0; pl < NA; pl++) {
            const unsigned short* Ap =
                (const unsigned short*)args.A[pl] + (size_t)bm * K + c * BK;
            const uint32_t abase = sb + pl * A_PL;
#pragma unroll
            for (int r = 0; r < 4; r++)
                cp_async16(abase + swz64(ld_row + r * 32, ld_seg),
                           Ap + g_off0 + r * rstep);
        }
#pragma unroll
        for (int pl = 0; pl < NB; pl++) {
            const unsigned short* Bp =
                (const unsigned short*)Bset[pl] + (size_t)bn * K + c * BK;
            const uint32_t bbase = sb + NA * A_PL + pl * B_PL;
#pragma unroll
            for (int r = 0; r < 4; r++)
                cp_async16(bbase + swz64(ld_row + r * 32, ld_seg),
                           Bp + g_off0 + r * rstep);
        }
    };

    // prologue: stages 0..STAGES-2 in flight
#pragma unroll
    for (int j = 0; j < STAGES - 1; j++) {
        issue_tile(j, j);
        CP_COMMIT();
    }
    CP_WAIT(STAGES - 2);
    __syncthreads();

    for (int i = 0; i < nchunk; i++) {
        // fill slot (i+STAGES-1)%STAGES — freed by the barrier ending iter i-1
        if (i + STAGES - 1 < nchunk) {
            issue_tile(i + STAGES - 1, (i + STAGES - 1) % STAGES);
            CP_COMMIT();
        }

        const uint32_t sb = sbase + (i % STAGES) * STAGE_B;
        const uint32_t a0 = sb, a1 = sb + A_PL;
        const uint32_t b0 = sb + NA * A_PL, b1 = b0 + B_PL;
#pragma unroll
        for (int kk = 0; kk < 2; kk++) {
            uint32_t bh[4][4];
#pragma unroll
            for (int nj = 0; nj < 4; nj++) ldsm4(bh[nj], b0 + boff[kk][nj]);
            uint32_t bm_[4][4];
            if (MODE == 0) {
#pragma unroll
                for (int nj = 0; nj < 4; nj++) ldsm4(bm_[nj], b1 + boff[kk][nj]);
            }
#pragma unroll
            for (int mi = 0; mi < 4; mi++) {
                uint32_t ah[4];
                ldsm4(ah, a0 + aoff[kk][mi]);
                // product A0 x B0
#pragma unroll
                for (int ni = 0; ni < 8; ni++) {
                    const int nj = ni >> 1, o = (ni & 1) * 2;
                    mma16816(acc[mi][ni], ah, bh[nj][o], bh[nj][o + 1]);
                }
                if (MODE == 0) {
                    uint32_t am[4];
                    ldsm4(am, a1 + aoff[kk][mi]);
                    // product A0 x B1
#pragma unroll
                    for (int ni = 0; ni < 8; ni++) {
                        const int nj = ni >> 1, o = (ni & 1) * 2;
                        mma16816(acc[mi][ni], ah, bm_[nj][o], bm_[nj][o + 1]);
                    }
                    // product A1 x B0
#pragma unroll
                    for (int ni = 0; ni < 8; ni++) {
                        const int nj = ni >> 1, o = (ni & 1) * 2;
                        mma16816(acc[mi][ni], am, bh[nj][o], bh[nj][o + 1]);
                    }
                }
            }
        }
        CP_WAIT(STAGES - 2);   // next tile resident
        __syncthreads();       // everyone done reading this slot
    }

    // ---- epilogue from registers ----
    const int ldc = args.ldc;
    __half* Ohp = z ? args.Oh2 : args.Oh;
    __half* Omp = z ? args.Om2 : args.Om;
#pragma unroll
    for (int mi = 0; mi < 4; mi++) {
#pragma unroll
        for (int ni = 0; ni < 8; ni++) {
            const int r0 = bm + wm * 64 + mi * 16 + (lane >> 2);
            const int c0 = bn + wn * 64 + ni * 8 + (lane & 3) * 2;
#pragma unroll
            for (int h = 0; h < 2; h++) {
                const size_t o = (size_t)(r0 + h * 8) * ldc + c0;
                const float v0 = acc[mi][ni][2 * h + 0];
                const float v1 = acc[mi][ni][2 * h + 1];
                if (EPI == 0) {
                    float2 w;
                    w.x = args.alpha * v0;
                    w.y = args.alpha * v1;
                    // streaming store — C (S / out) is never re-read via L2
                    __stcs((float2*)(args.C + o), w);
                } else {
                    __half h0 = __float2half_rn(v0);
                    __half h1 = __float2half_rn(v1);
                    __half m0 = __float2half_rn(v0 - __half2float(h0));
                    __half m1 = __float2half_rn(v1 - __half2float(h1));
                    uint32_t ph = (uint32_t)*(unsigned short*)&h0 |
                                  ((uint32_t)*(unsigned short*)&h1 << 16);
                    uint32_t pm = (uint32_t)*(unsigned short*)&m0 |
                                  ((uint32_t)*(unsigned short*)&m1 << 16);
                    *(uint32_t*)((unsigned short*)Ohp + o) = ph;
                    *(uint32_t*)((unsigned short*)Omp + o) = pm;
                }
            }
        }
    }
}

// ---------------------------------------------------------------------------
// elementwise 2-way fp16 split
// ---------------------------------------------------------------------------
__global__ __launch_bounds__(256)
void split2h_kernel(const float* __restrict__ in, __half* __restrict__ oh,
                    __half* __restrict__ om)
{
    size_t i = (size_t)blockIdx.x * 256 + threadIdx.x;
    float v = in[i];
    __half h = __float2half_rn(v);
    om[i] = __float2half_rn(v - __half2float(h));
    oh[i] = h;
}

// ---------------------------------------------------------------------------
// transpose + 2-way fp16 split: in[R][C] fp32 -> oh/om [C][R] fp16
// blockIdx.z selects (input, output) pair — merged Wq/Wk transpose.
// ---------------------------------------------------------------------------
__global__ __launch_bounds__(256)
void transp_split2h_dual(const float* __restrict__ in0, __half* oh0, __half* om0,
                         const float* __restrict__ in1, __half* oh1, __half* om1,
                         int R, int C)
{
    const float* in = blockIdx.z ? in1 : in0;
    __half* oh = blockIdx.z ? oh1 : oh0;
    __half* om = blockIdx.z ? om1 : om0;
    __shared__ float t[32][33];
    const int bc = blockIdx.x * 32, br = blockIdx.y * 32;
    const int tx = threadIdx.x & 31, ty = threadIdx.x >> 5;
#pragma unroll
    for (int j = 0; j < 32; j += 8)
        t[ty + j][tx] = in[(size_t)(br + ty + j) * C + bc + tx];
    __syncthreads();
#pragma unroll
    for (int j = 0; j < 32; j += 8) {
        int oc = bc + ty + j;
        float v = t[tx][ty + j];
        __half h = __float2half_rn(v);
        size_t o = (size_t)oc * R + br + tx;
        oh[o] = h;
        om[o] = __float2half_rn(v - __half2float(h));
    }
}

// ---------------------------------------------------------------------------
// transpose to fp16 (high only): in[R][C] fp32 -> oh[C][R] fp16
// ---------------------------------------------------------------------------
__global__ __launch_bounds__(256)
void transp_h(const float* __restrict__ in, __half* oh, int R, int C)
{
    __shared__ float t[32][33];
    const int bc = blockIdx.x * 32, br = blockIdx.y * 32;
    const int tx = threadIdx.x & 31, ty = threadIdx.x >> 5;
#pragma unroll
    for (int j = 0; j < 32; j += 8)
        t[ty + j][tx] = in[(size_t)(br + ty + j) * C + bc + tx];
    __syncthreads();
#pragma unroll
    for (int j = 0; j < 32; j += 8) {
        int oc = bc + ty + j;
        oh[(size_t)oc * R + br + tx] = __float2half_rn(t[tx][ty + j]);
    }
}

// ---------------------------------------------------------------------------
// softmax over rows of S, emitting fp16 P. 512 threads, float4 streaming
// loads, __expf, shuffle+smem reductions, streaming vectorized stores.
// ---------------------------------------------------------------------------
__global__ __launch_bounds__(512)
void softmax_h(const float* __restrict__ S, __half* __restrict__ Ph, int n)
{
    __shared__ float row[SEQ];
    __shared__ float red[16];
    const int tid = threadIdx.x;
    const int lane = tid & 31;
    const int warp = tid >> 5;
    const int nv = n / 4;                      // float4 count
    const float4* s4 = (const float4*)(S + (size_t)blockIdx.x * n);
    float4* r4 = (float4*)row;

    // pass 1: load (streaming), cache, local max
    float m = -3.4e38f;
    for (int i = tid; i < nv; i += 512) {
        float4 v = __ldcs(s4 + i);
        r4[i] = v;
        m = fmaxf(fmaxf(m, v.x), fmaxf(v.y, fmaxf(v.z, v.w)));
    }
#pragma unroll
    for (int o = 16; o > 0; o >>= 1)
        m = fmaxf(m, __shfl_xor_sync(0xffffffffu, m, o));
    if (lane == 0) red[warp] = m;
    __syncthreads();
    {
        float t = red[lane & 15];
#pragma unroll
        for (int o = 8; o > 0; o >>= 1)
            t = fmaxf(t, __shfl_xor_sync(0xffffffffu, t, o));
        m = __shfl_sync(0xffffffffu, t, 0);
    }
    __syncthreads();

    // pass 2: exp + local sum (in smem)
    float sum = 0.0f;
    for (int i = tid; i < nv; i += 512) {
        float4 v = r4[i];
        v.x = __expf(v.x - m);
        v.y = __expf(v.y - m);
        v.z = __expf(v.z - m);
        v.w = __expf(v.w - m);
        r4[i] = v;
        sum += v.x + v.y + v.z + v.w;
    }
#pragma unroll
    for (int o = 16; o > 0; o >>= 1)
        sum += __shfl_xor_sync(0xffffffffu, sum, o);
    if (lane == 0) red[warp] = sum;
    __syncthreads();
    {
        float t = red[lane & 15];
#pragma unroll
        for (int o = 8; o > 0; o >>= 1)
            t += __shfl_xor_sync(0xffffffffu, t, o);
        sum = __shfl_sync(0xffffffffu, t, 0);
    }
    const float inv = 1.0f / sum;
    __syncthreads();

    // pass 3: normalize + fp16 round, streaming vector stores
    unsigned short* ph = (unsigned short*)(Ph + (size_t)blockIdx.x * n);
    for (int i = tid; i < nv; i += 512) {
        float4 v = r4[i];
        __half h0 = __float2half_rn(v.x * inv);
        __half h1 = __float2half_rn(v.y * inv);
        __half h2 = __float2half_rn(v.z * inv);
        __half h3 = __float2half_rn(v.w * inv);
        int2 wh;
        wh.x = (int)((uint32_t)*(unsigned short*)&h0 |
                     ((uint32_t)*(unsigned short*)&h1 << 16));
        wh.y = (int)((uint32_t)*(unsigned short*)&h2 |
                     ((uint32_t)*(unsigned short*)&h3 << 16));
        __stcs((int2*)(ph + i * 4), wh);
    }
}

// ---------------------------------------------------------------------------
extern "C" void kernel_launch(void* const* d_in, const int* in_sizes, int n_in,
                              void* d_out, int out_size)
{
    const float* X  = (const float*)d_in[0];
    const float* Wq = (const float*)d_in[1];
    const float* Wk = (const float*)d_in[2];
    float* out = (float*)d_out;

    void* p;
#define SYM(name, var) cudaGetSymbolAddress(&p, name); auto* var = (decltype(&name[0]))p;
    SYM(g_S, S) SYM(g_Ph, Ph)
    SYM(g_Qh, Qh) SYM(g_Qm, Qm)
    SYM(g_Kh, Kh) SYM(g_Km, Km)
    SYM(g_Xh, Xh) SYM(g_Xm, Xm)
    SYM(g_Xth, Xth)
    SYM(g_Wqh, Wqh) SYM(g_Wqm, Wqm)
    SYM(g_Wkh, Wkh) SYM(g_Wkm, Wkm)
#undef SYM

    const int SMEM_M0 = 3 * 32768;   // 3 stages x 32KB (2 CTAs/SM)
    const int SMEM_M1 = 6 * 16384;   // 6 stages x 16KB (2 CTAs/SM)
    cudaFuncSetAttribute(gemm_mma<0, 1>, cudaFuncAttributeMaxDynamicSharedMemorySize, SMEM_M0);
    cudaFuncSetAttribute(gemm_mma<0, 0>, cudaFuncAttributeMaxDynamicSharedMemorySize, SMEM_M0);
    cudaFuncSetAttribute(gemm_mma<1, 0>, cudaFuncAttributeMaxDynamicSharedMemorySize, SMEM_M1);

    // --- prep: splits & transposes ---
    split2h_kernel<<<SEQ * DIM / 256, 256>>>(X, Xh, Xm);
    transp_h<<<dim3(DIM / 32, SEQ / 32), 256>>>(X, Xth, SEQ, DIM);
    transp_split2h_dual<<<dim3(DIM / 32, DIM / 32, 2), 256>>>(
        Wq, Wqh, Wqm, Wk, Wkh, Wkm, DIM, DIM);

    // --- projections Q and K in one launch (z selects weight set) ---
    {
        GemmArgs a{};
        a.A[0] = Xh;  a.A[1] = Xm;
        a.B[0] = Wqh; a.B[1] = Wqm;
        a.B2[0] = Wkh; a.B2[1] = Wkm;
        a.K = DIM; a.ldc = DIM; a.alpha = 1.0f;
        a.Oh = Qh; a.Om = Qm; a.Oh2 = Kh; a.Om2 = Km;
        gemm_mma<0, 1><<<dim3(DIM / 128, SEQ / 128, 2), 128, SMEM_M0>>>(a);
    }
    // --- S = (Q @ K^T) / 32 : products {hh, hm, mh} ---
    {
        GemmArgs a{};
        a.A[0] = Qh; a.A[1] = Qm;
        a.B[0] = Kh; a.B[1] = Km;
        a.K = DIM; a.ldc = SEQ; a.alpha = 0.03125f;
        a.C = S;
        gemm_mma<0, 0><<<dim3(SEQ / 128, SEQ / 128, 1), 128, SMEM_M0>>>(a);
    }
    // --- softmax -> fp16 P ---
    softmax_h<<<SEQ, 512>>>(S, Ph, SEQ);
    // --- out = Ph @ Xth^T : single fp16 product ---
    {
        GemmArgs a{};
        a.A[0] = Ph;
        a.B[0] = Xth;
        a.K = SEQ; a.ldc = DIM; a.alpha = 1.0f;
        a.C = out;
        gemm_mma<1, 0><<<dim3(DIM / 128, SEQ / 128, 1), 128, SMEM_M1>>>(a);
    }
}